// round 1
// baseline (speedup 1.0000x reference)
#include <cuda_runtime.h>
#include <math.h>

#define DIMM 1024
#define NHEAD 16
#define HDIM 64
#define SLEN 2048
#define BSZ 2
#define NTOK (BSZ*SLEN)          // 4096
#define NEXP 8
#define TOPK 2
#define HIDD 1024
#define NSLOT (NTOK*TOPK)        // 8192
#define EPSV 1e-6f

// ---------------- scratch (device globals; no allocation allowed) ----------------
__device__ float g_xn[NTOK*DIMM];
__device__ float g_q [NTOK*DIMM];
__device__ float g_k [NTOK*DIMM];
__device__ float g_v [NTOK*DIMM];
__device__ float g_scores[(size_t)BSZ*NHEAD*SLEN*SLEN];   // 512 MB
__device__ float g_att[NTOK*DIMM];
__device__ float g_h  [NTOK*DIMM];
__device__ float g_hn [NTOK*DIMM];
__device__ int   g_topk_idx[NTOK*TOPK];
__device__ float g_topk_w [NTOK*TOPK];
__device__ int   g_counts[NEXP];
__device__ int   g_offsets[NEXP+1];
__device__ int   g_fill[NEXP];
__device__ int   g_tok_idx[NSLOT];
__device__ int   g_slot_map[NTOK*TOPK];
__device__ float g_h1[(size_t)NSLOT*HIDD];   // 32 MB
__device__ float g_h3[(size_t)NSLOT*HIDD];   // 32 MB
__device__ float g_eo[(size_t)NSLOT*DIMM];   // 32 MB
__device__ float g_s1[(size_t)NTOK*HIDD];
__device__ float g_s3[(size_t)NTOK*HIDD];

// ---------------- RMSNorm: one block per row ----------------
__global__ void rmsnorm_kernel(const float* __restrict__ x, const float* __restrict__ w,
                               float* __restrict__ out) {
    int row = blockIdx.x;
    const float* xr = x + (size_t)row*DIMM;
    float v[4]; float s = 0.f;
#pragma unroll
    for (int i = 0; i < 4; i++) { v[i] = xr[threadIdx.x + i*256]; s += v[i]*v[i]; }
    __shared__ float red[8];
#pragma unroll
    for (int o = 16; o > 0; o >>= 1) s += __shfl_xor_sync(0xffffffffu, s, o);
    if ((threadIdx.x & 31) == 0) red[threadIdx.x >> 5] = s;
    __syncthreads();
    if (threadIdx.x < 8) {
        float t = red[threadIdx.x];
#pragma unroll
        for (int o = 4; o > 0; o >>= 1) t += __shfl_xor_sync(0xffu, t, o);
        if (threadIdx.x == 0) red[0] = t;
    }
    __syncthreads();
    float r = rsqrtf(red[0] / (float)DIMM + EPSV);
#pragma unroll
    for (int i = 0; i < 4; i++) {
        int c = threadIdx.x + i*256;
        out[(size_t)row*DIMM + c] = v[i]*r*w[c];
    }
}

// ---------------- RoPE on q and k ----------------
__global__ void rope_kernel(float* __restrict__ q, float* __restrict__ k,
                            const float* __restrict__ freqs) {
    int idx = blockIdx.x*blockDim.x + threadIdx.x;   // NTOK*NHEAD*(HDIM/2)
    if (idx >= NTOK*NHEAD*(HDIM/2)) return;
    int p = idx % (HDIM/2);
    int h = (idx / (HDIM/2)) % NHEAD;
    int n = idx / (NHEAD*(HDIM/2));
    int s = n % SLEN;
    float c  = freqs[(s*(HDIM/2) + p)*2 + 0];
    float sn = freqs[(s*(HDIM/2) + p)*2 + 1];
    size_t base = (size_t)n*DIMM + h*HDIM + 2*p;
    float q0 = q[base], q1 = q[base+1];
    q[base]   = q0*c - q1*sn;
    q[base+1] = q0*sn + q1*c;
    float k0 = k[base], k1 = k[base+1];
    k[base]   = k0*c - k1*sn;
    k[base+1] = k0*sn + k1*c;
}

// ---------------- generic batched NN SGEMM ----------------
// C[z] = A[z] @ B[z] (+ R[z]) ; 128 x BN x 8 tile, 256 threads, TMxTN = 8 x (BN/16)
template<int BN, bool GATHER, bool GROUPED, bool RESID>
__global__ void gemm_nn(const float* __restrict__ A, const float* __restrict__ B,
                        float* __restrict__ C, const float* __restrict__ R,
                        int M, int Kd, int lda, int ldb, int ldc,
                        int zdiv,
                        long long sAo, long long sAi,
                        long long sBo, long long sBi,
                        long long sCo, long long sCi,
                        const int* __restrict__ gidx, const int* __restrict__ offsets) {
    constexpr int BM = 128, BK = 8, TN = BN/16;
    __shared__ float As[BK][BM];
    __shared__ float Bs[BK][BN];
    int tid = threadIdx.x;

    int Mz = M;
    int seg0 = 0;
    if (GROUPED) {
        int e = blockIdx.z;
        seg0 = offsets[e];
        Mz = offsets[e+1] - seg0;
        B += (size_t)e * sBo;
    } else {
        int z = blockIdx.z;
        int zo = z / zdiv, zi = z % zdiv;
        A += zo*sAo + zi*sAi;
        B += zo*sBo + zi*sBi;
        C += zo*sCo + zi*sCi;
        if (RESID) R += zo*sCo + zi*sCi;
    }
    int m0 = blockIdx.x * BM;
    if (m0 >= Mz) return;
    int n0 = blockIdx.y * BN;

    int arow = tid >> 1;
    int acol = (tid & 1) * 4;
    bool arow_ok = (m0 + arow) < Mz;
    const float* Aptr = nullptr;
    if (arow_ok) {
        size_t r;
        if (GATHER)       r = (size_t)gidx[seg0 + m0 + arow];
        else if (GROUPED) r = (size_t)(seg0 + m0 + arow);
        else              r = (size_t)(m0 + arow);
        Aptr = A + r*(size_t)lda + acol;
    }

    float acc[8][TN];
#pragma unroll
    for (int i = 0; i < 8; i++)
#pragma unroll
        for (int j = 0; j < TN; j++) acc[i][j] = 0.f;

    for (int kt = 0; kt < Kd; kt += BK) {
        float4 av = arow_ok ? *(const float4*)(Aptr + kt) : make_float4(0,0,0,0);
        As[acol+0][arow] = av.x; As[acol+1][arow] = av.y;
        As[acol+2][arow] = av.z; As[acol+3][arow] = av.w;
        if (BN == 128) {
            int brow = tid >> 5, bcol = (tid & 31) * 4;
            *(float4*)&Bs[brow][bcol] =
                *(const float4*)(B + (size_t)(kt+brow)*ldb + n0 + bcol);
        } else {
            if (tid < 128) {
                int brow = tid >> 4, bcol = (tid & 15) * 4;
                *(float4*)&Bs[brow][bcol] =
                    *(const float4*)(B + (size_t)(kt+brow)*ldb + n0 + bcol);
            }
        }
        __syncthreads();
        int rb = (tid >> 4) * 8;
        int cb = (tid & 15) * TN;
#pragma unroll
        for (int kk = 0; kk < BK; kk++) {
            float a[8], b[TN];
            *(float4*)&a[0] = *(const float4*)&As[kk][rb];
            *(float4*)&a[4] = *(const float4*)&As[kk][rb+4];
#pragma unroll
            for (int j = 0; j < TN; j += 4)
                *(float4*)&b[j] = *(const float4*)&Bs[kk][cb+j];
#pragma unroll
            for (int i = 0; i < 8; i++)
#pragma unroll
                for (int j = 0; j < TN; j++)
                    acc[i][j] += a[i]*b[j];
        }
        __syncthreads();
    }

    int rb = (tid >> 4) * 8;
    int cb = (tid & 15) * TN;
#pragma unroll
    for (int i = 0; i < 8; i++) {
        int row = m0 + rb + i;
        if (GROUPED && row >= Mz) break;
        size_t crow = (size_t)(GROUPED ? seg0 + row : row)*ldc + n0 + cb;
#pragma unroll
        for (int j = 0; j < TN; j++) {
            float val = acc[i][j];
            if (RESID) val += R[crow + j];
            C[crow + j] = val;
        }
    }
}

// ---------------- NT GEMM for attention scores (scaled) ----------------
__global__ void gemm_nt_scores(const float* __restrict__ Q, const float* __restrict__ Km,
                               float* __restrict__ Cs) {
    __shared__ float As[8][128];
    __shared__ float Bs[8][128];
    int tid = threadIdx.x;
    int z = blockIdx.z, b = z / NHEAD, h = z % NHEAD;
    const float* Aq = Q  + (size_t)b*SLEN*DIMM + h*HDIM;
    const float* Bk = Km + (size_t)b*SLEN*DIMM + h*HDIM;
    float* C = Cs + (size_t)z*SLEN*SLEN;
    int m0 = blockIdx.x*128, n0 = blockIdx.y*128;
    int lrow = tid >> 1, lcol = (tid & 1)*4;

    float acc[8][8];
#pragma unroll
    for (int i = 0; i < 8; i++)
#pragma unroll
        for (int j = 0; j < 8; j++) acc[i][j] = 0.f;

    for (int kt = 0; kt < HDIM; kt += 8) {
        float4 av = *(const float4*)(Aq + (size_t)(m0+lrow)*DIMM + kt + lcol);
        As[lcol+0][lrow] = av.x; As[lcol+1][lrow] = av.y;
        As[lcol+2][lrow] = av.z; As[lcol+3][lrow] = av.w;
        float4 bv = *(const float4*)(Bk + (size_t)(n0+lrow)*DIMM + kt + lcol);
        Bs[lcol+0][lrow] = bv.x; Bs[lcol+1][lrow] = bv.y;
        Bs[lcol+2][lrow] = bv.z; Bs[lcol+3][lrow] = bv.w;
        __syncthreads();
        int rb = (tid >> 4)*8, cb = (tid & 15)*8;
#pragma unroll
        for (int kk = 0; kk < 8; kk++) {
            float a[8], bb[8];
            *(float4*)&a[0]  = *(const float4*)&As[kk][rb];
            *(float4*)&a[4]  = *(const float4*)&As[kk][rb+4];
            *(float4*)&bb[0] = *(const float4*)&Bs[kk][cb];
            *(float4*)&bb[4] = *(const float4*)&Bs[kk][cb+4];
#pragma unroll
            for (int i = 0; i < 8; i++)
#pragma unroll
                for (int j = 0; j < 8; j++)
                    acc[i][j] += a[i]*bb[j];
        }
        __syncthreads();
    }
    int rb = (tid >> 4)*8, cb = (tid & 15)*8;
#pragma unroll
    for (int i = 0; i < 8; i++)
#pragma unroll
        for (int j = 0; j < 8; j++)
            C[(size_t)(m0+rb+i)*SLEN + n0 + cb + j] = acc[i][j]*0.125f;
}

// ---------------- row softmax over SLEN ----------------
__global__ void softmax_rows(float* __restrict__ scores) {
    size_t row = blockIdx.x;
    float* r = scores + row*SLEN;
    float v[8]; float mx = -1e30f;
#pragma unroll
    for (int i = 0; i < 8; i++) { v[i] = r[threadIdx.x + i*256]; mx = fmaxf(mx, v[i]); }
    __shared__ float red[8];
#pragma unroll
    for (int o = 16; o > 0; o >>= 1) mx = fmaxf(mx, __shfl_xor_sync(0xffffffffu, mx, o));
    if ((threadIdx.x & 31) == 0) red[threadIdx.x >> 5] = mx;
    __syncthreads();
    if (threadIdx.x < 8) {
        float t = red[threadIdx.x];
#pragma unroll
        for (int o = 4; o > 0; o >>= 1) t = fmaxf(t, __shfl_xor_sync(0xffu, t, o));
        if (threadIdx.x == 0) red[0] = t;
    }
    __syncthreads();
    mx = red[0];
    float sum = 0.f;
#pragma unroll
    for (int i = 0; i < 8; i++) { v[i] = __expf(v[i]-mx); sum += v[i]; }
    __syncthreads();
#pragma unroll
    for (int o = 16; o > 0; o >>= 1) sum += __shfl_xor_sync(0xffffffffu, sum, o);
    if ((threadIdx.x & 31) == 0) red[threadIdx.x >> 5] = sum;
    __syncthreads();
    if (threadIdx.x < 8) {
        float t = red[threadIdx.x];
#pragma unroll
        for (int o = 4; o > 0; o >>= 1) t += __shfl_xor_sync(0xffu, t, o);
        if (threadIdx.x == 0) red[0] = t;
    }
    __syncthreads();
    float inv = 1.f / red[0];
#pragma unroll
    for (int i = 0; i < 8; i++) r[threadIdx.x + i*256] = v[i]*inv;
}

// ---------------- gating: softmax over 8 experts + top-2 ----------------
__global__ void zero_counts_kernel(int* c) { if (threadIdx.x < NEXP) c[threadIdx.x] = 0; }

__global__ void gate_topk(const float* __restrict__ hn, const float* __restrict__ gw,
                          int* __restrict__ tidx, float* __restrict__ tw,
                          int* __restrict__ counts) {
    int n = blockIdx.x;
    int w = threadIdx.x >> 5, lane = threadIdx.x & 31;
    const float* x = hn + (size_t)n*DIMM;
    const float* g = gw + (size_t)w*DIMM;
    float s = 0.f;
    for (int i = lane; i < DIMM; i += 32) s += x[i]*g[i];
#pragma unroll
    for (int o = 16; o > 0; o >>= 1) s += __shfl_xor_sync(0xffffffffu, s, o);
    __shared__ float sc[NEXP];
    if (lane == 0) sc[w] = s;
    __syncthreads();
    if (threadIdx.x == 0) {
        float mx = sc[0];
        for (int e = 1; e < NEXP; e++) mx = fmaxf(mx, sc[e]);
        float p[NEXP]; float sum = 0.f;
        for (int e = 0; e < NEXP; e++) { p[e] = expf(sc[e]-mx); sum += p[e]; }
        for (int e = 0; e < NEXP; e++) p[e] /= sum;
        int i0 = 0;
        for (int e = 1; e < NEXP; e++) if (p[e] > p[i0]) i0 = e;
        int i1 = -1;
        for (int e = 0; e < NEXP; e++)
            if (e != i0 && (i1 < 0 || p[e] > p[i1])) i1 = e;
        tidx[n*2]   = i0; tidx[n*2+1] = i1;
        tw[n*2]     = p[i0]; tw[n*2+1] = p[i1];
        atomicAdd(&counts[i0], 1);
        atomicAdd(&counts[i1], 1);
    }
}

__global__ void prefix_kernel(const int* __restrict__ counts, int* __restrict__ offs,
                              int* __restrict__ fill) {
    if (threadIdx.x == 0) {
        int a = 0;
        for (int e = 0; e < NEXP; e++) { offs[e] = a; a += counts[e]; }
        offs[NEXP] = a;
    }
    if (threadIdx.x < NEXP) fill[threadIdx.x] = 0;
}

__global__ void scatter_kernel(const int* __restrict__ tidx,
                               const int* __restrict__ offs, int* __restrict__ fill,
                               int* __restrict__ tok, int* __restrict__ smap) {
    int n = blockIdx.x*blockDim.x + threadIdx.x;
    if (n >= NTOK) return;
#pragma unroll
    for (int j = 0; j < TOPK; j++) {
        int e = tidx[n*2+j];
        int slot = offs[e] + atomicAdd(&fill[e], 1);
        tok[slot] = n;
        smap[n*2+j] = slot;
    }
}

// ---------------- silu(a)*b -> a ----------------
__global__ void silu_mul(float* __restrict__ a, const float* __restrict__ b, size_t n) {
    size_t i = (size_t)blockIdx.x*blockDim.x + threadIdx.x;
    if (i >= n) return;
    float x = a[i];
    float s = x / (1.f + __expf(-x));
    a[i] = s * b[i];
}

// ---------------- final combine: out += w0*eo[slot0] + w1*eo[slot1] ----------------
__global__ void combine_kernel(float* __restrict__ out, const float* __restrict__ eo,
                               const int* __restrict__ smap, const float* __restrict__ tw) {
    size_t idx = (size_t)blockIdx.x*blockDim.x + threadIdx.x;
    if (idx >= (size_t)NTOK*DIMM) return;
    size_t n = idx / DIMM, d = idx % DIMM;
    int s0 = smap[n*2], s1 = smap[n*2+1];
    out[idx] += tw[n*2]*eo[(size_t)s0*DIMM + d] + tw[n*2+1]*eo[(size_t)s1*DIMM + d];
}

// ---------------- launcher ----------------
extern "C" void kernel_launch(void* const* d_in, const int* in_sizes, int n_in,
                              void* d_out, int out_size) {
    (void)in_sizes; (void)n_in; (void)out_size;
    const float* x     = (const float*)d_in[0];
    const float* freqs = (const float*)d_in[1];
    const float* att_w = (const float*)d_in[2];
    const float* wq    = (const float*)d_in[3];
    const float* wk    = (const float*)d_in[4];
    const float* wv    = (const float*)d_in[5];
    const float* wo    = (const float*)d_in[6];
    const float* ffn_w = (const float*)d_in[7];
    const float* gw    = (const float*)d_in[8];
    const float* ew1   = (const float*)d_in[9];
    const float* ew2   = (const float*)d_in[10];
    const float* ew3   = (const float*)d_in[11];
    const float* sw1   = (const float*)d_in[12];
    const float* sw2   = (const float*)d_in[13];
    const float* sw3   = (const float*)d_in[14];
    float* out = (float*)d_out;

    float *xn,*q,*k,*v,*scores,*att,*h,*hn,*h1,*h3,*eo,*s1,*s3,*tw;
    int *tidx,*counts,*offs,*fill,*tok,*smap;
    cudaGetSymbolAddress((void**)&xn, g_xn);
    cudaGetSymbolAddress((void**)&q,  g_q);
    cudaGetSymbolAddress((void**)&k,  g_k);
    cudaGetSymbolAddress((void**)&v,  g_v);
    cudaGetSymbolAddress((void**)&scores, g_scores);
    cudaGetSymbolAddress((void**)&att, g_att);
    cudaGetSymbolAddress((void**)&h,   g_h);
    cudaGetSymbolAddress((void**)&hn,  g_hn);
    cudaGetSymbolAddress((void**)&tidx, g_topk_idx);
    cudaGetSymbolAddress((void**)&tw,   g_topk_w);
    cudaGetSymbolAddress((void**)&counts, g_counts);
    cudaGetSymbolAddress((void**)&offs,   g_offsets);
    cudaGetSymbolAddress((void**)&fill,   g_fill);
    cudaGetSymbolAddress((void**)&tok,    g_tok_idx);
    cudaGetSymbolAddress((void**)&smap,   g_slot_map);
    cudaGetSymbolAddress((void**)&h1, g_h1);
    cudaGetSymbolAddress((void**)&h3, g_h3);
    cudaGetSymbolAddress((void**)&eo, g_eo);
    cudaGetSymbolAddress((void**)&s1, g_s1);
    cudaGetSymbolAddress((void**)&s3, g_s3);

    const int T = 256;

    // 1) attention pre-norm
    rmsnorm_kernel<<<NTOK, T>>>(x, att_w, xn);

    // 2) QKV projections (4096x1024x1024 each)
    gemm_nn<128,false,false,false><<<dim3(32,8,1), T>>>(xn, wq, q, nullptr,
        NTOK, DIMM, DIMM, DIMM, DIMM, 1, 0,0, 0,0, 0,0, nullptr, nullptr);
    gemm_nn<128,false,false,false><<<dim3(32,8,1), T>>>(xn, wk, k, nullptr,
        NTOK, DIMM, DIMM, DIMM, DIMM, 1, 0,0, 0,0, 0,0, nullptr, nullptr);
    gemm_nn<128,false,false,false><<<dim3(32,8,1), T>>>(xn, wv, v, nullptr,
        NTOK, DIMM, DIMM, DIMM, DIMM, 1, 0,0, 0,0, 0,0, nullptr, nullptr);

    // 3) RoPE on q, k
    rope_kernel<<<(NTOK*NHEAD*(HDIM/2))/T, T>>>(q, k, freqs);

    // 4) scores = (q @ k^T) / sqrt(HD), batched over 32 (b,h)
    gemm_nt_scores<<<dim3(16,16,BSZ*NHEAD), T>>>(q, k, scores);

    // 5) softmax over keys
    softmax_rows<<<BSZ*NHEAD*SLEN, T>>>(scores);

    // 6) att = probs @ v, batched
    gemm_nn<64,false,false,false><<<dim3(16,1,BSZ*NHEAD), T>>>(scores, v, att, nullptr,
        SLEN, SLEN, SLEN, DIMM, DIMM, NHEAD,
        (long long)NHEAD*SLEN*SLEN, (long long)SLEN*SLEN,
        (long long)SLEN*DIMM, (long long)HDIM,
        (long long)SLEN*DIMM, (long long)HDIM, nullptr, nullptr);

    // 7) h = x + att @ wo
    gemm_nn<128,false,false,true><<<dim3(32,8,1), T>>>(att, wo, h, x,
        NTOK, DIMM, DIMM, DIMM, DIMM, 1, 0,0, 0,0, 0,0, nullptr, nullptr);

    // 8) ffn pre-norm
    rmsnorm_kernel<<<NTOK, T>>>(h, ffn_w, hn);

    // 9) gate + routing
    zero_counts_kernel<<<1, 32>>>(counts);
    gate_topk<<<NTOK, T>>>(hn, gw, tidx, tw, counts);
    prefix_kernel<<<1, 32>>>(counts, offs, fill);
    scatter_kernel<<<(NTOK + T - 1)/T, T>>>(tidx, offs, fill, tok, smap);

    // 10) experts: h1 = gather(hn) @ ew1[e], h3 = gather(hn) @ ew3[e]
    gemm_nn<128,true,true,false><<<dim3(32,8,NEXP), T>>>(hn, ew1, h1, nullptr,
        0, DIMM, DIMM, HIDD, HIDD, 1, 0,0,
        (long long)DIMM*HIDD, 0, 0,0, tok, offs);
    gemm_nn<128,true,true,false><<<dim3(32,8,NEXP), T>>>(hn, ew3, h3, nullptr,
        0, DIMM, DIMM, HIDD, HIDD, 1, 0,0,
        (long long)DIMM*HIDD, 0, 0,0, tok, offs);
    silu_mul<<<(unsigned)(((size_t)NSLOT*HIDD)/T), T>>>(h1, h3, (size_t)NSLOT*HIDD);
    // eo = (silu(h1)*h3) @ ew2[e]
    gemm_nn<128,false,true,false><<<dim3(32,8,NEXP), T>>>(h1, ew2, eo, nullptr,
        0, HIDD, HIDD, DIMM, DIMM, 1, 0,0,
        (long long)HIDD*DIMM, 0, 0,0, nullptr, offs);

    // 11) shared expert
    gemm_nn<128,false,false,false><<<dim3(32,8,1), T>>>(hn, sw1, s1, nullptr,
        NTOK, DIMM, DIMM, HIDD, HIDD, 1, 0,0, 0,0, 0,0, nullptr, nullptr);
    gemm_nn<128,false,false,false><<<dim3(32,8,1), T>>>(hn, sw3, s3, nullptr,
        NTOK, DIMM, DIMM, HIDD, HIDD, 1, 0,0, 0,0, 0,0, nullptr, nullptr);
    silu_mul<<<(unsigned)(((size_t)NTOK*HIDD)/T), T>>>(s1, s3, (size_t)NTOK*HIDD);
    // out = h + (silu(s1)*s3) @ sw2
    gemm_nn<128,false,false,true><<<dim3(32,8,1), T>>>(s1, sw2, out, h,
        NTOK, HIDD, HIDD, DIMM, DIMM, 1, 0,0, 0,0, 0,0, nullptr, nullptr);

    // 12) out += routed expert contributions (deterministic, no atomics)
    combine_kernel<<<(unsigned)(((size_t)NTOK*DIMM)/T), T>>>(out, eo, smap, tw);
}

// round 3
// speedup vs baseline: 1.6078x; 1.6078x over previous
#include <cuda_runtime.h>
#include <math.h>
#include <stdint.h>

#define DIMM 1024
#define NHEAD 16
#define HDIM 64
#define SLEN 2048
#define BSZ 2
#define NTOK (BSZ*SLEN)          // 4096
#define NEXP 8
#define TOPK 2
#define HIDD 1024
#define NSLOT (NTOK*TOPK)        // 8192
#define EPSV 1e-6f

// ================= scratch =================
__device__ float g_xn[NTOK*DIMM];
__device__ float g_q [NTOK*DIMM];
__device__ float g_k [NTOK*DIMM];
__device__ float g_v [NTOK*DIMM];
__device__ float g_scores[(size_t)BSZ*NHEAD*SLEN*SLEN];   // 512 MB
__device__ float g_att[NTOK*DIMM];
__device__ float g_h  [NTOK*DIMM];
__device__ float g_hn [NTOK*DIMM];
__device__ int   g_topk_idx[NTOK*TOPK];
__device__ float g_topk_w [NTOK*TOPK];
__device__ int   g_counts[NEXP];
__device__ int   g_offsets[NEXP+1];
__device__ int   g_fill[NEXP];
__device__ int   g_tok_idx[NSLOT];
__device__ int   g_slot_map[NTOK*TOPK];
__device__ float g_h1[(size_t)NSLOT*HIDD];
__device__ float g_h3[(size_t)NSLOT*HIDD];
__device__ float g_eo[(size_t)NSLOT*DIMM];
__device__ float g_s1[(size_t)NTOK*HIDD];
__device__ float g_s3[(size_t)NTOK*HIDD];

__device__ __forceinline__ uint32_t f2tf32(float f) {
    uint32_t r; asm("cvt.rna.tf32.f32 %0, %1;" : "=r"(r) : "f"(f)); return r;
}

// ================= tf32 mma.sync GEMM =================
// C[BM=128 x BN=64] (+R) = A[M,K](row-major, lda) @ B
//   BT=false: B global [K,N] row-major (ldb)  -> direct smem copy
//   BT=true : B global [N,K] row-major (ldb)  -> transpose on load
// 8 warps: warpM=wid&3 (32 rows), warpN=wid>>2 (32 cols); warp tile 32x32
// = 2 (m16) x 4 (n8) mma tiles, k8 steps, BK=16 per chunk.
template<bool BT, bool GATHER, bool GROUPED, bool RESID>
__global__ void __launch_bounds__(256) mma_gemm(
    const float* __restrict__ A, const float* __restrict__ B,
    float* __restrict__ C, const float* __restrict__ Rr,
    int M, int Kd, int lda, int ldb, int ldc, float scale, int zdiv,
    long long sAo, long long sAi, long long sBo, long long sBi,
    long long sCo, long long sCi,
    const int* __restrict__ gidx, const int* __restrict__ offsets)
{
    __shared__ uint32_t As[16][136];   // stride 136: bank = (8k+m)%32, conflict-free frags
    __shared__ uint32_t Bs[16][72];    // stride 72 : bank = (8k+n)%32, conflict-free frags
    int tid = threadIdx.x;
    int wid = tid >> 5, lane = tid & 31;
    int warpM = wid & 3, warpN = wid >> 2;

    int Mz = M, seg0 = 0;
    if (GROUPED) {
        int e = blockIdx.z;
        seg0 = offsets[e];
        Mz = offsets[e+1] - seg0;
        B += (size_t)e * sBo;
    } else {
        int z = blockIdx.z; int zo = z / zdiv, zi = z % zdiv;
        A += zo*sAo + zi*sAi; B += zo*sBo + zi*sBi;
        C += zo*sCo + zi*sCi; if (RESID) Rr += zo*sCo + zi*sCi;
    }
    int m0 = blockIdx.x * 128;
    if (GROUPED && m0 >= Mz) return;
    int n0 = blockIdx.y * 64;

    // ---- A load assignment: row am = tid&127, two k-group float4s (kg, kg+2)
    int am = tid & 127;
    int akg = tid >> 7;                 // 0 or 1 -> k offsets akg*4 and (akg+2)*4
    bool aOK = true; long long gr;
    if (GROUPED) aOK = (m0 + am) < Mz;
    if (GATHER)        gr = aOK ? (long long)gidx[seg0 + m0 + am] : 0;
    else if (GROUPED)  gr = aOK ? (long long)(seg0 + m0 + am) : 0;
    else               gr = m0 + am;
    const float* aBase = A + (size_t)gr*lda;

    // ---- B load assignment
    int b_kb, b_n4, b_n, b_kg;
    const float* bBase;
    if (!BT) {
        b_kb = tid >> 4; b_n4 = tid & 15;              // [k][n] direct, float4 along n
        bBase = B + n0 + b_n4*4;
    } else {
        b_n = tid >> 2; b_kg = tid & 3;                // [n][k], float4 along k
        bBase = B + (size_t)(n0 + b_n)*ldb + b_kg*4;
    }

    float acc[2][4][4];
#pragma unroll
    for (int mt = 0; mt < 2; mt++)
#pragma unroll
        for (int nt = 0; nt < 4; nt++)
#pragma unroll
            for (int j = 0; j < 4; j++) acc[mt][nt][j] = 0.f;

    int nc = Kd >> 4;
    float4 aR0, aR1, bR;
    {
        aR0 = aOK ? *(const float4*)(aBase + akg*4)     : make_float4(0,0,0,0);
        aR1 = aOK ? *(const float4*)(aBase + (akg+2)*4) : make_float4(0,0,0,0);
        if (!BT) bR = *(const float4*)(bBase + (size_t)b_kb*ldb);
        else     bR = *(const float4*)bBase;
    }

    for (int c = 0; c < nc; c++) {
        // store chunk (converted to tf32 bits)
        {
            int k0 = akg*4;
            As[k0+0][am] = f2tf32(aR0.x); As[k0+1][am] = f2tf32(aR0.y);
            As[k0+2][am] = f2tf32(aR0.z); As[k0+3][am] = f2tf32(aR0.w);
            int k1 = (akg+2)*4;
            As[k1+0][am] = f2tf32(aR1.x); As[k1+1][am] = f2tf32(aR1.y);
            As[k1+2][am] = f2tf32(aR1.z); As[k1+3][am] = f2tf32(aR1.w);
            if (!BT) {
                Bs[b_kb][b_n4*4+0] = f2tf32(bR.x); Bs[b_kb][b_n4*4+1] = f2tf32(bR.y);
                Bs[b_kb][b_n4*4+2] = f2tf32(bR.z); Bs[b_kb][b_n4*4+3] = f2tf32(bR.w);
            } else {
                int k0b = b_kg*4;
                Bs[k0b+0][b_n] = f2tf32(bR.x); Bs[k0b+1][b_n] = f2tf32(bR.y);
                Bs[k0b+2][b_n] = f2tf32(bR.z); Bs[k0b+3][b_n] = f2tf32(bR.w);
            }
        }
        __syncthreads();
        // prefetch next chunk
        if (c + 1 < nc) {
            int kt = (c + 1) * 16;
            aR0 = aOK ? *(const float4*)(aBase + kt + akg*4)     : make_float4(0,0,0,0);
            aR1 = aOK ? *(const float4*)(aBase + kt + (akg+2)*4) : make_float4(0,0,0,0);
            if (!BT) bR = *(const float4*)(bBase + (size_t)(kt + b_kb)*ldb);
            else     bR = *(const float4*)(bBase + kt);
        }
        // compute: 2 k-steps of m16n8k8
#pragma unroll
        for (int ks = 0; ks < 2; ks++) {
            int kc = ks*8 + (lane & 3);
            uint32_t af[2][4];
#pragma unroll
            for (int mt = 0; mt < 2; mt++) {
                int mr = warpM*32 + mt*16 + (lane >> 2);
                af[mt][0] = As[kc  ][mr];
                af[mt][1] = As[kc  ][mr+8];
                af[mt][2] = As[kc+4][mr];
                af[mt][3] = As[kc+4][mr+8];
            }
            uint32_t bf[4][2];
#pragma unroll
            for (int nt = 0; nt < 4; nt++) {
                int ncol = warpN*32 + nt*8 + (lane >> 2);
                bf[nt][0] = Bs[kc  ][ncol];
                bf[nt][1] = Bs[kc+4][ncol];
            }
#pragma unroll
            for (int mt = 0; mt < 2; mt++)
#pragma unroll
                for (int nt = 0; nt < 4; nt++) {
                    asm volatile(
                        "mma.sync.aligned.m16n8k8.row.col.f32.tf32.tf32.f32 "
                        "{%0,%1,%2,%3}, {%4,%5,%6,%7}, {%8,%9}, {%0,%1,%2,%3};"
                        : "+f"(acc[mt][nt][0]), "+f"(acc[mt][nt][1]),
                          "+f"(acc[mt][nt][2]), "+f"(acc[mt][nt][3])
                        : "r"(af[mt][0]), "r"(af[mt][1]), "r"(af[mt][2]), "r"(af[mt][3]),
                          "r"(bf[nt][0]), "r"(bf[nt][1]));
                }
        }
        __syncthreads();
    }

    // ---- epilogue ----
#pragma unroll
    for (int mt = 0; mt < 2; mt++) {
        int rbase = m0 + warpM*32 + mt*16 + (lane >> 2);
#pragma unroll
        for (int half = 0; half < 2; half++) {
            int r = rbase + half*8;
            bool rok = (!GROUPED) || (r < Mz);
            if (!rok) continue;
            size_t crow = (size_t)(GROUPED ? (seg0 + r) : r) * ldc;
#pragma unroll
            for (int nt = 0; nt < 4; nt++) {
                int col = n0 + warpN*32 + nt*8 + (lane & 3)*2;
                float2 v2;
                v2.x = acc[mt][nt][half*2+0] * scale;
                v2.y = acc[mt][nt][half*2+1] * scale;
                if (RESID) {
                    float2 rv = *(const float2*)(Rr + crow + col);
                    v2.x += rv.x; v2.y += rv.y;
                }
                *(float2*)(C + crow + col) = v2;
            }
        }
    }
}

// ================= elementwise / reduction kernels =================
__global__ void rmsnorm_kernel(const float* __restrict__ x, const float* __restrict__ w,
                               float* __restrict__ out) {
    int row = blockIdx.x;
    const float* xr = x + (size_t)row*DIMM;
    float v[4]; float s = 0.f;
#pragma unroll
    for (int i = 0; i < 4; i++) { v[i] = xr[threadIdx.x + i*256]; s += v[i]*v[i]; }
    __shared__ float red[8];
#pragma unroll
    for (int o = 16; o > 0; o >>= 1) s += __shfl_xor_sync(0xffffffffu, s, o);
    if ((threadIdx.x & 31) == 0) red[threadIdx.x >> 5] = s;
    __syncthreads();
    if (threadIdx.x < 8) {
        float t = red[threadIdx.x];
#pragma unroll
        for (int o = 4; o > 0; o >>= 1) t += __shfl_xor_sync(0xffu, t, o);
        if (threadIdx.x == 0) red[0] = t;
    }
    __syncthreads();
    float r = rsqrtf(red[0] / (float)DIMM + EPSV);
#pragma unroll
    for (int i = 0; i < 4; i++) {
        int c = threadIdx.x + i*256;
        out[(size_t)row*DIMM + c] = v[i]*r*w[c];
    }
}

__global__ void rope_kernel(float* __restrict__ q, float* __restrict__ k,
                            const float* __restrict__ freqs) {
    int idx = blockIdx.x*blockDim.x + threadIdx.x;
    if (idx >= NTOK*NHEAD*(HDIM/2)) return;
    int p = idx % (HDIM/2);
    int h = (idx / (HDIM/2)) % NHEAD;
    int n = idx / (NHEAD*(HDIM/2));
    int s = n % SLEN;
    float c  = freqs[(s*(HDIM/2) + p)*2 + 0];
    float sn = freqs[(s*(HDIM/2) + p)*2 + 1];
    size_t base = (size_t)n*DIMM + h*HDIM + 2*p;
    float q0 = q[base], q1 = q[base+1];
    q[base]   = q0*c - q1*sn;
    q[base+1] = q0*sn + q1*c;
    float k0 = k[base], k1 = k[base+1];
    k[base]   = k0*c - k1*sn;
    k[base+1] = k0*sn + k1*c;
}

__global__ void softmax_rows(float* __restrict__ scores) {
    size_t row = blockIdx.x;
    float* r = scores + row*SLEN;
    float v[8]; float mx = -1e30f;
#pragma unroll
    for (int i = 0; i < 8; i++) { v[i] = r[threadIdx.x + i*256]; mx = fmaxf(mx, v[i]); }
    __shared__ float red[8];
#pragma unroll
    for (int o = 16; o > 0; o >>= 1) mx = fmaxf(mx, __shfl_xor_sync(0xffffffffu, mx, o));
    if ((threadIdx.x & 31) == 0) red[threadIdx.x >> 5] = mx;
    __syncthreads();
    if (threadIdx.x < 8) {
        float t = red[threadIdx.x];
#pragma unroll
        for (int o = 4; o > 0; o >>= 1) t = fmaxf(t, __shfl_xor_sync(0xffu, t, o));
        if (threadIdx.x == 0) red[0] = t;
    }
    __syncthreads();
    mx = red[0];
    float sum = 0.f;
#pragma unroll
    for (int i = 0; i < 8; i++) { v[i] = __expf(v[i]-mx); sum += v[i]; }
    __syncthreads();
#pragma unroll
    for (int o = 16; o > 0; o >>= 1) sum += __shfl_xor_sync(0xffffffffu, sum, o);
    if ((threadIdx.x & 31) == 0) red[threadIdx.x >> 5] = sum;
    __syncthreads();
    if (threadIdx.x < 8) {
        float t = red[threadIdx.x];
#pragma unroll
        for (int o = 4; o > 0; o >>= 1) t += __shfl_xor_sync(0xffu, t, o);
        if (threadIdx.x == 0) red[0] = t;
    }
    __syncthreads();
    float inv = 1.f / red[0];
#pragma unroll
    for (int i = 0; i < 8; i++) r[threadIdx.x + i*256] = v[i]*inv;
}

__global__ void zero_counts_kernel(int* c) { if (threadIdx.x < NEXP) c[threadIdx.x] = 0; }

__global__ void gate_topk(const float* __restrict__ hn, const float* __restrict__ gw,
                          int* __restrict__ tidx, float* __restrict__ tw,
                          int* __restrict__ counts) {
    int n = blockIdx.x;
    int w = threadIdx.x >> 5, lane = threadIdx.x & 31;
    const float* x = hn + (size_t)n*DIMM;
    const float* g = gw + (size_t)w*DIMM;
    float s = 0.f;
    for (int i = lane; i < DIMM; i += 32) s += x[i]*g[i];
#pragma unroll
    for (int o = 16; o > 0; o >>= 1) s += __shfl_xor_sync(0xffffffffu, s, o);
    __shared__ float sc[NEXP];
    if (lane == 0) sc[w] = s;
    __syncthreads();
    if (threadIdx.x == 0) {
        float mx = sc[0];
        for (int e = 1; e < NEXP; e++) mx = fmaxf(mx, sc[e]);
        float p[NEXP]; float sum = 0.f;
        for (int e = 0; e < NEXP; e++) { p[e] = expf(sc[e]-mx); sum += p[e]; }
        for (int e = 0; e < NEXP; e++) p[e] /= sum;
        int i0 = 0;
        for (int e = 1; e < NEXP; e++) if (p[e] > p[i0]) i0 = e;
        int i1 = -1;
        for (int e = 0; e < NEXP; e++)
            if (e != i0 && (i1 < 0 || p[e] > p[i1])) i1 = e;
        tidx[n*2]   = i0; tidx[n*2+1] = i1;
        tw[n*2]     = p[i0]; tw[n*2+1] = p[i1];
        atomicAdd(&counts[i0], 1);
        atomicAdd(&counts[i1], 1);
    }
}

__global__ void prefix_kernel(const int* __restrict__ counts, int* __restrict__ offs,
                              int* __restrict__ fill) {
    if (threadIdx.x == 0) {
        int a = 0;
        for (int e = 0; e < NEXP; e++) { offs[e] = a; a += counts[e]; }
        offs[NEXP] = a;
    }
    if (threadIdx.x < NEXP) fill[threadIdx.x] = 0;
}

__global__ void scatter_kernel(const int* __restrict__ tidx,
                               const int* __restrict__ offs, int* __restrict__ fill,
                               int* __restrict__ tok, int* __restrict__ smap) {
    int n = blockIdx.x*blockDim.x + threadIdx.x;
    if (n >= NTOK) return;
#pragma unroll
    for (int j = 0; j < TOPK; j++) {
        int e = tidx[n*2+j];
        int slot = offs[e] + atomicAdd(&fill[e], 1);
        tok[slot] = n;
        smap[n*2+j] = slot;
    }
}

__global__ void silu_mul(float* __restrict__ a, const float* __restrict__ b, size_t n) {
    size_t i = (size_t)blockIdx.x*blockDim.x + threadIdx.x;
    if (i >= n) return;
    float x = a[i];
    float s = x / (1.f + __expf(-x));
    a[i] = s * b[i];
}

__global__ void combine_kernel(float* __restrict__ out, const float* __restrict__ eo,
                               const int* __restrict__ smap, const float* __restrict__ tw) {
    size_t idx = (size_t)blockIdx.x*blockDim.x + threadIdx.x;
    if (idx >= (size_t)NTOK*DIMM) return;
    size_t n = idx / DIMM, d = idx % DIMM;
    int s0 = smap[n*2], s1 = smap[n*2+1];
    out[idx] += tw[n*2]*eo[(size_t)s0*DIMM + d] + tw[n*2+1]*eo[(size_t)s1*DIMM + d];
}

// ================= launcher =================
extern "C" void kernel_launch(void* const* d_in, const int* in_sizes, int n_in,
                              void* d_out, int out_size) {
    (void)in_sizes; (void)n_in; (void)out_size;
    const float* x     = (const float*)d_in[0];
    const float* freqs = (const float*)d_in[1];
    const float* att_w = (const float*)d_in[2];
    const float* wq    = (const float*)d_in[3];
    const float* wk    = (const float*)d_in[4];
    const float* wv    = (const float*)d_in[5];
    const float* wo    = (const float*)d_in[6];
    const float* ffn_w = (const float*)d_in[7];
    const float* gw    = (const float*)d_in[8];
    const float* ew1   = (const float*)d_in[9];
    const float* ew2   = (const float*)d_in[10];
    const float* ew3   = (const float*)d_in[11];
    const float* sw1   = (const float*)d_in[12];
    const float* sw2   = (const float*)d_in[13];
    const float* sw3   = (const float*)d_in[14];
    float* out = (float*)d_out;

    float *xn,*q,*k,*v,*scores,*att,*h,*hn,*h1,*h3,*eo,*s1,*s3,*tw;
    int *tidx,*counts,*offs,*fill,*tok,*smap;
    cudaGetSymbolAddress((void**)&xn, g_xn);
    cudaGetSymbolAddress((void**)&q,  g_q);
    cudaGetSymbolAddress((void**)&k,  g_k);
    cudaGetSymbolAddress((void**)&v,  g_v);
    cudaGetSymbolAddress((void**)&scores, g_scores);
    cudaGetSymbolAddress((void**)&att, g_att);
    cudaGetSymbolAddress((void**)&h,   g_h);
    cudaGetSymbolAddress((void**)&hn,  g_hn);
    cudaGetSymbolAddress((void**)&tidx, g_topk_idx);
    cudaGetSymbolAddress((void**)&tw,   g_topk_w);
    cudaGetSymbolAddress((void**)&counts, g_counts);
    cudaGetSymbolAddress((void**)&offs,   g_offsets);
    cudaGetSymbolAddress((void**)&fill,   g_fill);
    cudaGetSymbolAddress((void**)&tok,    g_tok_idx);
    cudaGetSymbolAddress((void**)&smap,   g_slot_map);
    cudaGetSymbolAddress((void**)&h1, g_h1);
    cudaGetSymbolAddress((void**)&h3, g_h3);
    cudaGetSymbolAddress((void**)&eo, g_eo);
    cudaGetSymbolAddress((void**)&s1, g_s1);
    cudaGetSymbolAddress((void**)&s3, g_s3);

    const int T = 256;

    // 1) attention pre-norm
    rmsnorm_kernel<<<NTOK, T>>>(x, att_w, xn);

    // 2) QKV projections (N=1024 -> grid y 16)
    mma_gemm<false,false,false,false><<<dim3(32,16,1), T>>>(xn, wq, q, nullptr,
        NTOK, DIMM, DIMM, DIMM, DIMM, 1.f, 1, 0,0, 0,0, 0,0, nullptr, nullptr);
    mma_gemm<false,false,false,false><<<dim3(32,16,1), T>>>(xn, wk, k, nullptr,
        NTOK, DIMM, DIMM, DIMM, DIMM, 1.f, 1, 0,0, 0,0, 0,0, nullptr, nullptr);
    mma_gemm<false,false,false,false><<<dim3(32,16,1), T>>>(xn, wv, v, nullptr,
        NTOK, DIMM, DIMM, DIMM, DIMM, 1.f, 1, 0,0, 0,0, 0,0, nullptr, nullptr);

    // 3) RoPE
    rope_kernel<<<(NTOK*NHEAD*(HDIM/2))/T, T>>>(q, k, freqs);

    // 4) scores = q @ k^T / 8   (B transposed-on-load)
    mma_gemm<true,false,false,false><<<dim3(16,32,BSZ*NHEAD), T>>>(q, k, scores, nullptr,
        SLEN, HDIM, DIMM, DIMM, SLEN, 0.125f, NHEAD,
        (long long)SLEN*DIMM, (long long)HDIM,
        (long long)SLEN*DIMM, (long long)HDIM,
        (long long)NHEAD*SLEN*SLEN, (long long)SLEN*SLEN, nullptr, nullptr);

    // 5) softmax
    softmax_rows<<<BSZ*NHEAD*SLEN, T>>>(scores);

    // 6) att = probs @ v   (B = v [k][n] direct, per-head column slice)
    mma_gemm<false,false,false,false><<<dim3(16,1,BSZ*NHEAD), T>>>(scores, v, att, nullptr,
        SLEN, SLEN, SLEN, DIMM, DIMM, 1.f, NHEAD,
        (long long)NHEAD*SLEN*SLEN, (long long)SLEN*SLEN,
        (long long)SLEN*DIMM, (long long)HDIM,
        (long long)SLEN*DIMM, (long long)HDIM, nullptr, nullptr);

    // 7) h = x + att @ wo
    mma_gemm<false,false,false,true><<<dim3(32,16,1), T>>>(att, wo, h, x,
        NTOK, DIMM, DIMM, DIMM, DIMM, 1.f, 1, 0,0, 0,0, 0,0, nullptr, nullptr);

    // 8) ffn pre-norm
    rmsnorm_kernel<<<NTOK, T>>>(h, ffn_w, hn);

    // 9) gate + routing
    zero_counts_kernel<<<1, 32>>>(counts);
    gate_topk<<<NTOK, T>>>(hn, gw, tidx, tw, counts);
    prefix_kernel<<<1, 32>>>(counts, offs, fill);
    scatter_kernel<<<(NTOK + T - 1)/T, T>>>(tidx, offs, fill, tok, smap);

    // 10) routed experts
    mma_gemm<false,true,true,false><<<dim3(32,16,NEXP), T>>>(hn, ew1, h1, nullptr,
        0, DIMM, DIMM, HIDD, HIDD, 1.f, 1, 0,0,
        (long long)DIMM*HIDD, 0, 0,0, tok, offs);
    mma_gemm<false,true,true,false><<<dim3(32,16,NEXP), T>>>(hn, ew3, h3, nullptr,
        0, DIMM, DIMM, HIDD, HIDD, 1.f, 1, 0,0,
        (long long)DIMM*HIDD, 0, 0,0, tok, offs);
    silu_mul<<<(unsigned)(((size_t)NSLOT*HIDD)/T), T>>>(h1, h3, (size_t)NSLOT*HIDD);
    mma_gemm<false,false,true,false><<<dim3(32,16,NEXP), T>>>(h1, ew2, eo, nullptr,
        0, HIDD, HIDD, DIMM, DIMM, 1.f, 1, 0,0,
        (long long)HIDD*DIMM, 0, 0,0, nullptr, offs);

    // 11) shared expert
    mma_gemm<false,false,false,false><<<dim3(32,16,1), T>>>(hn, sw1, s1, nullptr,
        NTOK, DIMM, DIMM, HIDD, HIDD, 1.f, 1, 0,0, 0,0, 0,0, nullptr, nullptr);
    mma_gemm<false,false,false,false><<<dim3(32,16,1), T>>>(hn, sw3, s3, nullptr,
        NTOK, DIMM, DIMM, HIDD, HIDD, 1.f, 1, 0,0, 0,0, 0,0, nullptr, nullptr);
    silu_mul<<<(unsigned)(((size_t)NTOK*HIDD)/T), T>>>(s1, s3, (size_t)NTOK*HIDD);
    mma_gemm<false,false,false,true><<<dim3(32,16,1), T>>>(s1, sw2, out, h,
        NTOK, HIDD, HIDD, DIMM, DIMM, 1.f, 1, 0,0, 0,0, 0,0, nullptr, nullptr);

    // 12) routed combine
    combine_kernel<<<(unsigned)(((size_t)NTOK*DIMM)/T), T>>>(out, eo, smap, tw);
}

// round 4
// speedup vs baseline: 1.8691x; 1.1625x over previous
#include <cuda_runtime.h>
#include <math.h>
#include <stdint.h>

#define DIMM 1024
#define NHEAD 16
#define HDIM 64
#define SLEN 2048
#define BSZ 2
#define NTOK (BSZ*SLEN)          // 4096
#define NEXP 8
#define TOPK 2
#define HIDD 1024
#define NSLOT (NTOK*TOPK)        // 8192
#define EPSV 1e-6f

// ================= scratch =================
__device__ float g_xn[NTOK*DIMM];
__device__ float g_q [NTOK*DIMM];
__device__ float g_k [NTOK*DIMM];
__device__ float g_v [NTOK*DIMM];
__device__ float g_scores[(size_t)BSZ*NHEAD*SLEN*SLEN];   // 512 MB
__device__ float g_att[NTOK*DIMM];
__device__ float g_h  [NTOK*DIMM];
__device__ float g_hn [NTOK*DIMM];
__device__ int   g_topk_idx[NTOK*TOPK];
__device__ float g_topk_w [NTOK*TOPK];
__device__ int   g_counts[NEXP];
__device__ int   g_offsets[NEXP+1];
__device__ int   g_fill[NEXP];
__device__ int   g_tok_idx[NSLOT];
__device__ int   g_slot_map[NTOK*TOPK];
__device__ float g_h1[(size_t)NSLOT*HIDD];
__device__ float g_h3[(size_t)NSLOT*HIDD];
__device__ float g_eo[(size_t)NSLOT*DIMM];
__device__ float g_s1[(size_t)NTOK*HIDD];
__device__ float g_s3[(size_t)NTOK*HIDD];

__device__ __forceinline__ uint32_t f2tf32(float f) {
    uint32_t r; asm("cvt.rna.tf32.f32 %0, %1;" : "=r"(r) : "f"(f)); return r;
}

// ================= tf32 mma.sync GEMM =================
// C[BM=128 x BN] (+R) = A[M,K](row-major, lda) @ B
//   BT=false: B global [K,N] row-major (ldb)
//   BT=true : B global [N,K] row-major (ldb), transposed on load
// 8 warps: warpM = wid&3 (32 rows), warpN = wid>>2 (BN/2 cols).
// Warp tile 32 x BN/2 = 2 (m16) x NT (n8) mma tiles; BK=16, double-buffered smem.
template<int BN, bool BT, bool GATHER, bool GROUPED, bool RESID>
__global__ void __launch_bounds__(256) mma_gemm(
    const float* __restrict__ A, const float* __restrict__ B,
    float* __restrict__ C, const float* __restrict__ Rr,
    int M, int Kd, int lda, int ldb, int ldc, float scale, int zdiv,
    long long sAo, long long sAi, long long sBo, long long sBi,
    long long sCo, long long sCi,
    const int* __restrict__ gidx, const int* __restrict__ offsets)
{
    constexpr int NT  = BN/16;            // n8 tiles per warp
    constexpr int NBL = (BN == 128) ? 2 : 1;  // B float4 loads per thread
    constexpr int BSTR = BN + 8;
    __shared__ uint32_t As[2][16][136];
    __shared__ uint32_t Bs[2][16][BSTR];
    int tid = threadIdx.x;
    int wid = tid >> 5, lane = tid & 31;
    int warpM = wid & 3, warpN = wid >> 2;

    int Mz = M, seg0 = 0;
    if (GROUPED) {
        int e = blockIdx.z;
        seg0 = offsets[e];
        Mz = offsets[e+1] - seg0;
        B += (size_t)e * sBo;
    } else {
        int z = blockIdx.z; int zo = z / zdiv, zi = z % zdiv;
        A += zo*sAo + zi*sAi; B += zo*sBo + zi*sBi;
        C += zo*sCo + zi*sCi; if (RESID) Rr += zo*sCo + zi*sCi;
    }
    int m0 = blockIdx.x * 128;
    if (GROUPED && m0 >= Mz) return;
    int n0 = blockIdx.y * BN;

    // ---- A: row am, two float4s at k-groups akg*4 and (akg+2)*4 ----
    int am = tid & 127;
    int akg = tid >> 7;                  // 0/1
    bool aOK = true; long long gr;
    if (GROUPED) aOK = (m0 + am) < Mz;
    if (GATHER)        gr = aOK ? (long long)gidx[seg0 + m0 + am] : 0;
    else if (GROUPED)  gr = aOK ? (long long)(seg0 + m0 + am) : 0;
    else               gr = m0 + am;
    const float* aBase = A + (size_t)gr*lda;
    int ak0 = akg*4, ak1 = (akg+2)*4;

    // ---- B load assignment ----
    int b_kb[2], b_n4 = 0, b_n = 0, b_kg[2];
    const float* bBase[2];
    if (!BT) {
        int kb = (BN == 128) ? (tid >> 5) : (tid >> 4);
        b_n4   = (BN == 128) ? (tid & 31) : (tid & 15);
#pragma unroll
        for (int i = 0; i < NBL; i++) {
            b_kb[i] = kb + i*8;
            bBase[i] = B + (size_t)b_kb[i]*ldb + n0 + b_n4*4;
        }
    } else {
        b_n = (BN == 128) ? (tid >> 1) : (tid >> 2);
        int kg = (BN == 128) ? (tid & 1) : (tid & 3);
#pragma unroll
        for (int i = 0; i < NBL; i++) {
            b_kg[i] = kg + i*2;
            bBase[i] = B + (size_t)(n0 + b_n)*ldb + b_kg[i]*4;
        }
    }

    float acc[2][NT][4];
#pragma unroll
    for (int mt = 0; mt < 2; mt++)
#pragma unroll
        for (int nt = 0; nt < NT; nt++)
#pragma unroll
            for (int j = 0; j < 4; j++) acc[mt][nt][j] = 0.f;

    int nc = Kd >> 4;
    float4 aR0, aR1, bR[2];

    // preload chunk 0 and store into buffer 0
    aR0 = aOK ? *(const float4*)(aBase + ak0) : make_float4(0,0,0,0);
    aR1 = aOK ? *(const float4*)(aBase + ak1) : make_float4(0,0,0,0);
#pragma unroll
    for (int i = 0; i < NBL; i++) bR[i] = *(const float4*)bBase[i];
    {
        As[0][ak0+0][am] = f2tf32(aR0.x); As[0][ak0+1][am] = f2tf32(aR0.y);
        As[0][ak0+2][am] = f2tf32(aR0.z); As[0][ak0+3][am] = f2tf32(aR0.w);
        As[0][ak1+0][am] = f2tf32(aR1.x); As[0][ak1+1][am] = f2tf32(aR1.y);
        As[0][ak1+2][am] = f2tf32(aR1.z); As[0][ak1+3][am] = f2tf32(aR1.w);
#pragma unroll
        for (int i = 0; i < NBL; i++) {
            if (!BT) {
                Bs[0][b_kb[i]][b_n4*4+0] = f2tf32(bR[i].x);
                Bs[0][b_kb[i]][b_n4*4+1] = f2tf32(bR[i].y);
                Bs[0][b_kb[i]][b_n4*4+2] = f2tf32(bR[i].z);
                Bs[0][b_kb[i]][b_n4*4+3] = f2tf32(bR[i].w);
            } else {
                int kk = b_kg[i]*4;
                Bs[0][kk+0][b_n] = f2tf32(bR[i].x);
                Bs[0][kk+1][b_n] = f2tf32(bR[i].y);
                Bs[0][kk+2][b_n] = f2tf32(bR[i].z);
                Bs[0][kk+3][b_n] = f2tf32(bR[i].w);
            }
        }
    }
    __syncthreads();

    for (int c = 0; c < nc; c++) {
        int cur = c & 1, nxt = cur ^ 1;
        // prefetch next chunk into registers
        if (c + 1 < nc) {
            int kt = (c + 1) * 16;
            aR0 = aOK ? *(const float4*)(aBase + kt + ak0) : make_float4(0,0,0,0);
            aR1 = aOK ? *(const float4*)(aBase + kt + ak1) : make_float4(0,0,0,0);
#pragma unroll
            for (int i = 0; i < NBL; i++) {
                if (!BT) bR[i] = *(const float4*)(bBase[i] + (size_t)kt*ldb);
                else     bR[i] = *(const float4*)(bBase[i] + kt);
            }
        }
        // compute from current buffer
#pragma unroll
        for (int ks = 0; ks < 2; ks++) {
            int kc = ks*8 + (lane & 3);
            uint32_t af[2][4];
#pragma unroll
            for (int mt = 0; mt < 2; mt++) {
                int mr = warpM*32 + mt*16 + (lane >> 2);
                af[mt][0] = As[cur][kc  ][mr];
                af[mt][1] = As[cur][kc  ][mr+8];
                af[mt][2] = As[cur][kc+4][mr];
                af[mt][3] = As[cur][kc+4][mr+8];
            }
            uint32_t bf[NT][2];
#pragma unroll
            for (int nt = 0; nt < NT; nt++) {
                int ncol = warpN*(BN/2) + nt*8 + (lane >> 2);
                bf[nt][0] = Bs[cur][kc  ][ncol];
                bf[nt][1] = Bs[cur][kc+4][ncol];
            }
#pragma unroll
            for (int mt = 0; mt < 2; mt++)
#pragma unroll
                for (int nt = 0; nt < NT; nt++) {
                    asm volatile(
                        "mma.sync.aligned.m16n8k8.row.col.f32.tf32.tf32.f32 "
                        "{%0,%1,%2,%3}, {%4,%5,%6,%7}, {%8,%9}, {%0,%1,%2,%3};"
                        : "+f"(acc[mt][nt][0]), "+f"(acc[mt][nt][1]),
                          "+f"(acc[mt][nt][2]), "+f"(acc[mt][nt][3])
                        : "r"(af[mt][0]), "r"(af[mt][1]), "r"(af[mt][2]), "r"(af[mt][3]),
                          "r"(bf[nt][0]), "r"(bf[nt][1]));
                }
        }
        // store next chunk into the other buffer
        if (c + 1 < nc) {
            As[nxt][ak0+0][am] = f2tf32(aR0.x); As[nxt][ak0+1][am] = f2tf32(aR0.y);
            As[nxt][ak0+2][am] = f2tf32(aR0.z); As[nxt][ak0+3][am] = f2tf32(aR0.w);
            As[nxt][ak1+0][am] = f2tf32(aR1.x); As[nxt][ak1+1][am] = f2tf32(aR1.y);
            As[nxt][ak1+2][am] = f2tf32(aR1.z); As[nxt][ak1+3][am] = f2tf32(aR1.w);
#pragma unroll
            for (int i = 0; i < NBL; i++) {
                if (!BT) {
                    Bs[nxt][b_kb[i]][b_n4*4+0] = f2tf32(bR[i].x);
                    Bs[nxt][b_kb[i]][b_n4*4+1] = f2tf32(bR[i].y);
                    Bs[nxt][b_kb[i]][b_n4*4+2] = f2tf32(bR[i].z);
                    Bs[nxt][b_kb[i]][b_n4*4+3] = f2tf32(bR[i].w);
                } else {
                    int kk = b_kg[i]*4;
                    Bs[nxt][kk+0][b_n] = f2tf32(bR[i].x);
                    Bs[nxt][kk+1][b_n] = f2tf32(bR[i].y);
                    Bs[nxt][kk+2][b_n] = f2tf32(bR[i].z);
                    Bs[nxt][kk+3][b_n] = f2tf32(bR[i].w);
                }
            }
        }
        __syncthreads();
    }

    // ---- epilogue ----
#pragma unroll
    for (int mt = 0; mt < 2; mt++) {
        int rbase = m0 + warpM*32 + mt*16 + (lane >> 2);
#pragma unroll
        for (int half = 0; half < 2; half++) {
            int r = rbase + half*8;
            bool rok = (!GROUPED) || (r < Mz);
            if (!rok) continue;
            size_t crow = (size_t)(GROUPED ? (seg0 + r) : r) * ldc;
#pragma unroll
            for (int nt = 0; nt < NT; nt++) {
                int col = n0 + warpN*(BN/2) + nt*8 + (lane & 3)*2;
                float2 v2;
                v2.x = acc[mt][nt][half*2+0] * scale;
                v2.y = acc[mt][nt][half*2+1] * scale;
                if (RESID) {
                    float2 rv = *(const float2*)(Rr + crow + col);
                    v2.x += rv.x; v2.y += rv.y;
                }
                *(float2*)(C + crow + col) = v2;
            }
        }
    }
}

// ================= elementwise / reduction kernels =================
__global__ void rmsnorm_kernel(const float* __restrict__ x, const float* __restrict__ w,
                               float* __restrict__ out) {
    int row = blockIdx.x;
    const float* xr = x + (size_t)row*DIMM;
    float v[4]; float s = 0.f;
#pragma unroll
    for (int i = 0; i < 4; i++) { v[i] = xr[threadIdx.x + i*256]; s += v[i]*v[i]; }
    __shared__ float red[8];
#pragma unroll
    for (int o = 16; o > 0; o >>= 1) s += __shfl_xor_sync(0xffffffffu, s, o);
    if ((threadIdx.x & 31) == 0) red[threadIdx.x >> 5] = s;
    __syncthreads();
    if (threadIdx.x < 8) {
        float t = red[threadIdx.x];
#pragma unroll
        for (int o = 4; o > 0; o >>= 1) t += __shfl_xor_sync(0xffu, t, o);
        if (threadIdx.x == 0) red[0] = t;
    }
    __syncthreads();
    float r = rsqrtf(red[0] / (float)DIMM + EPSV);
#pragma unroll
    for (int i = 0; i < 4; i++) {
        int c = threadIdx.x + i*256;
        out[(size_t)row*DIMM + c] = v[i]*r*w[c];
    }
}

__global__ void rope_kernel(float* __restrict__ q, float* __restrict__ k,
                            const float* __restrict__ freqs) {
    int idx = blockIdx.x*blockDim.x + threadIdx.x;
    if (idx >= NTOK*NHEAD*(HDIM/2)) return;
    int p = idx % (HDIM/2);
    int h = (idx / (HDIM/2)) % NHEAD;
    int n = idx / (NHEAD*(HDIM/2));
    int s = n % SLEN;
    float c  = freqs[(s*(HDIM/2) + p)*2 + 0];
    float sn = freqs[(s*(HDIM/2) + p)*2 + 1];
    size_t base = (size_t)n*DIMM + h*HDIM + 2*p;
    float q0 = q[base], q1 = q[base+1];
    q[base]   = q0*c - q1*sn;
    q[base+1] = q0*sn + q1*c;
    float k0 = k[base], k1 = k[base+1];
    k[base]   = k0*c - k1*sn;
    k[base+1] = k0*sn + k1*c;
}

__global__ void softmax_rows(float* __restrict__ scores) {
    size_t row = blockIdx.x;
    float* r = scores + row*SLEN;
    float v[8]; float mx = -1e30f;
#pragma unroll
    for (int i = 0; i < 8; i++) { v[i] = r[threadIdx.x + i*256]; mx = fmaxf(mx, v[i]); }
    __shared__ float red[8];
#pragma unroll
    for (int o = 16; o > 0; o >>= 1) mx = fmaxf(mx, __shfl_xor_sync(0xffffffffu, mx, o));
    if ((threadIdx.x & 31) == 0) red[threadIdx.x >> 5] = mx;
    __syncthreads();
    if (threadIdx.x < 8) {
        float t = red[threadIdx.x];
#pragma unroll
        for (int o = 4; o > 0; o >>= 1) t = fmaxf(t, __shfl_xor_sync(0xffu, t, o));
        if (threadIdx.x == 0) red[0] = t;
    }
    __syncthreads();
    mx = red[0];
    float sum = 0.f;
#pragma unroll
    for (int i = 0; i < 8; i++) { v[i] = __expf(v[i]-mx); sum += v[i]; }
    __syncthreads();
#pragma unroll
    for (int o = 16; o > 0; o >>= 1) sum += __shfl_xor_sync(0xffffffffu, sum, o);
    if ((threadIdx.x & 31) == 0) red[threadIdx.x >> 5] = sum;
    __syncthreads();
    if (threadIdx.x < 8) {
        float t = red[threadIdx.x];
#pragma unroll
        for (int o = 4; o > 0; o >>= 1) t += __shfl_xor_sync(0xffu, t, o);
        if (threadIdx.x == 0) red[0] = t;
    }
    __syncthreads();
    float inv = 1.f / red[0];
#pragma unroll
    for (int i = 0; i < 8; i++) r[threadIdx.x + i*256] = v[i]*inv;
}

__global__ void zero_counts_kernel(int* c) { if (threadIdx.x < NEXP) c[threadIdx.x] = 0; }

__global__ void gate_topk(const float* __restrict__ hn, const float* __restrict__ gw,
                          int* __restrict__ tidx, float* __restrict__ tw,
                          int* __restrict__ counts) {
    int n = blockIdx.x;
    int w = threadIdx.x >> 5, lane = threadIdx.x & 31;
    const float* x = hn + (size_t)n*DIMM;
    const float* g = gw + (size_t)w*DIMM;
    float s = 0.f;
    for (int i = lane; i < DIMM; i += 32) s += x[i]*g[i];
#pragma unroll
    for (int o = 16; o > 0; o >>= 1) s += __shfl_xor_sync(0xffffffffu, s, o);
    __shared__ float sc[NEXP];
    if (lane == 0) sc[w] = s;
    __syncthreads();
    if (threadIdx.x == 0) {
        float mx = sc[0];
        for (int e = 1; e < NEXP; e++) mx = fmaxf(mx, sc[e]);
        float p[NEXP]; float sum = 0.f;
        for (int e = 0; e < NEXP; e++) { p[e] = expf(sc[e]-mx); sum += p[e]; }
        for (int e = 0; e < NEXP; e++) p[e] /= sum;
        int i0 = 0;
        for (int e = 1; e < NEXP; e++) if (p[e] > p[i0]) i0 = e;
        int i1 = -1;
        for (int e = 0; e < NEXP; e++)
            if (e != i0 && (i1 < 0 || p[e] > p[i1])) i1 = e;
        tidx[n*2]   = i0; tidx[n*2+1] = i1;
        tw[n*2]     = p[i0]; tw[n*2+1] = p[i1];
        atomicAdd(&counts[i0], 1);
        atomicAdd(&counts[i1], 1);
    }
}

__global__ void prefix_kernel(const int* __restrict__ counts, int* __restrict__ offs,
                              int* __restrict__ fill) {
    if (threadIdx.x == 0) {
        int a = 0;
        for (int e = 0; e < NEXP; e++) { offs[e] = a; a += counts[e]; }
        offs[NEXP] = a;
    }
    if (threadIdx.x < NEXP) fill[threadIdx.x] = 0;
}

__global__ void scatter_kernel(const int* __restrict__ tidx,
                               const int* __restrict__ offs, int* __restrict__ fill,
                               int* __restrict__ tok, int* __restrict__ smap) {
    int n = blockIdx.x*blockDim.x + threadIdx.x;
    if (n >= NTOK) return;
#pragma unroll
    for (int j = 0; j < TOPK; j++) {
        int e = tidx[n*2+j];
        int slot = offs[e] + atomicAdd(&fill[e], 1);
        tok[slot] = n;
        smap[n*2+j] = slot;
    }
}

__global__ void silu_mul(float* __restrict__ a, const float* __restrict__ b, size_t n) {
    size_t i = (size_t)blockIdx.x*blockDim.x + threadIdx.x;
    if (i >= n) return;
    float x = a[i];
    float s = x / (1.f + __expf(-x));
    a[i] = s * b[i];
}

__global__ void combine_kernel(float* __restrict__ out, const float* __restrict__ eo,
                               const int* __restrict__ smap, const float* __restrict__ tw) {
    size_t idx = (size_t)blockIdx.x*blockDim.x + threadIdx.x;
    if (idx >= (size_t)NTOK*DIMM) return;
    size_t n = idx / DIMM, d = idx % DIMM;
    int s0 = smap[n*2], s1 = smap[n*2+1];
    out[idx] += tw[n*2]*eo[(size_t)s0*DIMM + d] + tw[n*2+1]*eo[(size_t)s1*DIMM + d];
}

// ================= launcher =================
extern "C" void kernel_launch(void* const* d_in, const int* in_sizes, int n_in,
                              void* d_out, int out_size) {
    (void)in_sizes; (void)n_in; (void)out_size;
    const float* x     = (const float*)d_in[0];
    const float* freqs = (const float*)d_in[1];
    const float* att_w = (const float*)d_in[2];
    const float* wq    = (const float*)d_in[3];
    const float* wk    = (const float*)d_in[4];
    const float* wv    = (const float*)d_in[5];
    const float* wo    = (const float*)d_in[6];
    const float* ffn_w = (const float*)d_in[7];
    const float* gw    = (const float*)d_in[8];
    const float* ew1   = (const float*)d_in[9];
    const float* ew2   = (const float*)d_in[10];
    const float* ew3   = (const float*)d_in[11];
    const float* sw1   = (const float*)d_in[12];
    const float* sw2   = (const float*)d_in[13];
    const float* sw3   = (const float*)d_in[14];
    float* out = (float*)d_out;

    float *xn,*q,*k,*v,*scores,*att,*h,*hn,*h1,*h3,*eo,*s1,*s3,*tw;
    int *tidx,*counts,*offs,*fill,*tok,*smap;
    cudaGetSymbolAddress((void**)&xn, g_xn);
    cudaGetSymbolAddress((void**)&q,  g_q);
    cudaGetSymbolAddress((void**)&k,  g_k);
    cudaGetSymbolAddress((void**)&v,  g_v);
    cudaGetSymbolAddress((void**)&scores, g_scores);
    cudaGetSymbolAddress((void**)&att, g_att);
    cudaGetSymbolAddress((void**)&h,   g_h);
    cudaGetSymbolAddress((void**)&hn,  g_hn);
    cudaGetSymbolAddress((void**)&tidx, g_topk_idx);
    cudaGetSymbolAddress((void**)&tw,   g_topk_w);
    cudaGetSymbolAddress((void**)&counts, g_counts);
    cudaGetSymbolAddress((void**)&offs,   g_offsets);
    cudaGetSymbolAddress((void**)&fill,   g_fill);
    cudaGetSymbolAddress((void**)&tok,    g_tok_idx);
    cudaGetSymbolAddress((void**)&smap,   g_slot_map);
    cudaGetSymbolAddress((void**)&h1, g_h1);
    cudaGetSymbolAddress((void**)&h3, g_h3);
    cudaGetSymbolAddress((void**)&eo, g_eo);
    cudaGetSymbolAddress((void**)&s1, g_s1);
    cudaGetSymbolAddress((void**)&s3, g_s3);

    const int T = 256;

    // 1) attention pre-norm
    rmsnorm_kernel<<<NTOK, T>>>(x, att_w, xn);

    // 2) QKV projections (BM=128, BN=128)
    mma_gemm<128,false,false,false,false><<<dim3(32,8,1), T>>>(xn, wq, q, nullptr,
        NTOK, DIMM, DIMM, DIMM, DIMM, 1.f, 1, 0,0, 0,0, 0,0, nullptr, nullptr);
    mma_gemm<128,false,false,false,false><<<dim3(32,8,1), T>>>(xn, wk, k, nullptr,
        NTOK, DIMM, DIMM, DIMM, DIMM, 1.f, 1, 0,0, 0,0, 0,0, nullptr, nullptr);
    mma_gemm<128,false,false,false,false><<<dim3(32,8,1), T>>>(xn, wv, v, nullptr,
        NTOK, DIMM, DIMM, DIMM, DIMM, 1.f, 1, 0,0, 0,0, 0,0, nullptr, nullptr);

    // 3) RoPE
    rope_kernel<<<(NTOK*NHEAD*(HDIM/2))/T, T>>>(q, k, freqs);

    // 4) scores = q @ k^T / 8   (B transposed-on-load)
    mma_gemm<128,true,false,false,false><<<dim3(16,16,BSZ*NHEAD), T>>>(q, k, scores, nullptr,
        SLEN, HDIM, DIMM, DIMM, SLEN, 0.125f, NHEAD,
        (long long)SLEN*DIMM, (long long)HDIM,
        (long long)SLEN*DIMM, (long long)HDIM,
        (long long)NHEAD*SLEN*SLEN, (long long)SLEN*SLEN, nullptr, nullptr);

    // 5) softmax
    softmax_rows<<<BSZ*NHEAD*SLEN, T>>>(scores);

    // 6) att = probs @ v  (BN=64 per-head slice)
    mma_gemm<64,false,false,false,false><<<dim3(16,1,BSZ*NHEAD), T>>>(scores, v, att, nullptr,
        SLEN, SLEN, SLEN, DIMM, DIMM, 1.f, NHEAD,
        (long long)NHEAD*SLEN*SLEN, (long long)SLEN*SLEN,
        (long long)SLEN*DIMM, (long long)HDIM,
        (long long)SLEN*DIMM, (long long)HDIM, nullptr, nullptr);

    // 7) h = x + att @ wo
    mma_gemm<128,false,false,false,true><<<dim3(32,8,1), T>>>(att, wo, h, x,
        NTOK, DIMM, DIMM, DIMM, DIMM, 1.f, 1, 0,0, 0,0, 0,0, nullptr, nullptr);

    // 8) ffn pre-norm
    rmsnorm_kernel<<<NTOK, T>>>(h, ffn_w, hn);

    // 9) gate + routing
    zero_counts_kernel<<<1, 32>>>(counts);
    gate_topk<<<NTOK, T>>>(hn, gw, tidx, tw, counts);
    prefix_kernel<<<1, 32>>>(counts, offs, fill);
    scatter_kernel<<<(NTOK + T - 1)/T, T>>>(tidx, offs, fill, tok, smap);

    // 10) routed experts (grid.x=64 covers worst-case expert load)
    mma_gemm<128,false,true,true,false><<<dim3(64,8,NEXP), T>>>(hn, ew1, h1, nullptr,
        0, DIMM, DIMM, HIDD, HIDD, 1.f, 1, 0,0,
        (long long)DIMM*HIDD, 0, 0,0, tok, offs);
    mma_gemm<128,false,true,true,false><<<dim3(64,8,NEXP), T>>>(hn, ew3, h3, nullptr,
        0, DIMM, DIMM, HIDD, HIDD, 1.f, 1, 0,0,
        (long long)DIMM*HIDD, 0, 0,0, tok, offs);
    silu_mul<<<(unsigned)(((size_t)NSLOT*HIDD)/T), T>>>(h1, h3, (size_t)NSLOT*HIDD);
    mma_gemm<128,false,false,true,false><<<dim3(64,8,NEXP), T>>>(h1, ew2, eo, nullptr,
        0, HIDD, HIDD, DIMM, DIMM, 1.f, 1, 0,0,
        (long long)HIDD*DIMM, 0, 0,0, nullptr, offs);

    // 11) shared expert
    mma_gemm<128,false,false,false,false><<<dim3(32,8,1), T>>>(hn, sw1, s1, nullptr,
        NTOK, DIMM, DIMM, HIDD, HIDD, 1.f, 1, 0,0, 0,0, 0,0, nullptr, nullptr);
    mma_gemm<128,false,false,false,false><<<dim3(32,8,1), T>>>(hn, sw3, s3, nullptr,
        NTOK, DIMM, DIMM, HIDD, HIDD, 1.f, 1, 0,0, 0,0, 0,0, nullptr, nullptr);
    silu_mul<<<(unsigned)(((size_t)NTOK*HIDD)/T), T>>>(s1, s3, (size_t)NTOK*HIDD);
    mma_gemm<128,false,false,false,true><<<dim3(32,8,1), T>>>(s1, sw2, out, h,
        NTOK, HIDD, HIDD, DIMM, DIMM, 1.f, 1, 0,0, 0,0, 0,0, nullptr, nullptr);

    // 12) routed combine
    combine_kernel<<<(unsigned)(((size_t)NTOK*DIMM)/T), T>>>(out, eo, smap, tw);
}

// round 5
// speedup vs baseline: 2.8722x; 1.5367x over previous
#include <cuda_runtime.h>
#include <cuda_fp16.h>
#include <math.h>
#include <stdint.h>

#define DIMM 1024
#define NHEAD 16
#define HDIM 64
#define SLEN 2048
#define BSZ 2
#define NTOK (BSZ*SLEN)          // 4096
#define NEXP 8
#define TOPK 2
#define HIDD 1024
#define NSLOT (NTOK*TOPK)        // 8192
#define EPSV 1e-6f

// ================= scratch =================
__device__ float g_xn[NTOK*DIMM];
__device__ float g_q [NTOK*DIMM];
__device__ float g_k [NTOK*DIMM];
__device__ float g_v [NTOK*DIMM];
__device__ float g_scores[(size_t)BSZ*NHEAD*SLEN*SLEN];   // 512 MB
__device__ float g_att[NTOK*DIMM];
__device__ float g_h  [NTOK*DIMM];
__device__ float g_hn [NTOK*DIMM];
__device__ int   g_topk_idx[NTOK*TOPK];
__device__ float g_topk_w [NTOK*TOPK];
__device__ int   g_counts[NEXP];
__device__ int   g_offsets[NEXP+1];
__device__ int   g_fill[NEXP];
__device__ int   g_tok_idx[NSLOT];
__device__ int   g_slot_map[NTOK*TOPK];
__device__ float g_h1[(size_t)NSLOT*HIDD];
__device__ float g_h3[(size_t)NSLOT*HIDD];
__device__ float g_eo[(size_t)NSLOT*DIMM];
__device__ float g_s1[(size_t)NTOK*HIDD];
__device__ float g_s3[(size_t)NTOK*HIDD];

__device__ __forceinline__ uint32_t f2h2(float lo, float hi) {
    __half2 h = __floats2half2_rn(lo, hi);
    return *reinterpret_cast<uint32_t*>(&h);
}

// ================= fp16 mma.sync GEMM =================
// C[BM=128 x BN] (+R) = A[M,K](row-major, lda) @ B
//   BT=false: B global [K,N] row-major (ldb)
//   BT=true : B global [N,K] row-major (ldb), transposed on load
// smem holds half2 packed along K: As[kp][m], Bs[kp][n]; BK=32 (16 kpairs).
// 8 warps: warpM=wid&3 (32 rows), warpN=wid>>2 (BN/2 cols); 2 x NT m16n8k16 tiles.
template<int BN, bool BT, bool GATHER, bool GROUPED, bool RESID>
__global__ void __launch_bounds__(256) mma_gemm(
    const float* __restrict__ A, const float* __restrict__ B,
    float* __restrict__ C, const float* __restrict__ Rr,
    int M, int Kd, int lda, int ldb, int ldc, float scale, int zdiv,
    long long sAo, long long sAi, long long sBo, long long sBi,
    long long sCo, long long sCi,
    const int* __restrict__ gidx, const int* __restrict__ offsets)
{
    constexpr int NT  = BN/16;            // n8 tiles per warp
    constexpr int BSTR = BN + 8;
    __shared__ uint32_t As[2][16][136];
    __shared__ uint32_t Bs[2][16][BSTR];
    int tid = threadIdx.x;
    int wid = tid >> 5, lane = tid & 31;
    int warpM = wid & 3, warpN = wid >> 2;

    int Mz = M, seg0 = 0;
    if (GROUPED) {
        int e = blockIdx.z;
        seg0 = offsets[e];
        Mz = offsets[e+1] - seg0;
        B += (size_t)e * sBo;
    } else {
        int z = blockIdx.z; int zo = z / zdiv, zi = z % zdiv;
        A += zo*sAo + zi*sAi; B += zo*sBo + zi*sBi;
        C += zo*sCo + zi*sCi; if (RESID) Rr += zo*sCo + zi*sCi;
    }
    int m0 = blockIdx.x * 128;
    if (GROUPED && m0 >= Mz) return;
    int n0 = blockIdx.y * BN;

    // ---- A: row am, 4 float4 quads at k = akg*16 + j*4 ----
    int am = tid & 127;
    int akg = tid >> 7;                  // 0/1
    bool aOK = true; long long gr;
    if (GROUPED) aOK = (m0 + am) < Mz;
    if (GATHER)        gr = aOK ? (long long)gidx[seg0 + m0 + am] : 0;
    else if (GROUPED)  gr = aOK ? (long long)(seg0 + m0 + am) : 0;
    else               gr = m0 + am;
    const float* aBase = A + (size_t)gr*lda + akg*16;

    // ---- B assignment ----
    int bn4 = 0, br = 0, bn = 0, bkg = 0;
    if (!BT) {
        if (BN == 128) { bn4 = tid & 31; br = tid >> 5; }   // kpairs br, br+8
        else           { bn4 = tid & 15; br = tid >> 4; }   // kpair br (0..15)
    } else {
        bn = tid >> 1; bkg = tid & 1;                       // 4 quads at k=bkg*16+j*4
    }
    const float* bBaseT = BT ? (B + (size_t)(n0 + bn)*ldb + bkg*16) : nullptr;

    float acc[2][NT][4];
#pragma unroll
    for (int mt = 0; mt < 2; mt++)
#pragma unroll
        for (int nt = 0; nt < NT; nt++)
#pragma unroll
            for (int j = 0; j < 4; j++) acc[mt][nt][j] = 0.f;

    int nc = Kd >> 5;                     // BK = 32
    uint32_t aU[8], bU[8];

    // ---- prefetch helper (c = chunk index) expanded inline ----
    // A: 4 float4 -> aU[0..7]; B: -> bU[0..7] (BN==64 uses bU[0..3])
#define PREFETCH(c_) do {                                                        \
    int kt_ = (c_) * 32;                                                         \
    _Pragma("unroll")                                                            \
    for (int j = 0; j < 4; j++) {                                                \
        float4 f = aOK ? *(const float4*)(aBase + kt_ + j*4)                     \
                       : make_float4(0,0,0,0);                                   \
        aU[2*j]   = f2h2(f.x, f.y);                                              \
        aU[2*j+1] = f2h2(f.z, f.w);                                              \
    }                                                                            \
    if (!BT) {                                                                   \
        if (BN == 128) {                                                         \
            _Pragma("unroll")                                                    \
            for (int p = 0; p < 2; p++) {                                        \
                const float* b0 = B + (size_t)(kt_ + 2*br + p*16)*ldb + n0 + bn4*4; \
                float4 r0 = *(const float4*)b0;                                  \
                float4 r1 = *(const float4*)(b0 + ldb);                          \
                bU[p*4+0] = f2h2(r0.x, r1.x); bU[p*4+1] = f2h2(r0.y, r1.y);      \
                bU[p*4+2] = f2h2(r0.z, r1.z); bU[p*4+3] = f2h2(r0.w, r1.w);      \
            }                                                                    \
        } else {                                                                 \
            const float* b0 = B + (size_t)(kt_ + 2*br)*ldb + n0 + bn4*4;         \
            float4 r0 = *(const float4*)b0;                                      \
            float4 r1 = *(const float4*)(b0 + ldb);                              \
            bU[0] = f2h2(r0.x, r1.x); bU[1] = f2h2(r0.y, r1.y);                  \
            bU[2] = f2h2(r0.z, r1.z); bU[3] = f2h2(r0.w, r1.w);                  \
        }                                                                        \
    } else {                                                                     \
        _Pragma("unroll")                                                        \
        for (int j = 0; j < 4; j++) {                                            \
            float4 f = *(const float4*)(bBaseT + kt_ + j*4);                     \
            bU[2*j]   = f2h2(f.x, f.y);                                          \
            bU[2*j+1] = f2h2(f.z, f.w);                                          \
        }                                                                        \
    }                                                                            \
} while (0)

#define STORE(buf_) do {                                                         \
    _Pragma("unroll")                                                            \
    for (int j = 0; j < 4; j++) {                                                \
        As[buf_][akg*8 + 2*j    ][am] = aU[2*j];                                 \
        As[buf_][akg*8 + 2*j + 1][am] = aU[2*j+1];                               \
    }                                                                            \
    if (!BT) {                                                                   \
        if (BN == 128) {                                                         \
            *(uint4*)&Bs[buf_][br    ][bn4*4] = make_uint4(bU[0],bU[1],bU[2],bU[3]); \
            *(uint4*)&Bs[buf_][br + 8][bn4*4] = make_uint4(bU[4],bU[5],bU[6],bU[7]); \
        } else {                                                                 \
            *(uint4*)&Bs[buf_][br][bn4*4] = make_uint4(bU[0],bU[1],bU[2],bU[3]); \
        }                                                                        \
    } else {                                                                     \
        _Pragma("unroll")                                                        \
        for (int j = 0; j < 4; j++) {                                            \
            Bs[buf_][bkg*8 + 2*j    ][bn] = bU[2*j];                             \
            Bs[buf_][bkg*8 + 2*j + 1][bn] = bU[2*j+1];                           \
        }                                                                        \
    }                                                                            \
} while (0)

    PREFETCH(0);
    STORE(0);
    __syncthreads();

    for (int c = 0; c < nc; c++) {
        int cur = c & 1, nxt = cur ^ 1;
        if (c + 1 < nc) PREFETCH(c + 1);
        // compute from current buffer: 2 k16 steps
#pragma unroll
        for (int ks = 0; ks < 2; ks++) {
            int kl = ks*8 + (lane & 3);
            int kh = kl + 4;
            uint32_t af[2][4];
#pragma unroll
            for (int mt = 0; mt < 2; mt++) {
                int mr = warpM*32 + mt*16 + (lane >> 2);
                af[mt][0] = As[cur][kl][mr];
                af[mt][1] = As[cur][kl][mr+8];
                af[mt][2] = As[cur][kh][mr];
                af[mt][3] = As[cur][kh][mr+8];
            }
            uint32_t bf[NT][2];
#pragma unroll
            for (int nt = 0; nt < NT; nt++) {
                int ncol = warpN*(BN/2) + nt*8 + (lane >> 2);
                bf[nt][0] = Bs[cur][kl][ncol];
                bf[nt][1] = Bs[cur][kh][ncol];
            }
#pragma unroll
            for (int mt = 0; mt < 2; mt++)
#pragma unroll
                for (int nt = 0; nt < NT; nt++) {
                    asm volatile(
                        "mma.sync.aligned.m16n8k16.row.col.f32.f16.f16.f32 "
                        "{%0,%1,%2,%3}, {%4,%5,%6,%7}, {%8,%9}, {%0,%1,%2,%3};"
                        : "+f"(acc[mt][nt][0]), "+f"(acc[mt][nt][1]),
                          "+f"(acc[mt][nt][2]), "+f"(acc[mt][nt][3])
                        : "r"(af[mt][0]), "r"(af[mt][1]), "r"(af[mt][2]), "r"(af[mt][3]),
                          "r"(bf[nt][0]), "r"(bf[nt][1]));
                }
        }
        if (c + 1 < nc) STORE(nxt);
        __syncthreads();
    }

    // ---- epilogue ----
#pragma unroll
    for (int mt = 0; mt < 2; mt++) {
        int rbase = m0 + warpM*32 + mt*16 + (lane >> 2);
#pragma unroll
        for (int half = 0; half < 2; half++) {
            int r = rbase + half*8;
            bool rok = (!GROUPED) || (r < Mz);
            if (!rok) continue;
            size_t crow = (size_t)(GROUPED ? (seg0 + r) : r) * ldc;
#pragma unroll
            for (int nt = 0; nt < NT; nt++) {
                int col = n0 + warpN*(BN/2) + nt*8 + (lane & 3)*2;
                float2 v2;
                v2.x = acc[mt][nt][half*2+0] * scale;
                v2.y = acc[mt][nt][half*2+1] * scale;
                if (RESID) {
                    float2 rv = *(const float2*)(Rr + crow + col);
                    v2.x += rv.x; v2.y += rv.y;
                }
                *(float2*)(C + crow + col) = v2;
            }
        }
    }
#undef PREFETCH
#undef STORE
}

// ================= elementwise / reduction kernels =================
__global__ void rmsnorm_kernel(const float* __restrict__ x, const float* __restrict__ w,
                               float* __restrict__ out) {
    int row = blockIdx.x;
    const float* xr = x + (size_t)row*DIMM;
    float v[4]; float s = 0.f;
#pragma unroll
    for (int i = 0; i < 4; i++) { v[i] = xr[threadIdx.x + i*256]; s += v[i]*v[i]; }
    __shared__ float red[8];
#pragma unroll
    for (int o = 16; o > 0; o >>= 1) s += __shfl_xor_sync(0xffffffffu, s, o);
    if ((threadIdx.x & 31) == 0) red[threadIdx.x >> 5] = s;
    __syncthreads();
    if (threadIdx.x < 8) {
        float t = red[threadIdx.x];
#pragma unroll
        for (int o = 4; o > 0; o >>= 1) t += __shfl_xor_sync(0xffu, t, o);
        if (threadIdx.x == 0) red[0] = t;
    }
    __syncthreads();
    float r = rsqrtf(red[0] / (float)DIMM + EPSV);
#pragma unroll
    for (int i = 0; i < 4; i++) {
        int c = threadIdx.x + i*256;
        out[(size_t)row*DIMM + c] = v[i]*r*w[c];
    }
}

__global__ void rope_kernel(float* __restrict__ q, float* __restrict__ k,
                            const float* __restrict__ freqs) {
    int idx = blockIdx.x*blockDim.x + threadIdx.x;
    if (idx >= NTOK*NHEAD*(HDIM/2)) return;
    int p = idx % (HDIM/2);
    int h = (idx / (HDIM/2)) % NHEAD;
    int n = idx / (NHEAD*(HDIM/2));
    int s = n % SLEN;
    float c  = freqs[(s*(HDIM/2) + p)*2 + 0];
    float sn = freqs[(s*(HDIM/2) + p)*2 + 1];
    size_t base = (size_t)n*DIMM + h*HDIM + 2*p;
    float q0 = q[base], q1 = q[base+1];
    q[base]   = q0*c - q1*sn;
    q[base+1] = q0*sn + q1*c;
    float k0 = k[base], k1 = k[base+1];
    k[base]   = k0*c - k1*sn;
    k[base+1] = k0*sn + k1*c;
}

__global__ void softmax_rows(float* __restrict__ scores) {
    size_t row = blockIdx.x;
    float* r = scores + row*SLEN;
    float v[8]; float mx = -1e30f;
#pragma unroll
    for (int i = 0; i < 8; i++) { v[i] = r[threadIdx.x + i*256]; mx = fmaxf(mx, v[i]); }
    __shared__ float red[8];
#pragma unroll
    for (int o = 16; o > 0; o >>= 1) mx = fmaxf(mx, __shfl_xor_sync(0xffffffffu, mx, o));
    if ((threadIdx.x & 31) == 0) red[threadIdx.x >> 5] = mx;
    __syncthreads();
    if (threadIdx.x < 8) {
        float t = red[threadIdx.x];
#pragma unroll
        for (int o = 4; o > 0; o >>= 1) t = fmaxf(t, __shfl_xor_sync(0xffu, t, o));
        if (threadIdx.x == 0) red[0] = t;
    }
    __syncthreads();
    mx = red[0];
    float sum = 0.f;
#pragma unroll
    for (int i = 0; i < 8; i++) { v[i] = __expf(v[i]-mx); sum += v[i]; }
    __syncthreads();
#pragma unroll
    for (int o = 16; o > 0; o >>= 1) sum += __shfl_xor_sync(0xffffffffu, sum, o);
    if ((threadIdx.x & 31) == 0) red[threadIdx.x >> 5] = sum;
    __syncthreads();
    if (threadIdx.x < 8) {
        float t = red[threadIdx.x];
#pragma unroll
        for (int o = 4; o > 0; o >>= 1) t += __shfl_xor_sync(0xffu, t, o);
        if (threadIdx.x == 0) red[0] = t;
    }
    __syncthreads();
    float inv = 1.f / red[0];
#pragma unroll
    for (int i = 0; i < 8; i++) r[threadIdx.x + i*256] = v[i]*inv;
}

__global__ void zero_counts_kernel(int* c) { if (threadIdx.x < NEXP) c[threadIdx.x] = 0; }

__global__ void gate_topk(const float* __restrict__ hn, const float* __restrict__ gw,
                          int* __restrict__ tidx, float* __restrict__ tw,
                          int* __restrict__ counts) {
    int n = blockIdx.x;
    int w = threadIdx.x >> 5, lane = threadIdx.x & 31;
    const float* x = hn + (size_t)n*DIMM;
    const float* g = gw + (size_t)w*DIMM;
    float s = 0.f;
    for (int i = lane; i < DIMM; i += 32) s += x[i]*g[i];
#pragma unroll
    for (int o = 16; o > 0; o >>= 1) s += __shfl_xor_sync(0xffffffffu, s, o);
    __shared__ float sc[NEXP];
    if (lane == 0) sc[w] = s;
    __syncthreads();
    if (threadIdx.x == 0) {
        float mx = sc[0];
        for (int e = 1; e < NEXP; e++) mx = fmaxf(mx, sc[e]);
        float p[NEXP]; float sum = 0.f;
        for (int e = 0; e < NEXP; e++) { p[e] = expf(sc[e]-mx); sum += p[e]; }
        for (int e = 0; e < NEXP; e++) p[e] /= sum;
        int i0 = 0;
        for (int e = 1; e < NEXP; e++) if (p[e] > p[i0]) i0 = e;
        int i1 = -1;
        for (int e = 0; e < NEXP; e++)
            if (e != i0 && (i1 < 0 || p[e] > p[i1])) i1 = e;
        tidx[n*2]   = i0; tidx[n*2+1] = i1;
        tw[n*2]     = p[i0]; tw[n*2+1] = p[i1];
        atomicAdd(&counts[i0], 1);
        atomicAdd(&counts[i1], 1);
    }
}

__global__ void prefix_kernel(const int* __restrict__ counts, int* __restrict__ offs,
                              int* __restrict__ fill) {
    if (threadIdx.x == 0) {
        int a = 0;
        for (int e = 0; e < NEXP; e++) { offs[e] = a; a += counts[e]; }
        offs[NEXP] = a;
    }
    if (threadIdx.x < NEXP) fill[threadIdx.x] = 0;
}

__global__ void scatter_kernel(const int* __restrict__ tidx,
                               const int* __restrict__ offs, int* __restrict__ fill,
                               int* __restrict__ tok, int* __restrict__ smap) {
    int n = blockIdx.x*blockDim.x + threadIdx.x;
    if (n >= NTOK) return;
#pragma unroll
    for (int j = 0; j < TOPK; j++) {
        int e = tidx[n*2+j];
        int slot = offs[e] + atomicAdd(&fill[e], 1);
        tok[slot] = n;
        smap[n*2+j] = slot;
    }
}

__global__ void silu_mul(float* __restrict__ a, const float* __restrict__ b, size_t n) {
    size_t i = (size_t)blockIdx.x*blockDim.x + threadIdx.x;
    if (i >= n) return;
    float x = a[i];
    float s = x / (1.f + __expf(-x));
    a[i] = s * b[i];
}

__global__ void combine_kernel(float* __restrict__ out, const float* __restrict__ eo,
                               const int* __restrict__ smap, const float* __restrict__ tw) {
    size_t idx = (size_t)blockIdx.x*blockDim.x + threadIdx.x;
    if (idx >= (size_t)NTOK*DIMM) return;
    size_t n = idx / DIMM, d = idx % DIMM;
    int s0 = smap[n*2], s1 = smap[n*2+1];
    out[idx] += tw[n*2]*eo[(size_t)s0*DIMM + d] + tw[n*2+1]*eo[(size_t)s1*DIMM + d];
}

// ================= launcher =================
extern "C" void kernel_launch(void* const* d_in, const int* in_sizes, int n_in,
                              void* d_out, int out_size) {
    (void)in_sizes; (void)n_in; (void)out_size;
    const float* x     = (const float*)d_in[0];
    const float* freqs = (const float*)d_in[1];
    const float* att_w = (const float*)d_in[2];
    const float* wq    = (const float*)d_in[3];
    const float* wk    = (const float*)d_in[4];
    const float* wv    = (const float*)d_in[5];
    const float* wo    = (const float*)d_in[6];
    const float* ffn_w = (const float*)d_in[7];
    const float* gw    = (const float*)d_in[8];
    const float* ew1   = (const float*)d_in[9];
    const float* ew2   = (const float*)d_in[10];
    const float* ew3   = (const float*)d_in[11];
    const float* sw1   = (const float*)d_in[12];
    const float* sw2   = (const float*)d_in[13];
    const float* sw3   = (const float*)d_in[14];
    float* out = (float*)d_out;

    float *xn,*q,*k,*v,*scores,*att,*h,*hn,*h1,*h3,*eo,*s1,*s3,*tw;
    int *tidx,*counts,*offs,*fill,*tok,*smap;
    cudaGetSymbolAddress((void**)&xn, g_xn);
    cudaGetSymbolAddress((void**)&q,  g_q);
    cudaGetSymbolAddress((void**)&k,  g_k);
    cudaGetSymbolAddress((void**)&v,  g_v);
    cudaGetSymbolAddress((void**)&scores, g_scores);
    cudaGetSymbolAddress((void**)&att, g_att);
    cudaGetSymbolAddress((void**)&h,   g_h);
    cudaGetSymbolAddress((void**)&hn,  g_hn);
    cudaGetSymbolAddress((void**)&tidx, g_topk_idx);
    cudaGetSymbolAddress((void**)&tw,   g_topk_w);
    cudaGetSymbolAddress((void**)&counts, g_counts);
    cudaGetSymbolAddress((void**)&offs,   g_offsets);
    cudaGetSymbolAddress((void**)&fill,   g_fill);
    cudaGetSymbolAddress((void**)&tok,    g_tok_idx);
    cudaGetSymbolAddress((void**)&smap,   g_slot_map);
    cudaGetSymbolAddress((void**)&h1, g_h1);
    cudaGetSymbolAddress((void**)&h3, g_h3);
    cudaGetSymbolAddress((void**)&eo, g_eo);
    cudaGetSymbolAddress((void**)&s1, g_s1);
    cudaGetSymbolAddress((void**)&s3, g_s3);

    const int T = 256;

    // 1) attention pre-norm
    rmsnorm_kernel<<<NTOK, T>>>(x, att_w, xn);

    // 2) QKV projections (BM=128, BN=128)
    mma_gemm<128,false,false,false,false><<<dim3(32,8,1), T>>>(xn, wq, q, nullptr,
        NTOK, DIMM, DIMM, DIMM, DIMM, 1.f, 1, 0,0, 0,0, 0,0, nullptr, nullptr);
    mma_gemm<128,false,false,false,false><<<dim3(32,8,1), T>>>(xn, wk, k, nullptr,
        NTOK, DIMM, DIMM, DIMM, DIMM, 1.f, 1, 0,0, 0,0, 0,0, nullptr, nullptr);
    mma_gemm<128,false,false,false,false><<<dim3(32,8,1), T>>>(xn, wv, v, nullptr,
        NTOK, DIMM, DIMM, DIMM, DIMM, 1.f, 1, 0,0, 0,0, 0,0, nullptr, nullptr);

    // 3) RoPE
    rope_kernel<<<(NTOK*NHEAD*(HDIM/2))/T, T>>>(q, k, freqs);

    // 4) scores = q @ k^T / 8   (B transposed-on-load, K=64)
    mma_gemm<128,true,false,false,false><<<dim3(16,16,BSZ*NHEAD), T>>>(q, k, scores, nullptr,
        SLEN, HDIM, DIMM, DIMM, SLEN, 0.125f, NHEAD,
        (long long)SLEN*DIMM, (long long)HDIM,
        (long long)SLEN*DIMM, (long long)HDIM,
        (long long)NHEAD*SLEN*SLEN, (long long)SLEN*SLEN, nullptr, nullptr);

    // 5) softmax
    softmax_rows<<<BSZ*NHEAD*SLEN, T>>>(scores);

    // 6) att = probs @ v  (BN=64 per-head slice)
    mma_gemm<64,false,false,false,false><<<dim3(16,1,BSZ*NHEAD), T>>>(scores, v, att, nullptr,
        SLEN, SLEN, SLEN, DIMM, DIMM, 1.f, NHEAD,
        (long long)NHEAD*SLEN*SLEN, (long long)SLEN*SLEN,
        (long long)SLEN*DIMM, (long long)HDIM,
        (long long)SLEN*DIMM, (long long)HDIM, nullptr, nullptr);

    // 7) h = x + att @ wo
    mma_gemm<128,false,false,false,true><<<dim3(32,8,1), T>>>(att, wo, h, x,
        NTOK, DIMM, DIMM, DIMM, DIMM, 1.f, 1, 0,0, 0,0, 0,0, nullptr, nullptr);

    // 8) ffn pre-norm
    rmsnorm_kernel<<<NTOK, T>>>(h, ffn_w, hn);

    // 9) gate + routing
    zero_counts_kernel<<<1, 32>>>(counts);
    gate_topk<<<NTOK, T>>>(hn, gw, tidx, tw, counts);
    prefix_kernel<<<1, 32>>>(counts, offs, fill);
    scatter_kernel<<<(NTOK + T - 1)/T, T>>>(tidx, offs, fill, tok, smap);

    // 10) routed experts (grid.x=64 covers worst-case expert load)
    mma_gemm<128,false,true,true,false><<<dim3(64,8,NEXP), T>>>(hn, ew1, h1, nullptr,
        0, DIMM, DIMM, HIDD, HIDD, 1.f, 1, 0,0,
        (long long)DIMM*HIDD, 0, 0,0, tok, offs);
    mma_gemm<128,false,true,true,false><<<dim3(64,8,NEXP), T>>>(hn, ew3, h3, nullptr,
        0, DIMM, DIMM, HIDD, HIDD, 1.f, 1, 0,0,
        (long long)DIMM*HIDD, 0, 0,0, tok, offs);
    silu_mul<<<(unsigned)(((size_t)NSLOT*HIDD)/T), T>>>(h1, h3, (size_t)NSLOT*HIDD);
    mma_gemm<128,false,false,true,false><<<dim3(64,8,NEXP), T>>>(h1, ew2, eo, nullptr,
        0, HIDD, HIDD, DIMM, DIMM, 1.f, 1, 0,0,
        (long long)HIDD*DIMM, 0, 0,0, nullptr, offs);

    // 11) shared expert
    mma_gemm<128,false,false,false,false><<<dim3(32,8,1), T>>>(hn, sw1, s1, nullptr,
        NTOK, DIMM, DIMM, HIDD, HIDD, 1.f, 1, 0,0, 0,0, 0,0, nullptr, nullptr);
    mma_gemm<128,false,false,false,false><<<dim3(32,8,1), T>>>(hn, sw3, s3, nullptr,
        NTOK, DIMM, DIMM, HIDD, HIDD, 1.f, 1, 0,0, 0,0, 0,0, nullptr, nullptr);
    silu_mul<<<(unsigned)(((size_t)NTOK*HIDD)/T), T>>>(s1, s3, (size_t)NTOK*HIDD);
    mma_gemm<128,false,false,false,true><<<dim3(32,8,1), T>>>(s1, sw2, out, h,
        NTOK, HIDD, HIDD, DIMM, DIMM, 1.f, 1, 0,0, 0,0, 0,0, nullptr, nullptr);

    // 12) routed combine
    combine_kernel<<<(unsigned)(((size_t)NTOK*DIMM)/T), T>>>(out, eo, smap, tw);
}

// round 6
// speedup vs baseline: 3.5241x; 1.2270x over previous
#include <cuda_runtime.h>
#include <cuda_fp16.h>
#include <math.h>
#include <stdint.h>

#define DIMM 1024
#define NHEAD 16
#define HDIM 64
#define SLEN 2048
#define BSZ 2
#define NTOK (BSZ*SLEN)          // 4096
#define NEXP 8
#define TOPK 2
#define HIDD 1024
#define NSLOT (NTOK*TOPK)        // 8192
#define EPSV 1e-6f

// ================= scratch =================
__device__ float g_xn[NTOK*DIMM];
__device__ float g_q [NTOK*DIMM];
__device__ float g_k [NTOK*DIMM];
__device__ float g_v [NTOK*DIMM];
__device__ float g_att[NTOK*DIMM];
__device__ float g_h  [NTOK*DIMM];
__device__ float g_hn [NTOK*DIMM];
__device__ int   g_topk_idx[NTOK*TOPK];
__device__ float g_topk_w [NTOK*TOPK];
__device__ int   g_counts[NEXP];
__device__ int   g_offsets[NEXP+1];
__device__ int   g_fill[NEXP];
__device__ int   g_tok_idx[NSLOT];
__device__ int   g_slot_map[NTOK*TOPK];
__device__ float g_h1[(size_t)NSLOT*HIDD];
__device__ float g_h3[(size_t)NSLOT*HIDD];
__device__ float g_eo[(size_t)NSLOT*DIMM];
__device__ float g_s1[(size_t)NTOK*HIDD];
__device__ float g_s3[(size_t)NTOK*HIDD];

__device__ __forceinline__ uint32_t f2h2(float lo, float hi) {
    __half2 h = __floats2half2_rn(lo, hi);
    return *reinterpret_cast<uint32_t*>(&h);
}

#define MMA16816(acc, a0,a1,a2,a3, b0,b1) \
    asm volatile( \
        "mma.sync.aligned.m16n8k16.row.col.f32.f16.f16.f32 " \
        "{%0,%1,%2,%3}, {%4,%5,%6,%7}, {%8,%9}, {%0,%1,%2,%3};" \
        : "+f"((acc)[0]), "+f"((acc)[1]), "+f"((acc)[2]), "+f"((acc)[3]) \
        : "r"(a0), "r"(a1), "r"(a2), "r"(a3), "r"(b0), "r"(b1))

// ================= fp16 mma.sync GEMM =================
template<int BN, bool BT, bool GATHER, bool GROUPED, bool RESID>
__global__ void __launch_bounds__(256) mma_gemm(
    const float* __restrict__ A, const float* __restrict__ B,
    float* __restrict__ C, const float* __restrict__ Rr,
    int M, int Kd, int lda, int ldb, int ldc, float scale, int zdiv,
    long long sAo, long long sAi, long long sBo, long long sBi,
    long long sCo, long long sCi,
    const int* __restrict__ gidx, const int* __restrict__ offsets)
{
    constexpr int NT  = BN/16;
    constexpr int BSTR = BN + 8;
    __shared__ uint32_t As[2][16][136];
    __shared__ uint32_t Bs[2][16][BSTR];
    int tid = threadIdx.x;
    int wid = tid >> 5, lane = tid & 31;
    int warpM = wid & 3, warpN = wid >> 2;

    int Mz = M, seg0 = 0;
    if (GROUPED) {
        int e = blockIdx.z;
        seg0 = offsets[e];
        Mz = offsets[e+1] - seg0;
        B += (size_t)e * sBo;
    } else {
        int z = blockIdx.z; int zo = z / zdiv, zi = z % zdiv;
        A += zo*sAo + zi*sAi; B += zo*sBo + zi*sBi;
        C += zo*sCo + zi*sCi; if (RESID) Rr += zo*sCo + zi*sCi;
    }
    int m0 = blockIdx.x * 128;
    if (GROUPED && m0 >= Mz) return;
    int n0 = blockIdx.y * BN;

    int am = tid & 127;
    int akg = tid >> 7;
    bool aOK = true; long long gr;
    if (GROUPED) aOK = (m0 + am) < Mz;
    if (GATHER)        gr = aOK ? (long long)gidx[seg0 + m0 + am] : 0;
    else if (GROUPED)  gr = aOK ? (long long)(seg0 + m0 + am) : 0;
    else               gr = m0 + am;
    const float* aBase = A + (size_t)gr*lda + akg*16;

    int bn4 = 0, br = 0, bn = 0, bkg = 0;
    if (!BT) {
        if (BN == 128) { bn4 = tid & 31; br = tid >> 5; }
        else           { bn4 = tid & 15; br = tid >> 4; }
    } else {
        bn = tid >> 1; bkg = tid & 1;
    }
    const float* bBaseT = BT ? (B + (size_t)(n0 + bn)*ldb + bkg*16) : nullptr;

    float acc[2][NT][4];
#pragma unroll
    for (int mt = 0; mt < 2; mt++)
#pragma unroll
        for (int nt = 0; nt < NT; nt++)
#pragma unroll
            for (int j = 0; j < 4; j++) acc[mt][nt][j] = 0.f;

    int nc = Kd >> 5;
    uint32_t aU[8], bU[8];

#define PREFETCH(c_) do {                                                        \
    int kt_ = (c_) * 32;                                                         \
    _Pragma("unroll")                                                            \
    for (int j = 0; j < 4; j++) {                                                \
        float4 f = aOK ? *(const float4*)(aBase + kt_ + j*4)                     \
                       : make_float4(0,0,0,0);                                   \
        aU[2*j]   = f2h2(f.x, f.y);                                              \
        aU[2*j+1] = f2h2(f.z, f.w);                                              \
    }                                                                            \
    if (!BT) {                                                                   \
        if (BN == 128) {                                                         \
            _Pragma("unroll")                                                    \
            for (int p = 0; p < 2; p++) {                                        \
                const float* b0 = B + (size_t)(kt_ + 2*br + p*16)*ldb + n0 + bn4*4; \
                float4 r0 = *(const float4*)b0;                                  \
                float4 r1 = *(const float4*)(b0 + ldb);                          \
                bU[p*4+0] = f2h2(r0.x, r1.x); bU[p*4+1] = f2h2(r0.y, r1.y);      \
                bU[p*4+2] = f2h2(r0.z, r1.z); bU[p*4+3] = f2h2(r0.w, r1.w);      \
            }                                                                    \
        } else {                                                                 \
            const float* b0 = B + (size_t)(kt_ + 2*br)*ldb + n0 + bn4*4;         \
            float4 r0 = *(const float4*)b0;                                      \
            float4 r1 = *(const float4*)(b0 + ldb);                              \
            bU[0] = f2h2(r0.x, r1.x); bU[1] = f2h2(r0.y, r1.y);                  \
            bU[2] = f2h2(r0.z, r1.z); bU[3] = f2h2(r0.w, r1.w);                  \
        }                                                                        \
    } else {                                                                     \
        _Pragma("unroll")                                                        \
        for (int j = 0; j < 4; j++) {                                            \
            float4 f = *(const float4*)(bBaseT + kt_ + j*4);                     \
            bU[2*j]   = f2h2(f.x, f.y);                                          \
            bU[2*j+1] = f2h2(f.z, f.w);                                          \
        }                                                                        \
    }                                                                            \
} while (0)

#define STORE(buf_) do {                                                         \
    _Pragma("unroll")                                                            \
    for (int j = 0; j < 4; j++) {                                                \
        As[buf_][akg*8 + 2*j    ][am] = aU[2*j];                                 \
        As[buf_][akg*8 + 2*j + 1][am] = aU[2*j+1];                               \
    }                                                                            \
    if (!BT) {                                                                   \
        if (BN == 128) {                                                         \
            *(uint4*)&Bs[buf_][br    ][bn4*4] = make_uint4(bU[0],bU[1],bU[2],bU[3]); \
            *(uint4*)&Bs[buf_][br + 8][bn4*4] = make_uint4(bU[4],bU[5],bU[6],bU[7]); \
        } else {                                                                 \
            *(uint4*)&Bs[buf_][br][bn4*4] = make_uint4(bU[0],bU[1],bU[2],bU[3]); \
        }                                                                        \
    } else {                                                                     \
        _Pragma("unroll")                                                        \
        for (int j = 0; j < 4; j++) {                                            \
            Bs[buf_][bkg*8 + 2*j    ][bn] = bU[2*j];                             \
            Bs[buf_][bkg*8 + 2*j + 1][bn] = bU[2*j+1];                           \
        }                                                                        \
    }                                                                            \
} while (0)

    PREFETCH(0);
    STORE(0);
    __syncthreads();

    for (int c = 0; c < nc; c++) {
        int cur = c & 1, nxt = cur ^ 1;
        if (c + 1 < nc) PREFETCH(c + 1);
#pragma unroll
        for (int ks = 0; ks < 2; ks++) {
            int kl = ks*8 + (lane & 3);
            int kh = kl + 4;
            uint32_t af[2][4];
#pragma unroll
            for (int mt = 0; mt < 2; mt++) {
                int mr = warpM*32 + mt*16 + (lane >> 2);
                af[mt][0] = As[cur][kl][mr];
                af[mt][1] = As[cur][kl][mr+8];
                af[mt][2] = As[cur][kh][mr];
                af[mt][3] = As[cur][kh][mr+8];
            }
            uint32_t bf[NT][2];
#pragma unroll
            for (int nt = 0; nt < NT; nt++) {
                int ncol = warpN*(BN/2) + nt*8 + (lane >> 2);
                bf[nt][0] = Bs[cur][kl][ncol];
                bf[nt][1] = Bs[cur][kh][ncol];
            }
#pragma unroll
            for (int mt = 0; mt < 2; mt++)
#pragma unroll
                for (int nt = 0; nt < NT; nt++)
                    MMA16816(acc[mt][nt], af[mt][0], af[mt][1], af[mt][2], af[mt][3],
                             bf[nt][0], bf[nt][1]);
        }
        if (c + 1 < nc) STORE(nxt);
        __syncthreads();
    }

#pragma unroll
    for (int mt = 0; mt < 2; mt++) {
        int rbase = m0 + warpM*32 + mt*16 + (lane >> 2);
#pragma unroll
        for (int half = 0; half < 2; half++) {
            int r = rbase + half*8;
            bool rok = (!GROUPED) || (r < Mz);
            if (!rok) continue;
            size_t crow = (size_t)(GROUPED ? (seg0 + r) : r) * ldc;
#pragma unroll
            for (int nt = 0; nt < NT; nt++) {
                int col = n0 + warpN*(BN/2) + nt*8 + (lane & 3)*2;
                float2 v2;
                v2.x = acc[mt][nt][half*2+0] * scale;
                v2.y = acc[mt][nt][half*2+1] * scale;
                if (RESID) {
                    float2 rv = *(const float2*)(Rr + crow + col);
                    v2.x += rv.x; v2.y += rv.y;
                }
                *(float2*)(C + crow + col) = v2;
            }
        }
    }
#undef PREFETCH
#undef STORE
}

// ================= flash attention =================
// grid (SLEN/128, BSZ*NHEAD), 256 threads (8 warps x 16 q-rows).
// K smem: Ks[hd_pair][key] stride 72 (conflict-free).
// V smem: Vs[key_pair][hd ^ (key_pair>>2)] stride 72 (xor swizzle, conflict-free).
__global__ void __launch_bounds__(256) flash_attn(
    const float* __restrict__ q, const float* __restrict__ k,
    const float* __restrict__ v, float* __restrict__ att)
{
    __shared__ uint32_t Ks[32][72];
    __shared__ uint32_t Vs[32][72];
    int tid = threadIdx.x, wid = tid >> 5, lane = tid & 31;
    int bh = blockIdx.y;
    int b = bh >> 4, h = bh & 15;
    const float* qh = q + (size_t)b*SLEN*DIMM + h*HDIM;
    const float* kh = k + (size_t)b*SLEN*DIMM + h*HDIM;
    const float* vh = v + (size_t)b*SLEN*DIMM + h*HDIM;
    float* oh = att + (size_t)b*SLEN*DIMM + h*HDIM;

    int qrow0 = blockIdx.x*128 + wid*16 + (lane >> 2);
    const float SC = 0.125f * 1.44269504f;   // fold 1/sqrt(64) and log2(e)

    // Q fragments (registers, reused across all KV tiles)
    uint32_t qf[4][4];
    {
        const float* qr0 = qh + (size_t)qrow0*DIMM;
        const float* qr1 = qr0 + 8*DIMM;
        int c0 = (lane & 3)*2;
#pragma unroll
        for (int ks = 0; ks < 4; ks++) {
            float2 x0 = *(const float2*)(qr0 + ks*16 + c0);
            float2 x1 = *(const float2*)(qr1 + ks*16 + c0);
            float2 x2 = *(const float2*)(qr0 + ks*16 + 8 + c0);
            float2 x3 = *(const float2*)(qr1 + ks*16 + 8 + c0);
            qf[ks][0] = f2h2(x0.x*SC, x0.y*SC);
            qf[ks][1] = f2h2(x1.x*SC, x1.y*SC);
            qf[ks][2] = f2h2(x2.x*SC, x2.y*SC);
            qf[ks][3] = f2h2(x3.x*SC, x3.y*SC);
        }
    }

    float oacc[8][4];
#pragma unroll
    for (int nt = 0; nt < 8; nt++)
#pragma unroll
        for (int j = 0; j < 4; j++) oacc[nt][j] = 0.f;
    float M0 = -1e30f, M1 = -1e30f, L0 = 0.f, L1 = 0.f;

    // loader assignments
    int kkey = tid & 63, khb = (tid >> 6)*16;    // K: one key, 16 hd
    int vkp  = tid & 31, vhb = (tid >> 5)*8;     // V: key pair, 8 hd
    int vswz = (vkp >> 2) & 7;

    for (int t = 0; t < SLEN/64; t++) {
        int key0 = t*64;
        __syncthreads();
        // ---- load K tile (packed along hd) ----
        {
            const float* kr = kh + (size_t)(key0 + kkey)*DIMM + khb;
#pragma unroll
            for (int j = 0; j < 4; j++) {
                float4 f = *(const float4*)(kr + j*4);
                Ks[(khb >> 1) + 2*j    ][kkey] = f2h2(f.x, f.y);
                Ks[(khb >> 1) + 2*j + 1][kkey] = f2h2(f.z, f.w);
            }
        }
        // ---- load V tile (packed along key, swizzled) ----
        {
            const float* vr0 = vh + (size_t)(key0 + 2*vkp)*DIMM + vhb;
            const float* vr1 = vr0 + DIMM;
            float4 a0 = *(const float4*)vr0, a1 = *(const float4*)(vr0 + 4);
            float4 b0 = *(const float4*)vr1, b1 = *(const float4*)(vr1 + 4);
            Vs[vkp][(vhb+0) ^ vswz] = f2h2(a0.x, b0.x);
            Vs[vkp][(vhb+1) ^ vswz] = f2h2(a0.y, b0.y);
            Vs[vkp][(vhb+2) ^ vswz] = f2h2(a0.z, b0.z);
            Vs[vkp][(vhb+3) ^ vswz] = f2h2(a0.w, b0.w);
            Vs[vkp][(vhb+4) ^ vswz] = f2h2(a1.x, b1.x);
            Vs[vkp][(vhb+5) ^ vswz] = f2h2(a1.y, b1.y);
            Vs[vkp][(vhb+6) ^ vswz] = f2h2(a1.z, b1.z);
            Vs[vkp][(vhb+7) ^ vswz] = f2h2(a1.w, b1.w);
        }
        __syncthreads();

        // ---- S = Q @ K^T (in log2 domain) ----
        float sacc[8][4];
#pragma unroll
        for (int nt = 0; nt < 8; nt++)
#pragma unroll
            for (int j = 0; j < 4; j++) sacc[nt][j] = 0.f;
#pragma unroll
        for (int ks = 0; ks < 4; ks++) {
            int kl = ks*8 + (lane & 3), kh2 = kl + 4;
#pragma unroll
            for (int nt = 0; nt < 8; nt++) {
                int ncol = nt*8 + (lane >> 2);
                uint32_t b0 = Ks[kl ][ncol];
                uint32_t b1 = Ks[kh2][ncol];
                MMA16816(sacc[nt], qf[ks][0], qf[ks][1], qf[ks][2], qf[ks][3], b0, b1);
            }
        }

        // ---- online softmax ----
        float mt0 = -1e30f, mt1 = -1e30f;
#pragma unroll
        for (int nt = 0; nt < 8; nt++) {
            mt0 = fmaxf(mt0, fmaxf(sacc[nt][0], sacc[nt][1]));
            mt1 = fmaxf(mt1, fmaxf(sacc[nt][2], sacc[nt][3]));
        }
        mt0 = fmaxf(mt0, __shfl_xor_sync(0xffffffffu, mt0, 1));
        mt0 = fmaxf(mt0, __shfl_xor_sync(0xffffffffu, mt0, 2));
        mt1 = fmaxf(mt1, __shfl_xor_sync(0xffffffffu, mt1, 1));
        mt1 = fmaxf(mt1, __shfl_xor_sync(0xffffffffu, mt1, 2));
        float Mn0 = fmaxf(M0, mt0), Mn1 = fmaxf(M1, mt1);
        float al0 = exp2f(M0 - Mn0), al1 = exp2f(M1 - Mn1);
        M0 = Mn0; M1 = Mn1;
        float rs0 = 0.f, rs1 = 0.f;
#pragma unroll
        for (int nt = 0; nt < 8; nt++) {
            sacc[nt][0] = exp2f(sacc[nt][0] - M0);
            sacc[nt][1] = exp2f(sacc[nt][1] - M0);
            sacc[nt][2] = exp2f(sacc[nt][2] - M1);
            sacc[nt][3] = exp2f(sacc[nt][3] - M1);
            rs0 += sacc[nt][0] + sacc[nt][1];
            rs1 += sacc[nt][2] + sacc[nt][3];
        }
        L0 = L0*al0 + rs0;
        L1 = L1*al1 + rs1;
#pragma unroll
        for (int nt = 0; nt < 8; nt++) {
            oacc[nt][0] *= al0; oacc[nt][1] *= al0;
            oacc[nt][2] *= al1; oacc[nt][3] *= al1;
        }

        // ---- O += P @ V (P from S accumulators, register-direct) ----
#pragma unroll
        for (int ks = 0; ks < 4; ks++) {
            uint32_t a0 = f2h2(sacc[2*ks  ][0], sacc[2*ks  ][1]);
            uint32_t a1 = f2h2(sacc[2*ks  ][2], sacc[2*ks  ][3]);
            uint32_t a2 = f2h2(sacc[2*ks+1][0], sacc[2*ks+1][1]);
            uint32_t a3 = f2h2(sacc[2*ks+1][2], sacc[2*ks+1][3]);
            int kl = ks*8 + (lane & 3), kh2 = kl + 4;
            int sw0 = (2*ks) & 7, sw1 = (2*ks + 1) & 7;
#pragma unroll
            for (int nt = 0; nt < 8; nt++) {
                int ncol = nt*8 + (lane >> 2);
                uint32_t b0 = Vs[kl ][ncol ^ sw0];
                uint32_t b1 = Vs[kh2][ncol ^ sw1];
                MMA16816(oacc[nt], a0, a1, a2, a3, b0, b1);
            }
        }
    }

    // ---- finalize: O /= L, write ----
    L0 += __shfl_xor_sync(0xffffffffu, L0, 1);
    L0 += __shfl_xor_sync(0xffffffffu, L0, 2);
    L1 += __shfl_xor_sync(0xffffffffu, L1, 1);
    L1 += __shfl_xor_sync(0xffffffffu, L1, 2);
    float inv0 = 1.f / L0, inv1 = 1.f / L1;
    float* or0 = oh + (size_t)qrow0*DIMM;
    float* or1 = or0 + 8*DIMM;
#pragma unroll
    for (int nt = 0; nt < 8; nt++) {
        int col = nt*8 + (lane & 3)*2;
        *(float2*)(or0 + col) = make_float2(oacc[nt][0]*inv0, oacc[nt][1]*inv0);
        *(float2*)(or1 + col) = make_float2(oacc[nt][2]*inv1, oacc[nt][3]*inv1);
    }
}

// ================= elementwise / reduction kernels =================
__global__ void rmsnorm_kernel(const float* __restrict__ x, const float* __restrict__ w,
                               float* __restrict__ out) {
    int row = blockIdx.x;
    const float* xr = x + (size_t)row*DIMM;
    float v[4]; float s = 0.f;
#pragma unroll
    for (int i = 0; i < 4; i++) { v[i] = xr[threadIdx.x + i*256]; s += v[i]*v[i]; }
    __shared__ float red[8];
#pragma unroll
    for (int o = 16; o > 0; o >>= 1) s += __shfl_xor_sync(0xffffffffu, s, o);
    if ((threadIdx.x & 31) == 0) red[threadIdx.x >> 5] = s;
    __syncthreads();
    if (threadIdx.x < 8) {
        float t = red[threadIdx.x];
#pragma unroll
        for (int o = 4; o > 0; o >>= 1) t += __shfl_xor_sync(0xffu, t, o);
        if (threadIdx.x == 0) red[0] = t;
    }
    __syncthreads();
    float r = rsqrtf(red[0] / (float)DIMM + EPSV);
#pragma unroll
    for (int i = 0; i < 4; i++) {
        int c = threadIdx.x + i*256;
        out[(size_t)row*DIMM + c] = v[i]*r*w[c];
    }
}

__global__ void rope_kernel(float* __restrict__ q, float* __restrict__ k,
                            const float* __restrict__ freqs) {
    int idx = blockIdx.x*blockDim.x + threadIdx.x;
    if (idx >= NTOK*NHEAD*(HDIM/2)) return;
    int p = idx % (HDIM/2);
    int h = (idx / (HDIM/2)) % NHEAD;
    int n = idx / (NHEAD*(HDIM/2));
    int s = n % SLEN;
    float c  = freqs[(s*(HDIM/2) + p)*2 + 0];
    float sn = freqs[(s*(HDIM/2) + p)*2 + 1];
    size_t base = (size_t)n*DIMM + h*HDIM + 2*p;
    float q0 = q[base], q1 = q[base+1];
    q[base]   = q0*c - q1*sn;
    q[base+1] = q0*sn + q1*c;
    float k0 = k[base], k1 = k[base+1];
    k[base]   = k0*c - k1*sn;
    k[base+1] = k0*sn + k1*c;
}

__global__ void zero_counts_kernel(int* c) { if (threadIdx.x < NEXP) c[threadIdx.x] = 0; }

__global__ void gate_topk(const float* __restrict__ hn, const float* __restrict__ gw,
                          int* __restrict__ tidx, float* __restrict__ tw,
                          int* __restrict__ counts) {
    int n = blockIdx.x;
    int w = threadIdx.x >> 5, lane = threadIdx.x & 31;
    const float* x = hn + (size_t)n*DIMM;
    const float* g = gw + (size_t)w*DIMM;
    float s = 0.f;
    for (int i = lane; i < DIMM; i += 32) s += x[i]*g[i];
#pragma unroll
    for (int o = 16; o > 0; o >>= 1) s += __shfl_xor_sync(0xffffffffu, s, o);
    __shared__ float sc[NEXP];
    if (lane == 0) sc[w] = s;
    __syncthreads();
    if (threadIdx.x == 0) {
        float mx = sc[0];
        for (int e = 1; e < NEXP; e++) mx = fmaxf(mx, sc[e]);
        float p[NEXP]; float sum = 0.f;
        for (int e = 0; e < NEXP; e++) { p[e] = expf(sc[e]-mx); sum += p[e]; }
        for (int e = 0; e < NEXP; e++) p[e] /= sum;
        int i0 = 0;
        for (int e = 1; e < NEXP; e++) if (p[e] > p[i0]) i0 = e;
        int i1 = -1;
        for (int e = 0; e < NEXP; e++)
            if (e != i0 && (i1 < 0 || p[e] > p[i1])) i1 = e;
        tidx[n*2]   = i0; tidx[n*2+1] = i1;
        tw[n*2]     = p[i0]; tw[n*2+1] = p[i1];
        atomicAdd(&counts[i0], 1);
        atomicAdd(&counts[i1], 1);
    }
}

__global__ void prefix_kernel(const int* __restrict__ counts, int* __restrict__ offs,
                              int* __restrict__ fill) {
    if (threadIdx.x == 0) {
        int a = 0;
        for (int e = 0; e < NEXP; e++) { offs[e] = a; a += counts[e]; }
        offs[NEXP] = a;
    }
    if (threadIdx.x < NEXP) fill[threadIdx.x] = 0;
}

__global__ void scatter_kernel(const int* __restrict__ tidx,
                               const int* __restrict__ offs, int* __restrict__ fill,
                               int* __restrict__ tok, int* __restrict__ smap) {
    int n = blockIdx.x*blockDim.x + threadIdx.x;
    if (n >= NTOK) return;
#pragma unroll
    for (int j = 0; j < TOPK; j++) {
        int e = tidx[n*2+j];
        int slot = offs[e] + atomicAdd(&fill[e], 1);
        tok[slot] = n;
        smap[n*2+j] = slot;
    }
}

__global__ void silu_mul(float* __restrict__ a, const float* __restrict__ b, size_t n) {
    size_t i = (size_t)blockIdx.x*blockDim.x + threadIdx.x;
    if (i >= n) return;
    float x = a[i];
    float s = x / (1.f + __expf(-x));
    a[i] = s * b[i];
}

__global__ void combine_kernel(float* __restrict__ out, const float* __restrict__ eo,
                               const int* __restrict__ smap, const float* __restrict__ tw) {
    size_t idx = (size_t)blockIdx.x*blockDim.x + threadIdx.x;
    if (idx >= (size_t)NTOK*DIMM) return;
    size_t n = idx / DIMM, d = idx % DIMM;
    int s0 = smap[n*2], s1 = smap[n*2+1];
    out[idx] += tw[n*2]*eo[(size_t)s0*DIMM + d] + tw[n*2+1]*eo[(size_t)s1*DIMM + d];
}

// ================= launcher =================
extern "C" void kernel_launch(void* const* d_in, const int* in_sizes, int n_in,
                              void* d_out, int out_size) {
    (void)in_sizes; (void)n_in; (void)out_size;
    const float* x     = (const float*)d_in[0];
    const float* freqs = (const float*)d_in[1];
    const float* att_w = (const float*)d_in[2];
    const float* wq    = (const float*)d_in[3];
    const float* wk    = (const float*)d_in[4];
    const float* wv    = (const float*)d_in[5];
    const float* wo    = (const float*)d_in[6];
    const float* ffn_w = (const float*)d_in[7];
    const float* gw    = (const float*)d_in[8];
    const float* ew1   = (const float*)d_in[9];
    const float* ew2   = (const float*)d_in[10];
    const float* ew3   = (const float*)d_in[11];
    const float* sw1   = (const float*)d_in[12];
    const float* sw2   = (const float*)d_in[13];
    const float* sw3   = (const float*)d_in[14];
    float* out = (float*)d_out;

    float *xn,*q,*k,*v,*att,*h,*hn,*h1,*h3,*eo,*s1,*s3,*tw;
    int *tidx,*counts,*offs,*fill,*tok,*smap;
    cudaGetSymbolAddress((void**)&xn, g_xn);
    cudaGetSymbolAddress((void**)&q,  g_q);
    cudaGetSymbolAddress((void**)&k,  g_k);
    cudaGetSymbolAddress((void**)&v,  g_v);
    cudaGetSymbolAddress((void**)&att, g_att);
    cudaGetSymbolAddress((void**)&h,   g_h);
    cudaGetSymbolAddress((void**)&hn,  g_hn);
    cudaGetSymbolAddress((void**)&tidx, g_topk_idx);
    cudaGetSymbolAddress((void**)&tw,   g_topk_w);
    cudaGetSymbolAddress((void**)&counts, g_counts);
    cudaGetSymbolAddress((void**)&offs,   g_offsets);
    cudaGetSymbolAddress((void**)&fill,   g_fill);
    cudaGetSymbolAddress((void**)&tok,    g_tok_idx);
    cudaGetSymbolAddress((void**)&smap,   g_slot_map);
    cudaGetSymbolAddress((void**)&h1, g_h1);
    cudaGetSymbolAddress((void**)&h3, g_h3);
    cudaGetSymbolAddress((void**)&eo, g_eo);
    cudaGetSymbolAddress((void**)&s1, g_s1);
    cudaGetSymbolAddress((void**)&s3, g_s3);

    const int T = 256;

    // 1) attention pre-norm
    rmsnorm_kernel<<<NTOK, T>>>(x, att_w, xn);

    // 2) QKV projections
    mma_gemm<128,false,false,false,false><<<dim3(32,8,1), T>>>(xn, wq, q, nullptr,
        NTOK, DIMM, DIMM, DIMM, DIMM, 1.f, 1, 0,0, 0,0, 0,0, nullptr, nullptr);
    mma_gemm<128,false,false,false,false><<<dim3(32,8,1), T>>>(xn, wk, k, nullptr,
        NTOK, DIMM, DIMM, DIMM, DIMM, 1.f, 1, 0,0, 0,0, 0,0, nullptr, nullptr);
    mma_gemm<128,false,false,false,false><<<dim3(32,8,1), T>>>(xn, wv, v, nullptr,
        NTOK, DIMM, DIMM, DIMM, DIMM, 1.f, 1, 0,0, 0,0, 0,0, nullptr, nullptr);

    // 3) RoPE
    rope_kernel<<<(NTOK*NHEAD*(HDIM/2))/T, T>>>(q, k, freqs);

    // 4-6) fused flash attention
    flash_attn<<<dim3(SLEN/128, BSZ*NHEAD), T>>>(q, k, v, att);

    // 7) h = x + att @ wo
    mma_gemm<128,false,false,false,true><<<dim3(32,8,1), T>>>(att, wo, h, x,
        NTOK, DIMM, DIMM, DIMM, DIMM, 1.f, 1, 0,0, 0,0, 0,0, nullptr, nullptr);

    // 8) ffn pre-norm
    rmsnorm_kernel<<<NTOK, T>>>(h, ffn_w, hn);

    // 9) gate + routing
    zero_counts_kernel<<<1, 32>>>(counts);
    gate_topk<<<NTOK, T>>>(hn, gw, tidx, tw, counts);
    prefix_kernel<<<1, 32>>>(counts, offs, fill);
    scatter_kernel<<<(NTOK + T - 1)/T, T>>>(tidx, offs, fill, tok, smap);

    // 10) routed experts
    mma_gemm<128,false,true,true,false><<<dim3(64,8,NEXP), T>>>(hn, ew1, h1, nullptr,
        0, DIMM, DIMM, HIDD, HIDD, 1.f, 1, 0,0,
        (long long)DIMM*HIDD, 0, 0,0, tok, offs);
    mma_gemm<128,false,true,true,false><<<dim3(64,8,NEXP), T>>>(hn, ew3, h3, nullptr,
        0, DIMM, DIMM, HIDD, HIDD, 1.f, 1, 0,0,
        (long long)DIMM*HIDD, 0, 0,0, tok, offs);
    silu_mul<<<(unsigned)(((size_t)NSLOT*HIDD)/T), T>>>(h1, h3, (size_t)NSLOT*HIDD);
    mma_gemm<128,false,false,true,false><<<dim3(64,8,NEXP), T>>>(h1, ew2, eo, nullptr,
        0, HIDD, HIDD, DIMM, DIMM, 1.f, 1, 0,0,
        (long long)HIDD*DIMM, 0, 0,0, nullptr, offs);

    // 11) shared expert
    mma_gemm<128,false,false,false,false><<<dim3(32,8,1), T>>>(hn, sw1, s1, nullptr,
        NTOK, DIMM, DIMM, HIDD, HIDD, 1.f, 1, 0,0, 0,0, 0,0, nullptr, nullptr);
    mma_gemm<128,false,false,false,false><<<dim3(32,8,1), T>>>(hn, sw3, s3, nullptr,
        NTOK, DIMM, DIMM, HIDD, HIDD, 1.f, 1, 0,0, 0,0, 0,0, nullptr, nullptr);
    silu_mul<<<(unsigned)(((size_t)NTOK*HIDD)/T), T>>>(s1, s3, (size_t)NTOK*HIDD);
    mma_gemm<128,false,false,false,true><<<dim3(32,8,1), T>>>(s1, sw2, out, h,
        NTOK, HIDD, HIDD, DIMM, DIMM, 1.f, 1, 0,0, 0,0, 0,0, nullptr, nullptr);

    // 12) routed combine
    combine_kernel<<<(unsigned)(((size_t)NTOK*DIMM)/T), T>>>(out, eo, smap, tw);
}

// round 7
// speedup vs baseline: 5.4327x; 1.5416x over previous
#include <cuda_runtime.h>
#include <cuda_fp16.h>
#include <math.h>
#include <stdint.h>

#define DIMM 1024
#define NHEAD 16
#define HDIM 64
#define SLEN 2048
#define BSZ 2
#define NTOK (BSZ*SLEN)          // 4096
#define NEXP 8
#define TOPK 2
#define HIDD 1024
#define NSLOT (NTOK*TOPK)        // 8192
#define EPSV 1e-6f

// GEMM v2 pipeline constants
#define AST 40                   // As row stride (halves) = 80B
#define BST 136                  // Bs row stride (halves) = 272B
#define A_STAGE (128*AST)        // halves per A stage
#define B_STAGE (32*BST)
#define STAGES 3
#define SMEMB (STAGES*(A_STAGE+B_STAGE)*2)

// ================= scratch =================
// half weights
__device__ __half g_wqkvh[(size_t)3*DIMM*DIMM];
__device__ __half g_woh[(size_t)DIMM*DIMM];
__device__ __half g_e13h[(size_t)2*NEXP*DIMM*HIDD];
__device__ __half g_e2h[(size_t)NEXP*HIDD*DIMM];
__device__ __half g_s13wh[(size_t)2*DIMM*HIDD];
__device__ __half g_s2wh[(size_t)HIDD*DIMM];
// half activations
__device__ __half g_xnh[(size_t)NTOK*DIMM];
__device__ __half g_qkvh[(size_t)3*NTOK*DIMM];
__device__ __half g_atth[(size_t)NTOK*DIMM];
__device__ __half g_hnh[(size_t)NTOK*DIMM];
__device__ __half g_g13h[(size_t)NSLOT*HIDD];
__device__ __half g_s13h[(size_t)NTOK*HIDD];
// fp32
__device__ float g_h[(size_t)NTOK*DIMM];
__device__ float g_hn32[(size_t)NTOK*DIMM];
__device__ float g_h13f[(size_t)2*NSLOT*HIDD];
__device__ float g_s13f[(size_t)2*NTOK*HIDD];
__device__ float g_eo[(size_t)NSLOT*DIMM];
// routing
__device__ int   g_topk_idx[NTOK*TOPK];
__device__ float g_topk_w [NTOK*TOPK];
__device__ int   g_counts[NEXP];
__device__ int   g_offsets[NEXP+1];
__device__ int   g_fill[NEXP];
__device__ int   g_tok_idx[NSLOT];
__device__ int   g_slot_map[NTOK*TOPK];

__device__ __forceinline__ uint32_t f2h2(float lo, float hi) {
    __half2 h = __floats2half2_rn(lo, hi);
    return *reinterpret_cast<uint32_t*>(&h);
}
__device__ __forceinline__ uint32_t smem_u32(const void* p) {
    uint32_t a;
    asm("{ .reg .u64 t; cvta.to.shared.u64 t, %1; cvt.u32.u64 %0, t; }" : "=r"(a) : "l"(p));
    return a;
}

#define MMA16816(acc, a0,a1,a2,a3, b0,b1) \
    asm volatile( \
        "mma.sync.aligned.m16n8k16.row.col.f32.f16.f16.f32 " \
        "{%0,%1,%2,%3}, {%4,%5,%6,%7}, {%8,%9}, {%0,%1,%2,%3};" \
        : "+f"((acc)[0]), "+f"((acc)[1]), "+f"((acc)[2]), "+f"((acc)[3]) \
        : "r"(a0), "r"(a1), "r"(a2), "r"(a3), "r"(b0), "r"(b1))

#define LDSM_X4(r, addr) \
    asm volatile("ldmatrix.sync.aligned.m8n8.x4.shared.b16 {%0,%1,%2,%3}, [%4];" \
        : "=r"((r)[0]),"=r"((r)[1]),"=r"((r)[2]),"=r"((r)[3]) : "r"(addr))
#define LDSM_X2T(r0, r1, addr) \
    asm volatile("ldmatrix.sync.aligned.m8n8.x2.trans.shared.b16 {%0,%1}, [%2];" \
        : "=r"(r0),"=r"(r1) : "r"(addr))

#define CP16(dst, src, sz) \
    asm volatile("cp.async.cg.shared.global [%0], [%1], 16, %2;" \
        :: "r"(dst), "l"(src), "r"(sz) : "memory")
#define CPCOMMIT asm volatile("cp.async.commit_group;" ::: "memory")
#define CPWAIT1  asm volatile("cp.async.wait_group 1;" ::: "memory")

// ================= GEMM v2: half A [M,1024], half B [1024,1024] =================
// C[128x128] per CTA; cp.async 3-stage; ldmatrix; mma m16n8k16.
template<bool GATHER, bool GROUPED, bool RESID, bool HALFOUT>
__global__ void __launch_bounds__(256) gemm2(
    const __half* __restrict__ A, const __half* __restrict__ B,
    void* __restrict__ Cv, const float* __restrict__ Rr,
    int M, float scale,
    long long sAo, long long sBo, long long sCo, long long sCg,
    const int* __restrict__ gidx, const int* __restrict__ offsets)
{
    extern __shared__ __half smx[];
    const int LDA = 1024;
    int tid = threadIdx.x, lane = tid & 31, wid = tid >> 5;
    int warpM = wid & 3, warpN = wid >> 2;
    int z = blockIdx.z;

    float* Cf = (float*)Cv;
    __half* Ch = (__half*)Cv;

    int Mz = M, seg0 = 0;
    if (GROUPED) {
        int e = z & 7;
        seg0 = offsets[e]; Mz = offsets[e+1] - seg0;
        B  += (size_t)z * sBo;
        Cf += (size_t)(z >> 3) * sCg;
    } else {
        A += (size_t)z * sAo;
        B += (size_t)z * sBo;
        if (HALFOUT) Ch += (size_t)z * sCo; else Cf += (size_t)z * sCo;
        if (RESID) Rr += (size_t)z * sCo;
    }
    int m0 = blockIdx.x * 128;
    if (GROUPED && m0 >= Mz) return;
    int n0 = blockIdx.y * 128;

    uint32_t AsB = smem_u32(smx);
    uint32_t BsB = AsB + STAGES*A_STAGE*2;

    // ---- loaders ----
    int arow = tid >> 1, acH = (tid & 1)*16;
    bool aOK = (!GROUPED) || ((m0 + arow) < Mz);
    long long grow = 0;
    if (aOK) grow = GATHER ? (long long)gidx[seg0 + m0 + arow]
                  : (GROUPED ? (long long)(seg0 + m0 + arow) : (long long)(m0 + arow));
    const __half* aP = A + (size_t)grow*LDA + acH;
    uint32_t aD = AsB + (arow*AST + acH)*2;
    int aSz = aOK ? 16 : 0;

    int brow = tid >> 3, bH = (tid & 7)*16;
    const __half* bP = B + (size_t)brow*LDA + n0 + bH;
    uint32_t bD = BsB + (brow*BST + bH)*2;

#define LOADST(s_, c_) do { \
    int kt_ = (c_)*32; \
    CP16(aD + (s_)*(A_STAGE*2),      aP + kt_,     aSz); \
    CP16(aD + (s_)*(A_STAGE*2) + 16, aP + kt_ + 8, aSz); \
    CP16(bD + (s_)*(B_STAGE*2),      bP + (size_t)kt_*LDA,     16); \
    CP16(bD + (s_)*(B_STAGE*2) + 16, bP + (size_t)kt_*LDA + 8, 16); \
} while (0)

    float acc[2][8][4];
#pragma unroll
    for (int mt = 0; mt < 2; mt++)
#pragma unroll
        for (int nt = 0; nt < 8; nt++)
#pragma unroll
            for (int j = 0; j < 4; j++) acc[mt][nt][j] = 0.f;

    uint32_t aAddr = AsB + ((warpM*32 + (lane & 15))*AST + ((lane >> 4) & 1)*8)*2;
    uint32_t bAddr = BsB + ((lane & 15)*BST + warpN*64)*2;

    LOADST(0, 0); CPCOMMIT;
    LOADST(1, 1); CPCOMMIT;

    for (int c = 0; c < 32; c++) {
        CPWAIT1;
        __syncthreads();
        int st = c % 3;
        uint32_t aS = aAddr + st*(A_STAGE*2);
        uint32_t bS = bAddr + st*(B_STAGE*2);
#pragma unroll
        for (int ks = 0; ks < 2; ks++) {
            uint32_t af0[4], af1[4];
            LDSM_X4(af0, aS + ks*32);
            LDSM_X4(af1, aS + ks*32 + 16*AST*2);
            uint32_t bf[8][2];
#pragma unroll
            for (int nt = 0; nt < 8; nt++)
                LDSM_X2T(bf[nt][0], bf[nt][1], bS + ks*(16*BST*2) + nt*16);
#pragma unroll
            for (int nt = 0; nt < 8; nt++) {
                MMA16816(acc[0][nt], af0[0],af0[1],af0[2],af0[3], bf[nt][0],bf[nt][1]);
                MMA16816(acc[1][nt], af1[0],af1[1],af1[2],af1[3], bf[nt][0],bf[nt][1]);
            }
        }
        if (c + 2 < 32) { int c2 = c + 2; LOADST(c2 % 3, c2); }
        CPCOMMIT;
    }

    // ---- epilogue ----
#pragma unroll
    for (int mt = 0; mt < 2; mt++) {
        int rb = m0 + warpM*32 + mt*16 + (lane >> 2);
#pragma unroll
        for (int hh = 0; hh < 2; hh++) {
            int r = rb + hh*8;
            if (GROUPED && r >= Mz) continue;
            size_t crow = (size_t)((GROUPED ? seg0 : 0) + r) * 1024;
#pragma unroll
            for (int nt = 0; nt < 8; nt++) {
                int col = n0 + warpN*64 + nt*8 + (lane & 3)*2;
                float vx = acc[mt][nt][hh*2+0]*scale;
                float vy = acc[mt][nt][hh*2+1]*scale;
                if (HALFOUT) {
                    *(uint32_t*)(Ch + crow + col) = f2h2(vx, vy);
                } else {
                    if (RESID) {
                        float2 rv = *(const float2*)(Rr + crow + col);
                        vx += rv.x; vy += rv.y;
                    }
                    *(float2*)(Cf + crow + col) = make_float2(vx, vy);
                }
            }
        }
    }
#undef LOADST
}

// ================= flash attention (half in/out) =================
__global__ void __launch_bounds__(256) flash_attn(
    const __half* __restrict__ qkv, __half* __restrict__ att)
{
    __shared__ uint32_t Ks[32][72];
    __shared__ uint32_t Vs[32][72];
    int tid = threadIdx.x, wid = tid >> 5, lane = tid & 31;
    int bh = blockIdx.y;
    int b = bh >> 4, h = bh & 15;
    size_t plane = (size_t)NTOK*DIMM;
    const __half* qh = qkv +           (size_t)b*SLEN*DIMM + h*HDIM;
    const __half* kh = qkv + plane   + (size_t)b*SLEN*DIMM + h*HDIM;
    const __half* vh = qkv + 2*plane + (size_t)b*SLEN*DIMM + h*HDIM;
    __half* oh = att + (size_t)b*SLEN*DIMM + h*HDIM;

    int qrow0 = blockIdx.x*128 + wid*16 + (lane >> 2);
    const float SC = 0.125f * 1.44269504f;

    // Q fragments (raw, unscaled)
    uint32_t qf[4][4];
    {
        const __half* qr0 = qh + (size_t)qrow0*DIMM;
        const __half* qr1 = qr0 + 8*DIMM;
        int c0 = (lane & 3)*2;
#pragma unroll
        for (int ks = 0; ks < 4; ks++) {
            qf[ks][0] = *(const uint32_t*)(qr0 + ks*16 + c0);
            qf[ks][1] = *(const uint32_t*)(qr1 + ks*16 + c0);
            qf[ks][2] = *(const uint32_t*)(qr0 + ks*16 + 8 + c0);
            qf[ks][3] = *(const uint32_t*)(qr1 + ks*16 + 8 + c0);
        }
    }

    float oacc[8][4];
#pragma unroll
    for (int nt = 0; nt < 8; nt++)
#pragma unroll
        for (int j = 0; j < 4; j++) oacc[nt][j] = 0.f;
    float M0 = -1e30f, M1 = -1e30f, L0 = 0.f, L1 = 0.f;

    int kkey = tid & 63, khb = (tid >> 6)*16;
    int vkp  = tid & 31, vhb = (tid >> 5)*8;
    int vswz = (vkp >> 2) & 7;

    for (int t = 0; t < SLEN/64; t++) {
        int key0 = t*64;
        __syncthreads();
        // K tile
        {
            const __half* kr = kh + (size_t)(key0 + kkey)*DIMM + khb;
            uint4 u0 = *(const uint4*)kr;
            uint4 u1 = *(const uint4*)(kr + 8);
            int kp = khb >> 1;
            Ks[kp+0][kkey] = u0.x; Ks[kp+1][kkey] = u0.y;
            Ks[kp+2][kkey] = u0.z; Ks[kp+3][kkey] = u0.w;
            Ks[kp+4][kkey] = u1.x; Ks[kp+5][kkey] = u1.y;
            Ks[kp+6][kkey] = u1.z; Ks[kp+7][kkey] = u1.w;
        }
        // V tile (interleave key pairs, xor swizzle)
        {
            const __half* vr0 = vh + (size_t)(key0 + 2*vkp)*DIMM + vhb;
            uint4 a = *(const uint4*)vr0;
            uint4 b2 = *(const uint4*)(vr0 + DIMM);
            Vs[vkp][(vhb+0) ^ vswz] = __byte_perm(a.x, b2.x, 0x5410);
            Vs[vkp][(vhb+1) ^ vswz] = __byte_perm(a.x, b2.x, 0x7632);
            Vs[vkp][(vhb+2) ^ vswz] = __byte_perm(a.y, b2.y, 0x5410);
            Vs[vkp][(vhb+3) ^ vswz] = __byte_perm(a.y, b2.y, 0x7632);
            Vs[vkp][(vhb+4) ^ vswz] = __byte_perm(a.z, b2.z, 0x5410);
            Vs[vkp][(vhb+5) ^ vswz] = __byte_perm(a.z, b2.z, 0x7632);
            Vs[vkp][(vhb+6) ^ vswz] = __byte_perm(a.w, b2.w, 0x5410);
            Vs[vkp][(vhb+7) ^ vswz] = __byte_perm(a.w, b2.w, 0x7632);
        }
        __syncthreads();

        // S = Q@K^T (raw)
        float sacc[8][4];
#pragma unroll
        for (int nt = 0; nt < 8; nt++)
#pragma unroll
            for (int j = 0; j < 4; j++) sacc[nt][j] = 0.f;
#pragma unroll
        for (int ks = 0; ks < 4; ks++) {
            int kl = ks*8 + (lane & 3), kh2 = kl + 4;
#pragma unroll
            for (int nt = 0; nt < 8; nt++) {
                int ncol = nt*8 + (lane >> 2);
                uint32_t b0 = Ks[kl ][ncol];
                uint32_t b1 = Ks[kh2][ncol];
                MMA16816(sacc[nt], qf[ks][0], qf[ks][1], qf[ks][2], qf[ks][3], b0, b1);
            }
        }

        // online softmax (scale folded into exp2)
        float mt0 = -1e30f, mt1 = -1e30f;
#pragma unroll
        for (int nt = 0; nt < 8; nt++) {
            mt0 = fmaxf(mt0, fmaxf(sacc[nt][0], sacc[nt][1]));
            mt1 = fmaxf(mt1, fmaxf(sacc[nt][2], sacc[nt][3]));
        }
        mt0 = fmaxf(mt0, __shfl_xor_sync(0xffffffffu, mt0, 1));
        mt0 = fmaxf(mt0, __shfl_xor_sync(0xffffffffu, mt0, 2));
        mt1 = fmaxf(mt1, __shfl_xor_sync(0xffffffffu, mt1, 1));
        mt1 = fmaxf(mt1, __shfl_xor_sync(0xffffffffu, mt1, 2));
        float Mn0 = fmaxf(M0, mt0), Mn1 = fmaxf(M1, mt1);
        float al0 = exp2f((M0 - Mn0)*SC), al1 = exp2f((M1 - Mn1)*SC);
        M0 = Mn0; M1 = Mn1;
        float c0 = M0*SC, c1 = M1*SC;
        float rs0 = 0.f, rs1 = 0.f;
#pragma unroll
        for (int nt = 0; nt < 8; nt++) {
            sacc[nt][0] = exp2f(sacc[nt][0]*SC - c0);
            sacc[nt][1] = exp2f(sacc[nt][1]*SC - c0);
            sacc[nt][2] = exp2f(sacc[nt][2]*SC - c1);
            sacc[nt][3] = exp2f(sacc[nt][3]*SC - c1);
            rs0 += sacc[nt][0] + sacc[nt][1];
            rs1 += sacc[nt][2] + sacc[nt][3];
        }
        L0 = L0*al0 + rs0;
        L1 = L1*al1 + rs1;
#pragma unroll
        for (int nt = 0; nt < 8; nt++) {
            oacc[nt][0] *= al0; oacc[nt][1] *= al0;
            oacc[nt][2] *= al1; oacc[nt][3] *= al1;
        }

        // O += P@V
#pragma unroll
        for (int ks = 0; ks < 4; ks++) {
            uint32_t a0 = f2h2(sacc[2*ks  ][0], sacc[2*ks  ][1]);
            uint32_t a1 = f2h2(sacc[2*ks  ][2], sacc[2*ks  ][3]);
            uint32_t a2 = f2h2(sacc[2*ks+1][0], sacc[2*ks+1][1]);
            uint32_t a3 = f2h2(sacc[2*ks+1][2], sacc[2*ks+1][3]);
            int kl = ks*8 + (lane & 3), kh2 = kl + 4;
            int sw0 = (2*ks) & 7, sw1 = (2*ks + 1) & 7;
#pragma unroll
            for (int nt = 0; nt < 8; nt++) {
                int ncol = nt*8 + (lane >> 2);
                uint32_t b0 = Vs[kl ][ncol ^ sw0];
                uint32_t b1 = Vs[kh2][ncol ^ sw1];
                MMA16816(oacc[nt], a0, a1, a2, a3, b0, b1);
            }
        }
    }

    L0 += __shfl_xor_sync(0xffffffffu, L0, 1);
    L0 += __shfl_xor_sync(0xffffffffu, L0, 2);
    L1 += __shfl_xor_sync(0xffffffffu, L1, 1);
    L1 += __shfl_xor_sync(0xffffffffu, L1, 2);
    float inv0 = 1.f / L0, inv1 = 1.f / L1;
    __half* or0 = oh + (size_t)qrow0*DIMM;
    __half* or1 = or0 + 8*DIMM;
#pragma unroll
    for (int nt = 0; nt < 8; nt++) {
        int col = nt*8 + (lane & 3)*2;
        *(uint32_t*)(or0 + col) = f2h2(oacc[nt][0]*inv0, oacc[nt][1]*inv0);
        *(uint32_t*)(or1 + col) = f2h2(oacc[nt][2]*inv1, oacc[nt][3]*inv1);
    }
}

// ================= elementwise kernels =================
__global__ void cvt_half(const float* __restrict__ s, __half* __restrict__ d, int n) {
    int i = (blockIdx.x*blockDim.x + threadIdx.x)*4;
    if (i >= n) return;
    float4 f = *(const float4*)(s + i);
    uint2 o; o.x = f2h2(f.x, f.y); o.y = f2h2(f.z, f.w);
    *(uint2*)(d + i) = o;
}

__global__ void rmsnorm_kernel(const float* __restrict__ x, const float* __restrict__ w,
                               __half* __restrict__ outh, float* __restrict__ outf) {
    int row = blockIdx.x;
    const float* xr = x + (size_t)row*DIMM;
    float v[4]; float s = 0.f;
#pragma unroll
    for (int i = 0; i < 4; i++) { v[i] = xr[threadIdx.x + i*256]; s += v[i]*v[i]; }
    __shared__ float red[8];
#pragma unroll
    for (int o = 16; o > 0; o >>= 1) s += __shfl_xor_sync(0xffffffffu, s, o);
    if ((threadIdx.x & 31) == 0) red[threadIdx.x >> 5] = s;
    __syncthreads();
    if (threadIdx.x < 8) {
        float t = red[threadIdx.x];
#pragma unroll
        for (int o = 4; o > 0; o >>= 1) t += __shfl_xor_sync(0xffu, t, o);
        if (threadIdx.x == 0) red[0] = t;
    }
    __syncthreads();
    float r = rsqrtf(red[0] / (float)DIMM + EPSV);
#pragma unroll
    for (int i = 0; i < 4; i++) {
        int c = threadIdx.x + i*256;
        float val = v[i]*r*w[c];
        outh[(size_t)row*DIMM + c] = __float2half(val);
        if (outf) outf[(size_t)row*DIMM + c] = val;
    }
}

__global__ void rope_half(__half* __restrict__ qkv, const float* __restrict__ freqs) {
    int idx = blockIdx.x*blockDim.x + threadIdx.x;
    if (idx >= NTOK*NHEAD*(HDIM/2)) return;
    int p = idx % (HDIM/2);
    int h = (idx / (HDIM/2)) % NHEAD;
    int n = idx / (NHEAD*(HDIM/2));
    int s = n % SLEN;
    float c  = freqs[(s*(HDIM/2) + p)*2 + 0];
    float sn = freqs[(s*(HDIM/2) + p)*2 + 1];
    size_t base = (size_t)n*DIMM + h*HDIM + 2*p;
    __half2* q2 = (__half2*)(qkv + base);
    __half2* k2 = (__half2*)(qkv + (size_t)NTOK*DIMM + base);
    float2 qv = __half22float2(*q2);
    *q2 = __floats2half2_rn(qv.x*c - qv.y*sn, qv.x*sn + qv.y*c);
    float2 kv = __half22float2(*k2);
    *k2 = __floats2half2_rn(kv.x*c - kv.y*sn, kv.x*sn + kv.y*c);
}

__global__ void zero_counts_kernel(int* c) { if (threadIdx.x < NEXP) c[threadIdx.x] = 0; }

__global__ void gate_topk(const float* __restrict__ hn, const float* __restrict__ gw,
                          int* __restrict__ tidx, float* __restrict__ tw,
                          int* __restrict__ counts) {
    int n = blockIdx.x;
    int w = threadIdx.x >> 5, lane = threadIdx.x & 31;
    const float* x = hn + (size_t)n*DIMM;
    const float* g = gw + (size_t)w*DIMM;
    float s = 0.f;
    for (int i = lane; i < DIMM; i += 32) s += x[i]*g[i];
#pragma unroll
    for (int o = 16; o > 0; o >>= 1) s += __shfl_xor_sync(0xffffffffu, s, o);
    __shared__ float sc[NEXP];
    if (lane == 0) sc[w] = s;
    __syncthreads();
    if (threadIdx.x == 0) {
        float mx = sc[0];
        for (int e = 1; e < NEXP; e++) mx = fmaxf(mx, sc[e]);
        float p[NEXP]; float sum = 0.f;
        for (int e = 0; e < NEXP; e++) { p[e] = expf(sc[e]-mx); sum += p[e]; }
        for (int e = 0; e < NEXP; e++) p[e] /= sum;
        int i0 = 0;
        for (int e = 1; e < NEXP; e++) if (p[e] > p[i0]) i0 = e;
        int i1 = -1;
        for (int e = 0; e < NEXP; e++)
            if (e != i0 && (i1 < 0 || p[e] > p[i1])) i1 = e;
        tidx[n*2]   = i0; tidx[n*2+1] = i1;
        tw[n*2]     = p[i0]; tw[n*2+1] = p[i1];
        atomicAdd(&counts[i0], 1);
        atomicAdd(&counts[i1], 1);
    }
}

__global__ void prefix_kernel(const int* __restrict__ counts, int* __restrict__ offs,
                              int* __restrict__ fill) {
    if (threadIdx.x == 0) {
        int a = 0;
        for (int e = 0; e < NEXP; e++) { offs[e] = a; a += counts[e]; }
        offs[NEXP] = a;
    }
    if (threadIdx.x < NEXP) fill[threadIdx.x] = 0;
}

__global__ void scatter_kernel(const int* __restrict__ tidx,
                               const int* __restrict__ offs, int* __restrict__ fill,
                               int* __restrict__ tok, int* __restrict__ smap) {
    int n = blockIdx.x*blockDim.x + threadIdx.x;
    if (n >= NTOK) return;
#pragma unroll
    for (int j = 0; j < TOPK; j++) {
        int e = tidx[n*2+j];
        int slot = offs[e] + atomicAdd(&fill[e], 1);
        tok[slot] = n;
        smap[n*2+j] = slot;
    }
}

__global__ void silu_mul_h(const float* __restrict__ a, const float* __restrict__ b,
                           __half* __restrict__ o, size_t n) {
    size_t i = ((size_t)blockIdx.x*blockDim.x + threadIdx.x)*4;
    if (i >= n) return;
    float4 av = *(const float4*)(a + i);
    float4 bv = *(const float4*)(b + i);
    float r0 = av.x / (1.f + __expf(-av.x)) * bv.x;
    float r1 = av.y / (1.f + __expf(-av.y)) * bv.y;
    float r2 = av.z / (1.f + __expf(-av.z)) * bv.z;
    float r3 = av.w / (1.f + __expf(-av.w)) * bv.w;
    uint2 ov; ov.x = f2h2(r0, r1); ov.y = f2h2(r2, r3);
    *(uint2*)(o + i) = ov;
}

__global__ void combine_kernel(float* __restrict__ out, const float* __restrict__ eo,
                               const int* __restrict__ smap, const float* __restrict__ tw) {
    size_t idx = (size_t)blockIdx.x*blockDim.x + threadIdx.x;
    if (idx >= (size_t)NTOK*DIMM) return;
    size_t n = idx / DIMM, d = idx % DIMM;
    int s0 = smap[n*2], s1 = smap[n*2+1];
    out[idx] += tw[n*2]*eo[(size_t)s0*DIMM + d] + tw[n*2+1]*eo[(size_t)s1*DIMM + d];
}

// ================= launcher =================
extern "C" void kernel_launch(void* const* d_in, const int* in_sizes, int n_in,
                              void* d_out, int out_size) {
    (void)in_sizes; (void)n_in; (void)out_size;
    const float* x     = (const float*)d_in[0];
    const float* freqs = (const float*)d_in[1];
    const float* att_w = (const float*)d_in[2];
    const float* wq    = (const float*)d_in[3];
    const float* wk    = (const float*)d_in[4];
    const float* wv    = (const float*)d_in[5];
    const float* wo    = (const float*)d_in[6];
    const float* ffn_w = (const float*)d_in[7];
    const float* gw    = (const float*)d_in[8];
    const float* ew1   = (const float*)d_in[9];
    const float* ew2   = (const float*)d_in[10];
    const float* ew3   = (const float*)d_in[11];
    const float* sw1   = (const float*)d_in[12];
    const float* sw2   = (const float*)d_in[13];
    const float* sw3   = (const float*)d_in[14];
    float* out = (float*)d_out;

    __half *wqkvh,*woh,*e13h,*e2h,*s13wh,*s2wh,*xnh,*qkvh,*atth,*hnh,*g13h,*s13h;
    float *h,*hn32,*h13f,*s13f,*eo,*tw;
    int *tidx,*counts,*offs,*fill,*tok,*smap;
    cudaGetSymbolAddress((void**)&wqkvh, g_wqkvh);
    cudaGetSymbolAddress((void**)&woh,   g_woh);
    cudaGetSymbolAddress((void**)&e13h,  g_e13h);
    cudaGetSymbolAddress((void**)&e2h,   g_e2h);
    cudaGetSymbolAddress((void**)&s13wh, g_s13wh);
    cudaGetSymbolAddress((void**)&s2wh,  g_s2wh);
    cudaGetSymbolAddress((void**)&xnh,   g_xnh);
    cudaGetSymbolAddress((void**)&qkvh,  g_qkvh);
    cudaGetSymbolAddress((void**)&atth,  g_atth);
    cudaGetSymbolAddress((void**)&hnh,   g_hnh);
    cudaGetSymbolAddress((void**)&g13h,  g_g13h);
    cudaGetSymbolAddress((void**)&s13h,  g_s13h);
    cudaGetSymbolAddress((void**)&h,     g_h);
    cudaGetSymbolAddress((void**)&hn32,  g_hn32);
    cudaGetSymbolAddress((void**)&h13f,  g_h13f);
    cudaGetSymbolAddress((void**)&s13f,  g_s13f);
    cudaGetSymbolAddress((void**)&eo,    g_eo);
    cudaGetSymbolAddress((void**)&tidx,  g_topk_idx);
    cudaGetSymbolAddress((void**)&tw,    g_topk_w);
    cudaGetSymbolAddress((void**)&counts, g_counts);
    cudaGetSymbolAddress((void**)&offs,   g_offsets);
    cudaGetSymbolAddress((void**)&fill,   g_fill);
    cudaGetSymbolAddress((void**)&tok,    g_tok_idx);
    cudaGetSymbolAddress((void**)&smap,   g_slot_map);

    // opt-in to >48KB dynamic smem (host-side attribute; set every call, harmless)
    cudaFuncSetAttribute(gemm2<false,false,false,true >, cudaFuncAttributeMaxDynamicSharedMemorySize, SMEMB);
    cudaFuncSetAttribute(gemm2<false,false,true, false>, cudaFuncAttributeMaxDynamicSharedMemorySize, SMEMB);
    cudaFuncSetAttribute(gemm2<true, true, false,false>, cudaFuncAttributeMaxDynamicSharedMemorySize, SMEMB);
    cudaFuncSetAttribute(gemm2<false,true, false,false>, cudaFuncAttributeMaxDynamicSharedMemorySize, SMEMB);
    cudaFuncSetAttribute(gemm2<false,false,false,false>, cudaFuncAttributeMaxDynamicSharedMemorySize, SMEMB);

    const int T = 256;
    const int WQN = DIMM*DIMM;       // 1M
    const int EWN = DIMM*HIDD;       // 1M

    // ---- weight conversions ----
    cvt_half<<<WQN/1024, T>>>(wq, wqkvh,          WQN);
    cvt_half<<<WQN/1024, T>>>(wk, wqkvh + WQN,    WQN);
    cvt_half<<<WQN/1024, T>>>(wv, wqkvh + 2*WQN,  WQN);
    cvt_half<<<WQN/1024, T>>>(wo, woh,            WQN);
    cvt_half<<<NEXP*EWN/1024, T>>>(ew1, e13h,             NEXP*EWN);
    cvt_half<<<NEXP*EWN/1024, T>>>(ew3, e13h + (size_t)NEXP*EWN, NEXP*EWN);
    cvt_half<<<NEXP*EWN/1024, T>>>(ew2, e2h,              NEXP*EWN);
    cvt_half<<<EWN/1024, T>>>(sw1, s13wh,        EWN);
    cvt_half<<<EWN/1024, T>>>(sw3, s13wh + EWN,  EWN);
    cvt_half<<<EWN/1024, T>>>(sw2, s2wh,         EWN);

    // 1) attention pre-norm (half out only)
    rmsnorm_kernel<<<NTOK, T>>>(x, att_w, xnh, nullptr);

    // 2) QKV: one GEMM, z=3
    gemm2<false,false,false,true><<<dim3(32,8,3), T, SMEMB>>>(
        xnh, wqkvh, qkvh, nullptr, NTOK, 1.f,
        0, (long long)DIMM*DIMM, (long long)NTOK*DIMM, 0, nullptr, nullptr);

    // 3) RoPE on half q,k
    rope_half<<<(NTOK*NHEAD*(HDIM/2))/T, T>>>(qkvh, freqs);

    // 4) flash attention
    flash_attn<<<dim3(SLEN/128, BSZ*NHEAD), T>>>(qkvh, atth);

    // 5) h = x + att @ wo
    gemm2<false,false,true,false><<<dim3(32,8,1), T, SMEMB>>>(
        atth, woh, h, x, NTOK, 1.f, 0, 0, 0, 0, nullptr, nullptr);

    // 6) ffn pre-norm (half + fp32)
    rmsnorm_kernel<<<NTOK, T>>>(h, ffn_w, hnh, hn32);

    // 7) gate + routing (fp32 hn)
    zero_counts_kernel<<<1, 32>>>(counts);
    gate_topk<<<NTOK, T>>>(hn32, gw, tidx, tw, counts);
    prefix_kernel<<<1, 32>>>(counts, offs, fill);
    scatter_kernel<<<(NTOK + T - 1)/T, T>>>(tidx, offs, fill, tok, smap);

    // 8) experts h1|h3: z=16 (matrix-major over [ew1 x8, ew3 x8])
    gemm2<true,true,false,false><<<dim3(32,8,16), T, SMEMB>>>(
        hnh, e13h, h13f, nullptr, 0, 1.f,
        0, (long long)EWN, 0, (long long)NSLOT*HIDD, tok, offs);
    silu_mul_h<<<(unsigned)(((size_t)NSLOT*HIDD)/1024), T>>>(
        h13f, h13f + (size_t)NSLOT*HIDD, g13h, (size_t)NSLOT*HIDD);
    // eo = g13 @ ew2[e]
    gemm2<false,true,false,false><<<dim3(32,8,NEXP), T, SMEMB>>>(
        g13h, e2h, eo, nullptr, 0, 1.f,
        0, (long long)EWN, 0, 0, nullptr, offs);

    // 9) shared expert: s1|s3 z=2
    gemm2<false,false,false,false><<<dim3(32,8,2), T, SMEMB>>>(
        hnh, s13wh, s13f, nullptr, NTOK, 1.f,
        0, (long long)EWN, (long long)NTOK*HIDD, 0, nullptr, nullptr);
    silu_mul_h<<<(unsigned)(((size_t)NTOK*HIDD)/1024), T>>>(
        s13f, s13f + (size_t)NTOK*HIDD, s13h, (size_t)NTOK*HIDD);
    // out = h + s13 @ sw2
    gemm2<false,false,true,false><<<dim3(32,8,1), T, SMEMB>>>(
        s13h, s2wh, out, h, NTOK, 1.f, 0, 0, 0, 0, nullptr, nullptr);

    // 10) routed combine
    combine_kernel<<<(unsigned)(((size_t)NTOK*DIMM)/T), T>>>(out, eo, smap, tw);
}

// round 8
// speedup vs baseline: 6.4271x; 1.1830x over previous
#include <cuda_runtime.h>
#include <cuda_fp16.h>
#include <math.h>
#include <stdint.h>

#define DIMM 1024
#define NHEAD 16
#define HDIM 64
#define SLEN 2048
#define BSZ 2
#define NTOK (BSZ*SLEN)          // 4096
#define NEXP 8
#define TOPK 2
#define HIDD 1024
#define NSLOT (NTOK*TOPK)        // 8192
#define EPSV 1e-6f

// GEMM pipeline constants
#define AST 40
#define BST 136
#define A_STAGE (128*AST)
#define B_STAGE (32*BST)
#define STAGES 3
#define SMEMB (STAGES*(A_STAGE+B_STAGE)*2)

// ================= scratch =================
__device__ __half g_wqkvh[(size_t)3*DIMM*DIMM];
__device__ __half g_woh[(size_t)DIMM*DIMM];
__device__ __half g_e13h[(size_t)2*NEXP*DIMM*HIDD];
__device__ __half g_e2h[(size_t)NEXP*HIDD*DIMM];
__device__ __half g_s13wh[(size_t)2*DIMM*HIDD];
__device__ __half g_s2wh[(size_t)HIDD*DIMM];
__device__ __half g_xnh[(size_t)NTOK*DIMM];
__device__ __half g_qkvh[(size_t)3*NTOK*DIMM];
__device__ __half g_atth[(size_t)NTOK*DIMM];
__device__ __half g_hnh[(size_t)NTOK*DIMM];
__device__ __half g_g13h[(size_t)NSLOT*HIDD];
__device__ __half g_s13h[(size_t)NTOK*HIDD];
__device__ float g_h[(size_t)NTOK*DIMM];
__device__ float g_hn32[(size_t)NTOK*DIMM];
__device__ float g_h13f[(size_t)2*NSLOT*HIDD];
__device__ float g_s13f[(size_t)2*NTOK*HIDD];
__device__ float g_eo[(size_t)NSLOT*DIMM];
__device__ int   g_topk_idx[NTOK*TOPK];
__device__ float g_topk_w [NTOK*TOPK];
__device__ int   g_counts[NEXP];
__device__ int   g_offsets[NEXP+1];
__device__ int   g_fill[NEXP];
__device__ int   g_tok_idx[NSLOT];
__device__ int   g_slot_map[NTOK*TOPK];

__device__ __forceinline__ uint32_t f2h2(float lo, float hi) {
    __half2 h = __floats2half2_rn(lo, hi);
    return *reinterpret_cast<uint32_t*>(&h);
}
__device__ __forceinline__ uint32_t smem_u32(const void* p) {
    uint32_t a;
    asm("{ .reg .u64 t; cvta.to.shared.u64 t, %1; cvt.u32.u64 %0, t; }" : "=r"(a) : "l"(p));
    return a;
}

#define MMA16816(acc, a0,a1,a2,a3, b0,b1) \
    asm volatile( \
        "mma.sync.aligned.m16n8k16.row.col.f32.f16.f16.f32 " \
        "{%0,%1,%2,%3}, {%4,%5,%6,%7}, {%8,%9}, {%0,%1,%2,%3};" \
        : "+f"((acc)[0]), "+f"((acc)[1]), "+f"((acc)[2]), "+f"((acc)[3]) \
        : "r"(a0), "r"(a1), "r"(a2), "r"(a3), "r"(b0), "r"(b1))

#define LDSM_X4(r, addr) \
    asm volatile("ldmatrix.sync.aligned.m8n8.x4.shared.b16 {%0,%1,%2,%3}, [%4];" \
        : "=r"((r)[0]),"=r"((r)[1]),"=r"((r)[2]),"=r"((r)[3]) : "r"(addr))
#define LDSM_X4T(r, addr) \
    asm volatile("ldmatrix.sync.aligned.m8n8.x4.trans.shared.b16 {%0,%1,%2,%3}, [%4];" \
        : "=r"((r)[0]),"=r"((r)[1]),"=r"((r)[2]),"=r"((r)[3]) : "r"(addr))
#define LDSM_X2T(r0, r1, addr) \
    asm volatile("ldmatrix.sync.aligned.m8n8.x2.trans.shared.b16 {%0,%1}, [%2];" \
        : "=r"(r0),"=r"(r1) : "r"(addr))

#define CP16(dst, src, sz) \
    asm volatile("cp.async.cg.shared.global [%0], [%1], 16, %2;" \
        :: "r"(dst), "l"(src), "r"(sz) : "memory")
#define CPCOMMIT asm volatile("cp.async.commit_group;" ::: "memory")
#define CPWAIT1  asm volatile("cp.async.wait_group 1;" ::: "memory")
#define CPWAIT0  asm volatile("cp.async.wait_group 0;" ::: "memory")

// ================= GEMM: half A [M,1024], half B [1024,1024] =================
template<bool GATHER, bool GROUPED, bool RESID, bool HALFOUT>
__global__ void __launch_bounds__(256) gemm2(
    const __half* __restrict__ A, const __half* __restrict__ B,
    void* __restrict__ Cv, const float* __restrict__ Rr,
    int M, float scale,
    long long sAo, long long sBo, long long sCo, long long sCg,
    const int* __restrict__ gidx, const int* __restrict__ offsets)
{
    extern __shared__ __half smx[];
    const int LDA = 1024;
    int tid = threadIdx.x, lane = tid & 31, wid = tid >> 5;
    int warpM = wid & 3, warpN = wid >> 2;
    int z = blockIdx.z;

    float* Cf = (float*)Cv;
    __half* Ch = (__half*)Cv;

    int Mz = M, seg0 = 0;
    if (GROUPED) {
        int e = z & 7;
        seg0 = offsets[e]; Mz = offsets[e+1] - seg0;
        B  += (size_t)z * sBo;
        Cf += (size_t)(z >> 3) * sCg;
    } else {
        A += (size_t)z * sAo;
        B += (size_t)z * sBo;
        if (HALFOUT) Ch += (size_t)z * sCo; else Cf += (size_t)z * sCo;
        if (RESID) Rr += (size_t)z * sCo;
    }
    int m0 = blockIdx.x * 128;
    if (GROUPED && m0 >= Mz) return;
    int n0 = blockIdx.y * 128;

    uint32_t AsB = smem_u32(smx);
    uint32_t BsB = AsB + STAGES*A_STAGE*2;

    int arow = tid >> 1, acH = (tid & 1)*16;
    bool aOK = (!GROUPED) || ((m0 + arow) < Mz);
    long long grow = 0;
    if (aOK) grow = GATHER ? (long long)gidx[seg0 + m0 + arow]
                  : (GROUPED ? (long long)(seg0 + m0 + arow) : (long long)(m0 + arow));
    const __half* aP = A + (size_t)grow*LDA + acH;
    uint32_t aD = AsB + (arow*AST + acH)*2;
    int aSz = aOK ? 16 : 0;

    int brow = tid >> 3, bH = (tid & 7)*16;
    const __half* bP = B + (size_t)brow*LDA + n0 + bH;
    uint32_t bD = BsB + (brow*BST + bH)*2;

#define LOADST(s_, c_) do { \
    int kt_ = (c_)*32; \
    CP16(aD + (s_)*(A_STAGE*2),      aP + kt_,     aSz); \
    CP16(aD + (s_)*(A_STAGE*2) + 16, aP + kt_ + 8, aSz); \
    CP16(bD + (s_)*(B_STAGE*2),      bP + (size_t)kt_*LDA,     16); \
    CP16(bD + (s_)*(B_STAGE*2) + 16, bP + (size_t)kt_*LDA + 8, 16); \
} while (0)

    float acc[2][8][4];
#pragma unroll
    for (int mt = 0; mt < 2; mt++)
#pragma unroll
        for (int nt = 0; nt < 8; nt++)
#pragma unroll
            for (int j = 0; j < 4; j++) acc[mt][nt][j] = 0.f;

    uint32_t aAddr = AsB + ((warpM*32 + (lane & 15))*AST + ((lane >> 4) & 1)*8)*2;
    uint32_t bAddr = BsB + ((lane & 15)*BST + warpN*64)*2;

    LOADST(0, 0); CPCOMMIT;
    LOADST(1, 1); CPCOMMIT;

    for (int c = 0; c < 32; c++) {
        CPWAIT1;
        __syncthreads();
        int st = c % 3;
        uint32_t aS = aAddr + st*(A_STAGE*2);
        uint32_t bS = bAddr + st*(B_STAGE*2);
#pragma unroll
        for (int ks = 0; ks < 2; ks++) {
            uint32_t af0[4], af1[4];
            LDSM_X4(af0, aS + ks*32);
            LDSM_X4(af1, aS + ks*32 + 16*AST*2);
            uint32_t bf[8][2];
#pragma unroll
            for (int nt = 0; nt < 8; nt++)
                LDSM_X2T(bf[nt][0], bf[nt][1], bS + ks*(16*BST*2) + nt*16);
#pragma unroll
            for (int nt = 0; nt < 8; nt++) {
                MMA16816(acc[0][nt], af0[0],af0[1],af0[2],af0[3], bf[nt][0],bf[nt][1]);
                MMA16816(acc[1][nt], af1[0],af1[1],af1[2],af1[3], bf[nt][0],bf[nt][1]);
            }
        }
        if (c + 2 < 32) { int c2 = c + 2; LOADST(c2 % 3, c2); }
        CPCOMMIT;
    }

#pragma unroll
    for (int mt = 0; mt < 2; mt++) {
        int rb = m0 + warpM*32 + mt*16 + (lane >> 2);
#pragma unroll
        for (int hh = 0; hh < 2; hh++) {
            int r = rb + hh*8;
            if (GROUPED && r >= Mz) continue;
            size_t crow = (size_t)((GROUPED ? seg0 : 0) + r) * 1024;
#pragma unroll
            for (int nt = 0; nt < 8; nt++) {
                int col = n0 + warpN*64 + nt*8 + (lane & 3)*2;
                float vx = acc[mt][nt][hh*2+0]*scale;
                float vy = acc[mt][nt][hh*2+1]*scale;
                if (HALFOUT) {
                    *(uint32_t*)(Ch + crow + col) = f2h2(vx, vy);
                } else {
                    if (RESID) {
                        float2 rv = *(const float2*)(Rr + crow + col);
                        vx += rv.x; vy += rv.y;
                    }
                    *(float2*)(Cf + crow + col) = make_float2(vx, vy);
                }
            }
        }
    }
#undef LOADST
}

// ================= flash attention v2: cp.async double-buffer + ldmatrix =================
// K,V smem in natural [key][hd] layout, 72-half row stride (conflict-free per
// 8-lane ldmatrix phase: banks 4*row+chunk cover all 32).
#define FTILEB (64*72*2)     // bytes per K or V stage
__global__ void __launch_bounds__(256) flash_attn(
    const __half* __restrict__ qkv, __half* __restrict__ att)
{
    __shared__ __align__(16) __half Ksm[2][64][72];
    __shared__ __align__(16) __half Vsm[2][64][72];
    int tid = threadIdx.x, wid = tid >> 5, lane = tid & 31;
    int bh = blockIdx.y;
    int b = bh >> 4, h = bh & 15;
    size_t plane = (size_t)NTOK*DIMM;
    const __half* qh = qkv +           (size_t)b*SLEN*DIMM + h*HDIM;
    const __half* kh = qkv + plane   + (size_t)b*SLEN*DIMM + h*HDIM;
    const __half* vh = qkv + 2*plane + (size_t)b*SLEN*DIMM + h*HDIM;
    __half* oh = att + (size_t)b*SLEN*DIMM + h*HDIM;

    int qrow0 = blockIdx.x*128 + wid*16 + (lane >> 2);
    const float SC = 0.125f * 1.44269504f;

    // Q fragments
    uint32_t qf[4][4];
    {
        const __half* qr0 = qh + (size_t)qrow0*DIMM;
        const __half* qr1 = qr0 + 8*DIMM;
        int c0 = (lane & 3)*2;
#pragma unroll
        for (int ks = 0; ks < 4; ks++) {
            qf[ks][0] = *(const uint32_t*)(qr0 + ks*16 + c0);
            qf[ks][1] = *(const uint32_t*)(qr1 + ks*16 + c0);
            qf[ks][2] = *(const uint32_t*)(qr0 + ks*16 + 8 + c0);
            qf[ks][3] = *(const uint32_t*)(qr1 + ks*16 + 8 + c0);
        }
    }

    float oacc[8][4];
#pragma unroll
    for (int nt = 0; nt < 8; nt++)
#pragma unroll
        for (int j = 0; j < 4; j++) oacc[nt][j] = 0.f;
    float M0 = -1e30f, M1 = -1e30f, L0 = 0.f, L1 = 0.f;

    // cp.async loader: row = tid>>2 (0..63), chunks (tid&3)*2 and +1 (16B each)
    int lrow = tid >> 2, lc = (tid & 3)*2;
    const __half* kSrc = kh + (size_t)lrow*DIMM + lc*8;
    const __half* vSrc = vh + (size_t)lrow*DIMM + lc*8;
    uint32_t kDst = smem_u32(&Ksm[0][lrow][lc*8]);
    uint32_t vDst = smem_u32(&Vsm[0][lrow][lc*8]);

#define FLOAD(buf_, t_) do { \
    size_t off_ = (size_t)(t_)*64*DIMM; \
    CP16(kDst + (buf_)*FTILEB,      kSrc + off_,     16); \
    CP16(kDst + (buf_)*FTILEB + 16, kSrc + off_ + 8, 16); \
    CP16(vDst + (buf_)*FTILEB,      vSrc + off_,     16); \
    CP16(vDst + (buf_)*FTILEB + 16, vSrc + off_ + 8, 16); \
} while (0)

    // fragment address bases
    uint32_t ksBase = smem_u32(&Ksm[0][0][0]);
    uint32_t vsBase = smem_u32(&Vsm[0][0][0]);
    // S-phase (non-trans x4): row = nt2*16 + ((lane>>4)&1)*8 + (lane&7); kbyte = ks*32 + ((lane>>3)&1)*16
    uint32_t sA = ksBase + (((lane>>4)&1)*8 + (lane&7))*144 + ((lane>>3)&1)*16;
    // V-phase (trans x4): row = ks*16 + (lane&15); colbyte = nt2*32 + (lane>>4)*16
    uint32_t vA = vsBase + (lane&15)*144 + (lane>>4)*16;

    FLOAD(0, 0); CPCOMMIT;

    const int NTILES = SLEN/64;
    for (int t = 0; t < NTILES; t++) {
        int buf = t & 1;
        if (t + 1 < NTILES) { FLOAD(buf ^ 1, t + 1); CPCOMMIT; CPWAIT1; }
        else                { CPWAIT0; }
        __syncthreads();

        uint32_t sB = sA + buf*FTILEB;
        uint32_t vB = vA + buf*FTILEB;

        // ---- S = Q@K^T ----
        float sacc[8][4];
#pragma unroll
        for (int nt = 0; nt < 8; nt++)
#pragma unroll
            for (int j = 0; j < 4; j++) sacc[nt][j] = 0.f;
#pragma unroll
        for (int ks = 0; ks < 4; ks++) {
#pragma unroll
            for (int nt2 = 0; nt2 < 4; nt2++) {
                uint32_t bb[4];
                LDSM_X4(bb, sB + nt2*(16*144) + ks*32);
                MMA16816(sacc[2*nt2  ], qf[ks][0], qf[ks][1], qf[ks][2], qf[ks][3], bb[0], bb[1]);
                MMA16816(sacc[2*nt2+1], qf[ks][0], qf[ks][1], qf[ks][2], qf[ks][3], bb[2], bb[3]);
            }
        }

        // ---- online softmax ----
        float mt0 = -1e30f, mt1 = -1e30f;
#pragma unroll
        for (int nt = 0; nt < 8; nt++) {
            mt0 = fmaxf(mt0, fmaxf(sacc[nt][0], sacc[nt][1]));
            mt1 = fmaxf(mt1, fmaxf(sacc[nt][2], sacc[nt][3]));
        }
        mt0 = fmaxf(mt0, __shfl_xor_sync(0xffffffffu, mt0, 1));
        mt0 = fmaxf(mt0, __shfl_xor_sync(0xffffffffu, mt0, 2));
        mt1 = fmaxf(mt1, __shfl_xor_sync(0xffffffffu, mt1, 1));
        mt1 = fmaxf(mt1, __shfl_xor_sync(0xffffffffu, mt1, 2));
        float Mn0 = fmaxf(M0, mt0), Mn1 = fmaxf(M1, mt1);
        float al0 = exp2f((M0 - Mn0)*SC), al1 = exp2f((M1 - Mn1)*SC);
        M0 = Mn0; M1 = Mn1;
        float c0 = M0*SC, c1 = M1*SC;
        float rs0 = 0.f, rs1 = 0.f;
#pragma unroll
        for (int nt = 0; nt < 8; nt++) {
            sacc[nt][0] = exp2f(sacc[nt][0]*SC - c0);
            sacc[nt][1] = exp2f(sacc[nt][1]*SC - c0);
            sacc[nt][2] = exp2f(sacc[nt][2]*SC - c1);
            sacc[nt][3] = exp2f(sacc[nt][3]*SC - c1);
            rs0 += sacc[nt][0] + sacc[nt][1];
            rs1 += sacc[nt][2] + sacc[nt][3];
        }
        L0 = L0*al0 + rs0;
        L1 = L1*al1 + rs1;
#pragma unroll
        for (int nt = 0; nt < 8; nt++) {
            oacc[nt][0] *= al0; oacc[nt][1] *= al0;
            oacc[nt][2] *= al1; oacc[nt][3] *= al1;
        }

        // ---- O += P@V ----
#pragma unroll
        for (int ks = 0; ks < 4; ks++) {
            uint32_t a0 = f2h2(sacc[2*ks  ][0], sacc[2*ks  ][1]);
            uint32_t a1 = f2h2(sacc[2*ks  ][2], sacc[2*ks  ][3]);
            uint32_t a2 = f2h2(sacc[2*ks+1][0], sacc[2*ks+1][1]);
            uint32_t a3 = f2h2(sacc[2*ks+1][2], sacc[2*ks+1][3]);
#pragma unroll
            for (int nt2 = 0; nt2 < 4; nt2++) {
                uint32_t bb[4];
                LDSM_X4T(bb, vB + ks*(16*144) + nt2*32);
                MMA16816(oacc[2*nt2  ], a0, a1, a2, a3, bb[0], bb[1]);
                MMA16816(oacc[2*nt2+1], a0, a1, a2, a3, bb[2], bb[3]);
            }
        }
        __syncthreads();
    }
#undef FLOAD

    L0 += __shfl_xor_sync(0xffffffffu, L0, 1);
    L0 += __shfl_xor_sync(0xffffffffu, L0, 2);
    L1 += __shfl_xor_sync(0xffffffffu, L1, 1);
    L1 += __shfl_xor_sync(0xffffffffu, L1, 2);
    float inv0 = 1.f / L0, inv1 = 1.f / L1;
    __half* or0 = oh + (size_t)qrow0*DIMM;
    __half* or1 = or0 + 8*DIMM;
#pragma unroll
    for (int nt = 0; nt < 8; nt++) {
        int col = nt*8 + (lane & 3)*2;
        *(uint32_t*)(or0 + col) = f2h2(oacc[nt][0]*inv0, oacc[nt][1]*inv0);
        *(uint32_t*)(or1 + col) = f2h2(oacc[nt][2]*inv1, oacc[nt][3]*inv1);
    }
}

// ================= elementwise kernels =================
__global__ void cvt_half(const float* __restrict__ s, __half* __restrict__ d, int n) {
    int i = (blockIdx.x*blockDim.x + threadIdx.x)*8;
    if (i >= n) return;
    float4 f0 = *(const float4*)(s + i);
    float4 f1 = *(const float4*)(s + i + 4);
    uint4 o;
    o.x = f2h2(f0.x, f0.y); o.y = f2h2(f0.z, f0.w);
    o.z = f2h2(f1.x, f1.y); o.w = f2h2(f1.z, f1.w);
    *(uint4*)(d + i) = o;
}

__global__ void rmsnorm_kernel(const float* __restrict__ x, const float* __restrict__ w,
                               __half* __restrict__ outh, float* __restrict__ outf) {
    int row = blockIdx.x;
    const float* xr = x + (size_t)row*DIMM;
    float v[4]; float s = 0.f;
#pragma unroll
    for (int i = 0; i < 4; i++) { v[i] = xr[threadIdx.x + i*256]; s += v[i]*v[i]; }
    __shared__ float red[8];
#pragma unroll
    for (int o = 16; o > 0; o >>= 1) s += __shfl_xor_sync(0xffffffffu, s, o);
    if ((threadIdx.x & 31) == 0) red[threadIdx.x >> 5] = s;
    __syncthreads();
    if (threadIdx.x < 8) {
        float t = red[threadIdx.x];
#pragma unroll
        for (int o = 4; o > 0; o >>= 1) t += __shfl_xor_sync(0xffu, t, o);
        if (threadIdx.x == 0) red[0] = t;
    }
    __syncthreads();
    float r = rsqrtf(red[0] / (float)DIMM + EPSV);
#pragma unroll
    for (int i = 0; i < 4; i++) {
        int c = threadIdx.x + i*256;
        float val = v[i]*r*w[c];
        outh[(size_t)row*DIMM + c] = __float2half(val);
        if (outf) outf[(size_t)row*DIMM + c] = val;
    }
}

__global__ void rope_half(__half* __restrict__ qkv, const float* __restrict__ freqs) {
    int idx = blockIdx.x*blockDim.x + threadIdx.x;
    if (idx >= NTOK*NHEAD*(HDIM/2)) return;
    int p = idx % (HDIM/2);
    int h = (idx / (HDIM/2)) % NHEAD;
    int n = idx / (NHEAD*(HDIM/2));
    int s = n % SLEN;
    float c  = freqs[(s*(HDIM/2) + p)*2 + 0];
    float sn = freqs[(s*(HDIM/2) + p)*2 + 1];
    size_t base = (size_t)n*DIMM + h*HDIM + 2*p;
    __half2* q2 = (__half2*)(qkv + base);
    __half2* k2 = (__half2*)(qkv + (size_t)NTOK*DIMM + base);
    float2 qv = __half22float2(*q2);
    *q2 = __floats2half2_rn(qv.x*c - qv.y*sn, qv.x*sn + qv.y*c);
    float2 kv = __half22float2(*k2);
    *k2 = __floats2half2_rn(kv.x*c - kv.y*sn, kv.x*sn + kv.y*c);
}

__global__ void zero_counts_kernel(int* c) { if (threadIdx.x < NEXP) c[threadIdx.x] = 0; }

__global__ void gate_topk(const float* __restrict__ hn, const float* __restrict__ gw,
                          int* __restrict__ tidx, float* __restrict__ tw,
                          int* __restrict__ counts) {
    int n = blockIdx.x;
    int w = threadIdx.x >> 5, lane = threadIdx.x & 31;
    const float* x = hn + (size_t)n*DIMM;
    const float* g = gw + (size_t)w*DIMM;
    float s = 0.f;
    for (int i = lane; i < DIMM; i += 32) s += x[i]*g[i];
#pragma unroll
    for (int o = 16; o > 0; o >>= 1) s += __shfl_xor_sync(0xffffffffu, s, o);
    __shared__ float sc[NEXP];
    if (lane == 0) sc[w] = s;
    __syncthreads();
    if (threadIdx.x == 0) {
        float mx = sc[0];
        for (int e = 1; e < NEXP; e++) mx = fmaxf(mx, sc[e]);
        float p[NEXP]; float sum = 0.f;
        for (int e = 0; e < NEXP; e++) { p[e] = expf(sc[e]-mx); sum += p[e]; }
        for (int e = 0; e < NEXP; e++) p[e] /= sum;
        int i0 = 0;
        for (int e = 1; e < NEXP; e++) if (p[e] > p[i0]) i0 = e;
        int i1 = -1;
        for (int e = 0; e < NEXP; e++)
            if (e != i0 && (i1 < 0 || p[e] > p[i1])) i1 = e;
        tidx[n*2]   = i0; tidx[n*2+1] = i1;
        tw[n*2]     = p[i0]; tw[n*2+1] = p[i1];
        atomicAdd(&counts[i0], 1);
        atomicAdd(&counts[i1], 1);
    }
}

__global__ void prefix_kernel(const int* __restrict__ counts, int* __restrict__ offs,
                              int* __restrict__ fill) {
    if (threadIdx.x == 0) {
        int a = 0;
        for (int e = 0; e < NEXP; e++) { offs[e] = a; a += counts[e]; }
        offs[NEXP] = a;
    }
    if (threadIdx.x < NEXP) fill[threadIdx.x] = 0;
}

__global__ void scatter_kernel(const int* __restrict__ tidx,
                               const int* __restrict__ offs, int* __restrict__ fill,
                               int* __restrict__ tok, int* __restrict__ smap) {
    int n = blockIdx.x*blockDim.x + threadIdx.x;
    if (n >= NTOK) return;
#pragma unroll
    for (int j = 0; j < TOPK; j++) {
        int e = tidx[n*2+j];
        int slot = offs[e] + atomicAdd(&fill[e], 1);
        tok[slot] = n;
        smap[n*2+j] = slot;
    }
}

__global__ void silu_mul_h(const float* __restrict__ a, const float* __restrict__ b,
                           __half* __restrict__ o, size_t n) {
    size_t i = ((size_t)blockIdx.x*blockDim.x + threadIdx.x)*4;
    if (i >= n) return;
    float4 av = *(const float4*)(a + i);
    float4 bv = *(const float4*)(b + i);
    float r0 = av.x / (1.f + __expf(-av.x)) * bv.x;
    float r1 = av.y / (1.f + __expf(-av.y)) * bv.y;
    float r2 = av.z / (1.f + __expf(-av.z)) * bv.z;
    float r3 = av.w / (1.f + __expf(-av.w)) * bv.w;
    uint2 ov; ov.x = f2h2(r0, r1); ov.y = f2h2(r2, r3);
    *(uint2*)(o + i) = ov;
}

__global__ void combine_kernel(float* __restrict__ out, const float* __restrict__ eo,
                               const int* __restrict__ smap, const float* __restrict__ tw) {
    size_t idx = (size_t)blockIdx.x*blockDim.x + threadIdx.x;
    if (idx >= (size_t)NTOK*DIMM) return;
    size_t n = idx / DIMM, d = idx % DIMM;
    int s0 = smap[n*2], s1 = smap[n*2+1];
    out[idx] += tw[n*2]*eo[(size_t)s0*DIMM + d] + tw[n*2+1]*eo[(size_t)s1*DIMM + d];
}

// ================= launcher =================
extern "C" void kernel_launch(void* const* d_in, const int* in_sizes, int n_in,
                              void* d_out, int out_size) {
    (void)in_sizes; (void)n_in; (void)out_size;
    const float* x     = (const float*)d_in[0];
    const float* freqs = (const float*)d_in[1];
    const float* att_w = (const float*)d_in[2];
    const float* wq    = (const float*)d_in[3];
    const float* wk    = (const float*)d_in[4];
    const float* wv    = (const float*)d_in[5];
    const float* wo    = (const float*)d_in[6];
    const float* ffn_w = (const float*)d_in[7];
    const float* gw    = (const float*)d_in[8];
    const float* ew1   = (const float*)d_in[9];
    const float* ew2   = (const float*)d_in[10];
    const float* ew3   = (const float*)d_in[11];
    const float* sw1   = (const float*)d_in[12];
    const float* sw2   = (const float*)d_in[13];
    const float* sw3   = (const float*)d_in[14];
    float* out = (float*)d_out;

    __half *wqkvh,*woh,*e13h,*e2h,*s13wh,*s2wh,*xnh,*qkvh,*atth,*hnh,*g13h,*s13h;
    float *h,*hn32,*h13f,*s13f,*eo,*tw;
    int *tidx,*counts,*offs,*fill,*tok,*smap;
    cudaGetSymbolAddress((void**)&wqkvh, g_wqkvh);
    cudaGetSymbolAddress((void**)&woh,   g_woh);
    cudaGetSymbolAddress((void**)&e13h,  g_e13h);
    cudaGetSymbolAddress((void**)&e2h,   g_e2h);
    cudaGetSymbolAddress((void**)&s13wh, g_s13wh);
    cudaGetSymbolAddress((void**)&s2wh,  g_s2wh);
    cudaGetSymbolAddress((void**)&xnh,   g_xnh);
    cudaGetSymbolAddress((void**)&qkvh,  g_qkvh);
    cudaGetSymbolAddress((void**)&atth,  g_atth);
    cudaGetSymbolAddress((void**)&hnh,   g_hnh);
    cudaGetSymbolAddress((void**)&g13h,  g_g13h);
    cudaGetSymbolAddress((void**)&s13h,  g_s13h);
    cudaGetSymbolAddress((void**)&h,     g_h);
    cudaGetSymbolAddress((void**)&hn32,  g_hn32);
    cudaGetSymbolAddress((void**)&h13f,  g_h13f);
    cudaGetSymbolAddress((void**)&s13f,  g_s13f);
    cudaGetSymbolAddress((void**)&eo,    g_eo);
    cudaGetSymbolAddress((void**)&tidx,  g_topk_idx);
    cudaGetSymbolAddress((void**)&tw,    g_topk_w);
    cudaGetSymbolAddress((void**)&counts, g_counts);
    cudaGetSymbolAddress((void**)&offs,   g_offsets);
    cudaGetSymbolAddress((void**)&fill,   g_fill);
    cudaGetSymbolAddress((void**)&tok,    g_tok_idx);
    cudaGetSymbolAddress((void**)&smap,   g_slot_map);

    cudaFuncSetAttribute(gemm2<false,false,false,true >, cudaFuncAttributeMaxDynamicSharedMemorySize, SMEMB);
    cudaFuncSetAttribute(gemm2<false,false,true, false>, cudaFuncAttributeMaxDynamicSharedMemorySize, SMEMB);
    cudaFuncSetAttribute(gemm2<true, true, false,false>, cudaFuncAttributeMaxDynamicSharedMemorySize, SMEMB);
    cudaFuncSetAttribute(gemm2<false,true, false,false>, cudaFuncAttributeMaxDynamicSharedMemorySize, SMEMB);
    cudaFuncSetAttribute(gemm2<false,false,false,false>, cudaFuncAttributeMaxDynamicSharedMemorySize, SMEMB);

    const int T = 256;
    const int WQN = DIMM*DIMM;
    const int EWN = DIMM*HIDD;

    // ---- weight conversions (8 elems/thread) ----
    cvt_half<<<WQN/2048, T>>>(wq, wqkvh,          WQN);
    cvt_half<<<WQN/2048, T>>>(wk, wqkvh + WQN,    WQN);
    cvt_half<<<WQN/2048, T>>>(wv, wqkvh + 2*WQN,  WQN);
    cvt_half<<<WQN/2048, T>>>(wo, woh,            WQN);
    cvt_half<<<NEXP*EWN/2048, T>>>(ew1, e13h,                     NEXP*EWN);
    cvt_half<<<NEXP*EWN/2048, T>>>(ew3, e13h + (size_t)NEXP*EWN,  NEXP*EWN);
    cvt_half<<<NEXP*EWN/2048, T>>>(ew2, e2h,                      NEXP*EWN);
    cvt_half<<<EWN/2048, T>>>(sw1, s13wh,        EWN);
    cvt_half<<<EWN/2048, T>>>(sw3, s13wh + EWN,  EWN);
    cvt_half<<<EWN/2048, T>>>(sw2, s2wh,         EWN);

    // 1) attention pre-norm
    rmsnorm_kernel<<<NTOK, T>>>(x, att_w, xnh, nullptr);

    // 2) QKV
    gemm2<false,false,false,true><<<dim3(32,8,3), T, SMEMB>>>(
        xnh, wqkvh, qkvh, nullptr, NTOK, 1.f,
        0, (long long)DIMM*DIMM, (long long)NTOK*DIMM, 0, nullptr, nullptr);

    // 3) RoPE
    rope_half<<<(NTOK*NHEAD*(HDIM/2))/T, T>>>(qkvh, freqs);

    // 4) flash attention
    flash_attn<<<dim3(SLEN/128, BSZ*NHEAD), T>>>(qkvh, atth);

    // 5) h = x + att @ wo
    gemm2<false,false,true,false><<<dim3(32,8,1), T, SMEMB>>>(
        atth, woh, h, x, NTOK, 1.f, 0, 0, 0, 0, nullptr, nullptr);

    // 6) ffn pre-norm
    rmsnorm_kernel<<<NTOK, T>>>(h, ffn_w, hnh, hn32);

    // 7) gate + routing
    zero_counts_kernel<<<1, 32>>>(counts);
    gate_topk<<<NTOK, T>>>(hn32, gw, tidx, tw, counts);
    prefix_kernel<<<1, 32>>>(counts, offs, fill);
    scatter_kernel<<<(NTOK + T - 1)/T, T>>>(tidx, offs, fill, tok, smap);

    // 8) experts
    gemm2<true,true,false,false><<<dim3(32,8,16), T, SMEMB>>>(
        hnh, e13h, h13f, nullptr, 0, 1.f,
        0, (long long)EWN, 0, (long long)NSLOT*HIDD, tok, offs);
    silu_mul_h<<<(unsigned)(((size_t)NSLOT*HIDD)/1024), T>>>(
        h13f, h13f + (size_t)NSLOT*HIDD, g13h, (size_t)NSLOT*HIDD);
    gemm2<false,true,false,false><<<dim3(32,8,NEXP), T, SMEMB>>>(
        g13h, e2h, eo, nullptr, 0, 1.f,
        0, (long long)EWN, 0, 0, nullptr, offs);

    // 9) shared expert
    gemm2<false,false,false,false><<<dim3(32,8,2), T, SMEMB>>>(
        hnh, s13wh, s13f, nullptr, NTOK, 1.f,
        0, (long long)EWN, (long long)NTOK*HIDD, 0, nullptr, nullptr);
    silu_mul_h<<<(unsigned)(((size_t)NTOK*HIDD)/1024), T>>>(
        s13f, s13f + (size_t)NTOK*HIDD, s13h, (size_t)NTOK*HIDD);
    gemm2<false,false,true,false><<<dim3(32,8,1), T, SMEMB>>>(
        s13h, s2wh, out, h, NTOK, 1.f, 0, 0, 0, 0, nullptr, nullptr);

    // 10) routed combine
    combine_kernel<<<(unsigned)(((size_t)NTOK*DIMM)/T), T>>>(out, eo, smap, tw);
}

// round 9
// speedup vs baseline: 7.3844x; 1.1489x over previous
#include <cuda_runtime.h>
#include <cuda_fp16.h>
#include <math.h>
#include <stdint.h>

#define DIMM 1024
#define NHEAD 16
#define HDIM 64
#define SLEN 2048
#define BSZ 2
#define NTOK (BSZ*SLEN)          // 4096
#define NEXP 8
#define TOPK 2
#define HIDD 1024
#define NSLOT (NTOK*TOPK)        // 8192
#define EPSV 1e-6f

// GEMM pipeline constants
#define AST 40
#define BST 136
#define A_STAGE (128*AST)
#define B_STAGE (32*BST)
#define STAGES 3
#define SMEMB (STAGES*(A_STAGE+B_STAGE)*2)

// ================= scratch =================
__device__ __half g_wqkvh[(size_t)3*DIMM*DIMM];
__device__ __half g_woh[(size_t)DIMM*DIMM];
__device__ __half g_e13h[(size_t)2*NEXP*DIMM*HIDD];
__device__ __half g_e2h[(size_t)NEXP*HIDD*DIMM];
__device__ __half g_s13wh[(size_t)2*DIMM*HIDD];
__device__ __half g_s2wh[(size_t)HIDD*DIMM];
__device__ __half g_xnh[(size_t)NTOK*DIMM];
__device__ __half g_qkvh[(size_t)3*NTOK*DIMM];
__device__ __half g_atth[(size_t)NTOK*DIMM];
__device__ __half g_hnh[(size_t)NTOK*DIMM];
__device__ __half g_h13h[(size_t)2*NSLOT*HIDD];
__device__ __half g_g13h[(size_t)NSLOT*HIDD];
__device__ __half g_s13hh[(size_t)2*NTOK*HIDD];
__device__ __half g_s13h[(size_t)NTOK*HIDD];
__device__ __half g_eoh[(size_t)NSLOT*DIMM];
__device__ float g_h[(size_t)NTOK*DIMM];
__device__ float g_hn32[(size_t)NTOK*DIMM];
__device__ int   g_topk_idx[NTOK*TOPK];
__device__ float g_topk_w [NTOK*TOPK];
__device__ int   g_counts[NEXP];
__device__ int   g_offsets[NEXP+1];
__device__ int   g_fill[NEXP];
__device__ int   g_tok_idx[NSLOT];
__device__ int   g_slot_map[NTOK*TOPK];

__device__ __forceinline__ uint32_t f2h2(float lo, float hi) {
    __half2 h = __floats2half2_rn(lo, hi);
    return *reinterpret_cast<uint32_t*>(&h);
}
__device__ __forceinline__ uint32_t smem_u32(const void* p) {
    uint32_t a;
    asm("{ .reg .u64 t; cvta.to.shared.u64 t, %1; cvt.u32.u64 %0, t; }" : "=r"(a) : "l"(p));
    return a;
}

#define MMA16816(acc, a0,a1,a2,a3, b0,b1) \
    asm volatile( \
        "mma.sync.aligned.m16n8k16.row.col.f32.f16.f16.f32 " \
        "{%0,%1,%2,%3}, {%4,%5,%6,%7}, {%8,%9}, {%0,%1,%2,%3};" \
        : "+f"((acc)[0]), "+f"((acc)[1]), "+f"((acc)[2]), "+f"((acc)[3]) \
        : "r"(a0), "r"(a1), "r"(a2), "r"(a3), "r"(b0), "r"(b1))

#define LDSM_X4(r, addr) \
    asm volatile("ldmatrix.sync.aligned.m8n8.x4.shared.b16 {%0,%1,%2,%3}, [%4];" \
        : "=r"((r)[0]),"=r"((r)[1]),"=r"((r)[2]),"=r"((r)[3]) : "r"(addr))
#define LDSM_X4T(r, addr) \
    asm volatile("ldmatrix.sync.aligned.m8n8.x4.trans.shared.b16 {%0,%1,%2,%3}, [%4];" \
        : "=r"((r)[0]),"=r"((r)[1]),"=r"((r)[2]),"=r"((r)[3]) : "r"(addr))

#define CP16(dst, src, sz) \
    asm volatile("cp.async.cg.shared.global [%0], [%1], 16, %2;" \
        :: "r"(dst), "l"(src), "r"(sz) : "memory")
#define CPCOMMIT asm volatile("cp.async.commit_group;" ::: "memory")
#define CPWAIT1  asm volatile("cp.async.wait_group 1;" ::: "memory")
#define CPWAIT0  asm volatile("cp.async.wait_group 0;" ::: "memory")

// ================= GEMM: half A [M,1024], half B [1024,1024] =================
template<bool GATHER, bool GROUPED, bool RESID, bool HALFOUT>
__global__ void __launch_bounds__(256) gemm2(
    const __half* __restrict__ A, const __half* __restrict__ B,
    void* __restrict__ Cv, const float* __restrict__ Rr,
    int M, float scale,
    long long sAo, long long sBo, long long sCo, long long sCg,
    const int* __restrict__ gidx, const int* __restrict__ offsets)
{
    extern __shared__ __half smx[];
    const int LDA = 1024;
    int tid = threadIdx.x, lane = tid & 31, wid = tid >> 5;
    int warpM = wid & 3, warpN = wid >> 2;
    int z = blockIdx.z;

    float* Cf = (float*)Cv;
    __half* Ch = (__half*)Cv;

    int Mz = M, seg0 = 0;
    if (GROUPED) {
        int e = z & 7;
        seg0 = offsets[e]; Mz = offsets[e+1] - seg0;
        B  += (size_t)z * sBo;
        if (HALFOUT) Ch += (size_t)(z >> 3) * sCg;
        else         Cf += (size_t)(z >> 3) * sCg;
    } else {
        A += (size_t)z * sAo;
        B += (size_t)z * sBo;
        if (HALFOUT) Ch += (size_t)z * sCo; else Cf += (size_t)z * sCo;
        if (RESID) Rr += (size_t)z * sCo;
    }
    int m0 = blockIdx.x * 128;
    if (GROUPED && m0 >= Mz) return;
    int n0 = blockIdx.y * 128;

    uint32_t AsB = smem_u32(smx);
    uint32_t BsB = AsB + STAGES*A_STAGE*2;

    int arow = tid >> 1, acH = (tid & 1)*16;
    bool aOK = (!GROUPED) || ((m0 + arow) < Mz);
    long long grow = 0;
    if (aOK) grow = GATHER ? (long long)gidx[seg0 + m0 + arow]
                  : (GROUPED ? (long long)(seg0 + m0 + arow) : (long long)(m0 + arow));
    const __half* aP = A + (size_t)grow*LDA + acH;
    uint32_t aD = AsB + (arow*AST + acH)*2;
    int aSz = aOK ? 16 : 0;

    int brow = tid >> 3, bH = (tid & 7)*16;
    const __half* bP = B + (size_t)brow*LDA + n0 + bH;
    uint32_t bD = BsB + (brow*BST + bH)*2;

#define LOADST(s_, c_) do { \
    int kt_ = (c_)*32; \
    CP16(aD + (s_)*(A_STAGE*2),      aP + kt_,     aSz); \
    CP16(aD + (s_)*(A_STAGE*2) + 16, aP + kt_ + 8, aSz); \
    CP16(bD + (s_)*(B_STAGE*2),      bP + (size_t)kt_*LDA,     16); \
    CP16(bD + (s_)*(B_STAGE*2) + 16, bP + (size_t)kt_*LDA + 8, 16); \
} while (0)

    float acc[2][8][4];
#pragma unroll
    for (int mt = 0; mt < 2; mt++)
#pragma unroll
        for (int nt = 0; nt < 8; nt++)
#pragma unroll
            for (int j = 0; j < 4; j++) acc[mt][nt][j] = 0.f;

    uint32_t aAddr = AsB + ((warpM*32 + (lane & 15))*AST + ((lane >> 4) & 1)*8)*2;
    uint32_t bAddr = BsB + ((lane & 15)*BST + warpN*64 + ((lane >> 4) & 1)*8)*2;

    LOADST(0, 0); CPCOMMIT;
    LOADST(1, 1); CPCOMMIT;

    for (int c = 0; c < 32; c++) {
        CPWAIT1;
        __syncthreads();
        int st = c % 3;
        uint32_t aS = aAddr + st*(A_STAGE*2);
        uint32_t bS = bAddr + st*(B_STAGE*2);
#pragma unroll
        for (int ks = 0; ks < 2; ks++) {
            uint32_t af0[4], af1[4];
            LDSM_X4(af0, aS + ks*32);
            LDSM_X4(af1, aS + ks*32 + 16*AST*2);
            uint32_t bf[4][4];
#pragma unroll
            for (int nt2 = 0; nt2 < 4; nt2++)
                LDSM_X4T(bf[nt2], bS + ks*(16*BST*2) + nt2*32);
#pragma unroll
            for (int nt2 = 0; nt2 < 4; nt2++) {
                MMA16816(acc[0][2*nt2  ], af0[0],af0[1],af0[2],af0[3], bf[nt2][0],bf[nt2][1]);
                MMA16816(acc[0][2*nt2+1], af0[0],af0[1],af0[2],af0[3], bf[nt2][2],bf[nt2][3]);
                MMA16816(acc[1][2*nt2  ], af1[0],af1[1],af1[2],af1[3], bf[nt2][0],bf[nt2][1]);
                MMA16816(acc[1][2*nt2+1], af1[0],af1[1],af1[2],af1[3], bf[nt2][2],bf[nt2][3]);
            }
        }
        if (c + 2 < 32) { int c2 = c + 2; LOADST(c2 % 3, c2); }
        CPCOMMIT;
    }

#pragma unroll
    for (int mt = 0; mt < 2; mt++) {
        int rb = m0 + warpM*32 + mt*16 + (lane >> 2);
#pragma unroll
        for (int hh = 0; hh < 2; hh++) {
            int r = rb + hh*8;
            if (GROUPED && r >= Mz) continue;
            size_t crow = (size_t)((GROUPED ? seg0 : 0) + r) * 1024;
#pragma unroll
            for (int nt = 0; nt < 8; nt++) {
                int col = n0 + warpN*64 + nt*8 + (lane & 3)*2;
                float vx = acc[mt][nt][hh*2+0]*scale;
                float vy = acc[mt][nt][hh*2+1]*scale;
                if (HALFOUT) {
                    *(uint32_t*)(Ch + crow + col) = f2h2(vx, vy);
                } else {
                    if (RESID) {
                        float2 rv = *(const float2*)(Rr + crow + col);
                        vx += rv.x; vy += rv.y;
                    }
                    *(float2*)(Cf + crow + col) = make_float2(vx, vy);
                }
            }
        }
    }
#undef LOADST
}

// ================= flash attention: cp.async double-buffer + ldmatrix + f16x2 exp =================
#define FTILEB (64*72*2)
__global__ void __launch_bounds__(256) flash_attn(
    const __half* __restrict__ qkv, __half* __restrict__ att)
{
    __shared__ __align__(16) __half Ksm[2][64][72];
    __shared__ __align__(16) __half Vsm[2][64][72];
    int tid = threadIdx.x, wid = tid >> 5, lane = tid & 31;
    int bh = blockIdx.y;
    int b = bh >> 4, h = bh & 15;
    size_t plane = (size_t)NTOK*DIMM;
    const __half* qh = qkv +           (size_t)b*SLEN*DIMM + h*HDIM;
    const __half* kh = qkv + plane   + (size_t)b*SLEN*DIMM + h*HDIM;
    const __half* vh = qkv + 2*plane + (size_t)b*SLEN*DIMM + h*HDIM;
    __half* oh = att + (size_t)b*SLEN*DIMM + h*HDIM;

    int qrow0 = blockIdx.x*128 + wid*16 + (lane >> 2);
    const float SC = 0.125f * 1.44269504f;

    uint32_t qf[4][4];
    {
        const __half* qr0 = qh + (size_t)qrow0*DIMM;
        const __half* qr1 = qr0 + 8*DIMM;
        int c0 = (lane & 3)*2;
#pragma unroll
        for (int ks = 0; ks < 4; ks++) {
            qf[ks][0] = *(const uint32_t*)(qr0 + ks*16 + c0);
            qf[ks][1] = *(const uint32_t*)(qr1 + ks*16 + c0);
            qf[ks][2] = *(const uint32_t*)(qr0 + ks*16 + 8 + c0);
            qf[ks][3] = *(const uint32_t*)(qr1 + ks*16 + 8 + c0);
        }
    }

    float oacc[8][4];
#pragma unroll
    for (int nt = 0; nt < 8; nt++)
#pragma unroll
        for (int j = 0; j < 4; j++) oacc[nt][j] = 0.f;
    float M0 = -1e30f, M1 = -1e30f, L0 = 0.f, L1 = 0.f;

    int lrow = tid >> 2, lc = (tid & 3)*2;
    const __half* kSrc = kh + (size_t)lrow*DIMM + lc*8;
    const __half* vSrc = vh + (size_t)lrow*DIMM + lc*8;
    uint32_t kDst = smem_u32(&Ksm[0][lrow][lc*8]);
    uint32_t vDst = smem_u32(&Vsm[0][lrow][lc*8]);

#define FLOAD(buf_, t_) do { \
    size_t off_ = (size_t)(t_)*64*DIMM; \
    CP16(kDst + (buf_)*FTILEB,      kSrc + off_,     16); \
    CP16(kDst + (buf_)*FTILEB + 16, kSrc + off_ + 8, 16); \
    CP16(vDst + (buf_)*FTILEB,      vSrc + off_,     16); \
    CP16(vDst + (buf_)*FTILEB + 16, vSrc + off_ + 8, 16); \
} while (0)

    uint32_t ksBase = smem_u32(&Ksm[0][0][0]);
    uint32_t vsBase = smem_u32(&Vsm[0][0][0]);
    uint32_t sA = ksBase + (((lane>>4)&1)*8 + (lane&7))*144 + ((lane>>3)&1)*16;
    uint32_t vA = vsBase + (lane&15)*144 + (lane>>4)*16;

    FLOAD(0, 0); CPCOMMIT;

    const int NTILES = SLEN/64;
    for (int t = 0; t < NTILES; t++) {
        int buf = t & 1;
        if (t + 1 < NTILES) { FLOAD(buf ^ 1, t + 1); CPCOMMIT; CPWAIT1; }
        else                { CPWAIT0; }
        __syncthreads();

        uint32_t sB = sA + buf*FTILEB;
        uint32_t vB = vA + buf*FTILEB;

        float sacc[8][4];
#pragma unroll
        for (int nt = 0; nt < 8; nt++)
#pragma unroll
            for (int j = 0; j < 4; j++) sacc[nt][j] = 0.f;
#pragma unroll
        for (int ks = 0; ks < 4; ks++) {
#pragma unroll
            for (int nt2 = 0; nt2 < 4; nt2++) {
                uint32_t bb[4];
                LDSM_X4(bb, sB + nt2*(16*144) + ks*32);
                MMA16816(sacc[2*nt2  ], qf[ks][0], qf[ks][1], qf[ks][2], qf[ks][3], bb[0], bb[1]);
                MMA16816(sacc[2*nt2+1], qf[ks][0], qf[ks][1], qf[ks][2], qf[ks][3], bb[2], bb[3]);
            }
        }

        // ---- online softmax (half2 exp path) ----
        float mt0 = -1e30f, mt1 = -1e30f;
#pragma unroll
        for (int nt = 0; nt < 8; nt++) {
            mt0 = fmaxf(mt0, fmaxf(sacc[nt][0], sacc[nt][1]));
            mt1 = fmaxf(mt1, fmaxf(sacc[nt][2], sacc[nt][3]));
        }
        mt0 = fmaxf(mt0, __shfl_xor_sync(0xffffffffu, mt0, 1));
        mt0 = fmaxf(mt0, __shfl_xor_sync(0xffffffffu, mt0, 2));
        mt1 = fmaxf(mt1, __shfl_xor_sync(0xffffffffu, mt1, 1));
        mt1 = fmaxf(mt1, __shfl_xor_sync(0xffffffffu, mt1, 2));
        float Mn0 = fmaxf(M0, mt0), Mn1 = fmaxf(M1, mt1);
        float al0 = exp2f((M0 - Mn0)*SC), al1 = exp2f((M1 - Mn1)*SC);
        M0 = Mn0; M1 = Mn1;
        float c0 = M0*SC, c1 = M1*SC;
        uint32_t pr[8][2];
        float rs0 = 0.f, rs1 = 0.f;
#pragma unroll
        for (int nt = 0; nt < 8; nt++) {
            uint32_t h0 = f2h2(sacc[nt][0]*SC - c0, sacc[nt][1]*SC - c0);
            uint32_t h1 = f2h2(sacc[nt][2]*SC - c1, sacc[nt][3]*SC - c1);
            asm("ex2.approx.f16x2 %0, %1;" : "=r"(pr[nt][0]) : "r"(h0));
            asm("ex2.approx.f16x2 %0, %1;" : "=r"(pr[nt][1]) : "r"(h1));
            float2 p0 = __half22float2(*(__half2*)&pr[nt][0]);
            float2 p1 = __half22float2(*(__half2*)&pr[nt][1]);
            rs0 += p0.x + p0.y;
            rs1 += p1.x + p1.y;
        }
        L0 = L0*al0 + rs0;
        L1 = L1*al1 + rs1;
#pragma unroll
        for (int nt = 0; nt < 8; nt++) {
            oacc[nt][0] *= al0; oacc[nt][1] *= al0;
            oacc[nt][2] *= al1; oacc[nt][3] *= al1;
        }

        // ---- O += P@V (P fragments straight from ex2 output) ----
#pragma unroll
        for (int ks = 0; ks < 4; ks++) {
            uint32_t a0 = pr[2*ks  ][0], a1 = pr[2*ks  ][1];
            uint32_t a2 = pr[2*ks+1][0], a3 = pr[2*ks+1][1];
#pragma unroll
            for (int nt2 = 0; nt2 < 4; nt2++) {
                uint32_t bb[4];
                LDSM_X4T(bb, vB + ks*(16*144) + nt2*32);
                MMA16816(oacc[2*nt2  ], a0, a1, a2, a3, bb[0], bb[1]);
                MMA16816(oacc[2*nt2+1], a0, a1, a2, a3, bb[2], bb[3]);
            }
        }
        __syncthreads();
    }
#undef FLOAD

    L0 += __shfl_xor_sync(0xffffffffu, L0, 1);
    L0 += __shfl_xor_sync(0xffffffffu, L0, 2);
    L1 += __shfl_xor_sync(0xffffffffu, L1, 1);
    L1 += __shfl_xor_sync(0xffffffffu, L1, 2);
    float inv0 = 1.f / L0, inv1 = 1.f / L1;
    __half* or0 = oh + (size_t)qrow0*DIMM;
    __half* or1 = or0 + 8*DIMM;
#pragma unroll
    for (int nt = 0; nt < 8; nt++) {
        int col = nt*8 + (lane & 3)*2;
        *(uint32_t*)(or0 + col) = f2h2(oacc[nt][0]*inv0, oacc[nt][1]*inv0);
        *(uint32_t*)(or1 + col) = f2h2(oacc[nt][2]*inv1, oacc[nt][3]*inv1);
    }
}

// ================= fused weight conversion =================
struct CvtArgs {
    const float* s[10];
    __half* d[10];
    int sb[10];       // start block of each region
};
__global__ void cvt_all(CvtArgs a) {
    int b = blockIdx.x;
    int r = 0;
#pragma unroll
    for (int i = 1; i < 10; i++) r += (b >= a.sb[i]);
    const float* src = a.s[r];
    __half* dst = a.d[r];
    int off = (b - a.sb[r])*2048 + threadIdx.x*8;
    float4 f0 = *(const float4*)(src + off);
    float4 f1 = *(const float4*)(src + off + 4);
    uint4 o;
    o.x = f2h2(f0.x, f0.y); o.y = f2h2(f0.z, f0.w);
    o.z = f2h2(f1.x, f1.y); o.w = f2h2(f1.z, f1.w);
    *(uint4*)(dst + off) = o;
}

// ================= elementwise kernels =================
__global__ void rmsnorm_kernel(const float* __restrict__ x, const float* __restrict__ w,
                               __half* __restrict__ outh, float* __restrict__ outf) {
    int row = blockIdx.x;
    const float* xr = x + (size_t)row*DIMM;
    float v[4]; float s = 0.f;
#pragma unroll
    for (int i = 0; i < 4; i++) { v[i] = xr[threadIdx.x + i*256]; s += v[i]*v[i]; }
    __shared__ float red[8];
#pragma unroll
    for (int o = 16; o > 0; o >>= 1) s += __shfl_xor_sync(0xffffffffu, s, o);
    if ((threadIdx.x & 31) == 0) red[threadIdx.x >> 5] = s;
    __syncthreads();
    if (threadIdx.x < 8) {
        float t = red[threadIdx.x];
#pragma unroll
        for (int o = 4; o > 0; o >>= 1) t += __shfl_xor_sync(0xffu, t, o);
        if (threadIdx.x == 0) red[0] = t;
    }
    __syncthreads();
    float r = rsqrtf(red[0] / (float)DIMM + EPSV);
#pragma unroll
    for (int i = 0; i < 4; i++) {
        int c = threadIdx.x + i*256;
        float val = v[i]*r*w[c];
        outh[(size_t)row*DIMM + c] = __float2half(val);
        if (outf) outf[(size_t)row*DIMM + c] = val;
    }
}

__global__ void rope_half(__half* __restrict__ qkv, const float* __restrict__ freqs) {
    int idx = blockIdx.x*blockDim.x + threadIdx.x;
    if (idx >= NTOK*NHEAD*(HDIM/2)) return;
    int p = idx % (HDIM/2);
    int h = (idx / (HDIM/2)) % NHEAD;
    int n = idx / (NHEAD*(HDIM/2));
    int s = n % SLEN;
    float c  = freqs[(s*(HDIM/2) + p)*2 + 0];
    float sn = freqs[(s*(HDIM/2) + p)*2 + 1];
    size_t base = (size_t)n*DIMM + h*HDIM + 2*p;
    __half2* q2 = (__half2*)(qkv + base);
    __half2* k2 = (__half2*)(qkv + (size_t)NTOK*DIMM + base);
    float2 qv = __half22float2(*q2);
    *q2 = __floats2half2_rn(qv.x*c - qv.y*sn, qv.x*sn + qv.y*c);
    float2 kv = __half22float2(*k2);
    *k2 = __floats2half2_rn(kv.x*c - kv.y*sn, kv.x*sn + kv.y*c);
}

__global__ void zero_counts_kernel(int* c) { if (threadIdx.x < NEXP) c[threadIdx.x] = 0; }

__global__ void gate_topk(const float* __restrict__ hn, const float* __restrict__ gw,
                          int* __restrict__ tidx, float* __restrict__ tw,
                          int* __restrict__ counts) {
    int n = blockIdx.x;
    int w = threadIdx.x >> 5, lane = threadIdx.x & 31;
    const float* x = hn + (size_t)n*DIMM;
    const float* g = gw + (size_t)w*DIMM;
    float s = 0.f;
    for (int i = lane; i < DIMM; i += 32) s += x[i]*g[i];
#pragma unroll
    for (int o = 16; o > 0; o >>= 1) s += __shfl_xor_sync(0xffffffffu, s, o);
    __shared__ float sc[NEXP];
    if (lane == 0) sc[w] = s;
    __syncthreads();
    if (threadIdx.x == 0) {
        float mx = sc[0];
        for (int e = 1; e < NEXP; e++) mx = fmaxf(mx, sc[e]);
        float p[NEXP]; float sum = 0.f;
        for (int e = 0; e < NEXP; e++) { p[e] = expf(sc[e]-mx); sum += p[e]; }
        for (int e = 0; e < NEXP; e++) p[e] /= sum;
        int i0 = 0;
        for (int e = 1; e < NEXP; e++) if (p[e] > p[i0]) i0 = e;
        int i1 = -1;
        for (int e = 0; e < NEXP; e++)
            if (e != i0 && (i1 < 0 || p[e] > p[i1])) i1 = e;
        tidx[n*2]   = i0; tidx[n*2+1] = i1;
        tw[n*2]     = p[i0]; tw[n*2+1] = p[i1];
        atomicAdd(&counts[i0], 1);
        atomicAdd(&counts[i1], 1);
    }
}

__global__ void prefix_kernel(const int* __restrict__ counts, int* __restrict__ offs,
                              int* __restrict__ fill) {
    if (threadIdx.x == 0) {
        int a = 0;
        for (int e = 0; e < NEXP; e++) { offs[e] = a; a += counts[e]; }
        offs[NEXP] = a;
    }
    if (threadIdx.x < NEXP) fill[threadIdx.x] = 0;
}

__global__ void scatter_kernel(const int* __restrict__ tidx,
                               const int* __restrict__ offs, int* __restrict__ fill,
                               int* __restrict__ tok, int* __restrict__ smap) {
    int n = blockIdx.x*blockDim.x + threadIdx.x;
    if (n >= NTOK) return;
#pragma unroll
    for (int j = 0; j < TOPK; j++) {
        int e = tidx[n*2+j];
        int slot = offs[e] + atomicAdd(&fill[e], 1);
        tok[slot] = n;
        smap[n*2+j] = slot;
    }
}

// silu(a)*b on half inputs -> half output, 8 elems/thread
__global__ void silu_mul_hh(const __half* __restrict__ a, const __half* __restrict__ b,
                            __half* __restrict__ o, size_t n) {
    size_t i = ((size_t)blockIdx.x*blockDim.x + threadIdx.x)*8;
    if (i >= n) return;
    uint4 av = *(const uint4*)(a + i);
    uint4 bv = *(const uint4*)(b + i);
    uint4 ov;
    uint32_t* ap = (uint32_t*)&av;
    uint32_t* bp = (uint32_t*)&bv;
    uint32_t* op = (uint32_t*)&ov;
#pragma unroll
    for (int j = 0; j < 4; j++) {
        float2 af = __half22float2(*(__half2*)&ap[j]);
        float2 bf = __half22float2(*(__half2*)&bp[j]);
        float r0 = af.x / (1.f + __expf(-af.x)) * bf.x;
        float r1 = af.y / (1.f + __expf(-af.y)) * bf.y;
        op[j] = f2h2(r0, r1);
    }
    *(uint4*)(o + i) = ov;
}

__global__ void combine_kernel(float* __restrict__ out, const __half* __restrict__ eo,
                               const int* __restrict__ smap, const float* __restrict__ tw) {
    size_t idx = (size_t)blockIdx.x*blockDim.x + threadIdx.x;   // over NTOK*DIMM/2
    if (idx >= (size_t)NTOK*DIMM/2) return;
    size_t n = idx / (DIMM/2), d = (idx % (DIMM/2))*2;
    int s0 = smap[n*2], s1 = smap[n*2+1];
    float w0 = tw[n*2], w1 = tw[n*2+1];
    float2 e0 = __half22float2(*(const __half2*)(eo + (size_t)s0*DIMM + d));
    float2 e1 = __half22float2(*(const __half2*)(eo + (size_t)s1*DIMM + d));
    float2 ov = *(float2*)(out + n*DIMM + d);
    ov.x += w0*e0.x + w1*e1.x;
    ov.y += w0*e0.y + w1*e1.y;
    *(float2*)(out + n*DIMM + d) = ov;
}

// ================= launcher =================
extern "C" void kernel_launch(void* const* d_in, const int* in_sizes, int n_in,
                              void* d_out, int out_size) {
    (void)in_sizes; (void)n_in; (void)out_size;
    const float* x     = (const float*)d_in[0];
    const float* freqs = (const float*)d_in[1];
    const float* att_w = (const float*)d_in[2];
    const float* wq    = (const float*)d_in[3];
    const float* wk    = (const float*)d_in[4];
    const float* wv    = (const float*)d_in[5];
    const float* wo    = (const float*)d_in[6];
    const float* ffn_w = (const float*)d_in[7];
    const float* gw    = (const float*)d_in[8];
    const float* ew1   = (const float*)d_in[9];
    const float* ew2   = (const float*)d_in[10];
    const float* ew3   = (const float*)d_in[11];
    const float* sw1   = (const float*)d_in[12];
    const float* sw2   = (const float*)d_in[13];
    const float* sw3   = (const float*)d_in[14];
    float* out = (float*)d_out;

    __half *wqkvh,*woh,*e13h,*e2h,*s13wh,*s2wh,*xnh,*qkvh,*atth,*hnh;
    __half *h13h,*g13h,*s13hh,*s13h,*eoh;
    float *h,*hn32,*tw;
    int *tidx,*counts,*offs,*fill,*tok,*smap;
    cudaGetSymbolAddress((void**)&wqkvh, g_wqkvh);
    cudaGetSymbolAddress((void**)&woh,   g_woh);
    cudaGetSymbolAddress((void**)&e13h,  g_e13h);
    cudaGetSymbolAddress((void**)&e2h,   g_e2h);
    cudaGetSymbolAddress((void**)&s13wh, g_s13wh);
    cudaGetSymbolAddress((void**)&s2wh,  g_s2wh);
    cudaGetSymbolAddress((void**)&xnh,   g_xnh);
    cudaGetSymbolAddress((void**)&qkvh,  g_qkvh);
    cudaGetSymbolAddress((void**)&atth,  g_atth);
    cudaGetSymbolAddress((void**)&hnh,   g_hnh);
    cudaGetSymbolAddress((void**)&h13h,  g_h13h);
    cudaGetSymbolAddress((void**)&g13h,  g_g13h);
    cudaGetSymbolAddress((void**)&s13hh, g_s13hh);
    cudaGetSymbolAddress((void**)&s13h,  g_s13h);
    cudaGetSymbolAddress((void**)&eoh,   g_eoh);
    cudaGetSymbolAddress((void**)&h,     g_h);
    cudaGetSymbolAddress((void**)&hn32,  g_hn32);
    cudaGetSymbolAddress((void**)&tidx,  g_topk_idx);
    cudaGetSymbolAddress((void**)&tw,    g_topk_w);
    cudaGetSymbolAddress((void**)&counts, g_counts);
    cudaGetSymbolAddress((void**)&offs,   g_offsets);
    cudaGetSymbolAddress((void**)&fill,   g_fill);
    cudaGetSymbolAddress((void**)&tok,    g_tok_idx);
    cudaGetSymbolAddress((void**)&smap,   g_slot_map);

    cudaFuncSetAttribute(gemm2<false,false,false,true >, cudaFuncAttributeMaxDynamicSharedMemorySize, SMEMB);
    cudaFuncSetAttribute(gemm2<false,false,true, false>, cudaFuncAttributeMaxDynamicSharedMemorySize, SMEMB);
    cudaFuncSetAttribute(gemm2<true, true, false,true >, cudaFuncAttributeMaxDynamicSharedMemorySize, SMEMB);
    cudaFuncSetAttribute(gemm2<false,true, false,true >, cudaFuncAttributeMaxDynamicSharedMemorySize, SMEMB);

    const int T = 256;
    const int WQN = DIMM*DIMM;     // 1M elements = 512 blocks of 2048
    const int EWN = DIMM*HIDD;     // 1M; expert tensors are 8M = 4096 blocks

    // ---- fused weight conversion (one launch, 15872 blocks) ----
    {
        CvtArgs a;
        a.s[0]=wq;  a.d[0]=wqkvh;         a.sb[0]=0;
        a.s[1]=wk;  a.d[1]=wqkvh+WQN;     a.sb[1]=512;
        a.s[2]=wv;  a.d[2]=wqkvh+2*WQN;   a.sb[2]=1024;
        a.s[3]=wo;  a.d[3]=woh;           a.sb[3]=1536;
        a.s[4]=ew1; a.d[4]=e13h;                        a.sb[4]=2048;
        a.s[5]=ew3; a.d[5]=e13h+(size_t)NEXP*EWN;       a.sb[5]=6144;
        a.s[6]=ew2; a.d[6]=e2h;                         a.sb[6]=10240;
        a.s[7]=sw1; a.d[7]=s13wh;         a.sb[7]=14336;
        a.s[8]=sw3; a.d[8]=s13wh+EWN;     a.sb[8]=14848;
        a.s[9]=sw2; a.d[9]=s2wh;          a.sb[9]=15360;
        cvt_all<<<15872, T>>>(a);
    }

    // 1) attention pre-norm
    rmsnorm_kernel<<<NTOK, T>>>(x, att_w, xnh, nullptr);

    // 2) QKV
    gemm2<false,false,false,true><<<dim3(32,8,3), T, SMEMB>>>(
        xnh, wqkvh, qkvh, nullptr, NTOK, 1.f,
        0, (long long)DIMM*DIMM, (long long)NTOK*DIMM, 0, nullptr, nullptr);

    // 3) RoPE
    rope_half<<<(NTOK*NHEAD*(HDIM/2))/T, T>>>(qkvh, freqs);

    // 4) flash attention
    flash_attn<<<dim3(SLEN/128, BSZ*NHEAD), T>>>(qkvh, atth);

    // 5) h = x + att @ wo
    gemm2<false,false,true,false><<<dim3(32,8,1), T, SMEMB>>>(
        atth, woh, h, x, NTOK, 1.f, 0, 0, 0, 0, nullptr, nullptr);

    // 6) ffn pre-norm
    rmsnorm_kernel<<<NTOK, T>>>(h, ffn_w, hnh, hn32);

    // 7) gate + routing
    zero_counts_kernel<<<1, 32>>>(counts);
    gate_topk<<<NTOK, T>>>(hn32, gw, tidx, tw, counts);
    prefix_kernel<<<1, 32>>>(counts, offs, fill);
    scatter_kernel<<<(NTOK + T - 1)/T, T>>>(tidx, offs, fill, tok, smap);

    // 8) experts (half intermediates)
    gemm2<true,true,false,true><<<dim3(32,8,16), T, SMEMB>>>(
        hnh, e13h, h13h, nullptr, 0, 1.f,
        0, (long long)EWN, 0, (long long)NSLOT*HIDD, tok, offs);
    silu_mul_hh<<<(unsigned)(((size_t)NSLOT*HIDD)/2048), T>>>(
        h13h, h13h + (size_t)NSLOT*HIDD, g13h, (size_t)NSLOT*HIDD);
    gemm2<false,true,false,true><<<dim3(32,8,NEXP), T, SMEMB>>>(
        g13h, e2h, eoh, nullptr, 0, 1.f,
        0, (long long)EWN, 0, 0, nullptr, offs);

    // 9) shared expert (half intermediates)
    gemm2<false,false,false,true><<<dim3(32,8,2), T, SMEMB>>>(
        hnh, s13wh, s13hh, nullptr, NTOK, 1.f,
        0, (long long)EWN, (long long)NTOK*HIDD, 0, nullptr, nullptr);
    silu_mul_hh<<<(unsigned)(((size_t)NTOK*HIDD)/2048), T>>>(
        s13hh, s13hh + (size_t)NTOK*HIDD, s13h, (size_t)NTOK*HIDD);
    gemm2<false,false,true,false><<<dim3(32,8,1), T, SMEMB>>>(
        s13h, s2wh, out, h, NTOK, 1.f, 0, 0, 0, 0, nullptr, nullptr);

    // 10) routed combine (half eo)
    combine_kernel<<<(unsigned)(((size_t)NTOK*DIMM/2 + T - 1)/T), T>>>(out, eoh, smap, tw);
}

// round 10
// speedup vs baseline: 7.6772x; 1.0397x over previous
#include <cuda_runtime.h>
#include <cuda_fp16.h>
#include <math.h>
#include <stdint.h>

#define DIMM 1024
#define NHEAD 16
#define HDIM 64
#define SLEN 2048
#define BSZ 2
#define NTOK (BSZ*SLEN)          // 4096
#define NEXP 8
#define TOPK 2
#define HIDD 1024
#define NSLOT (NTOK*TOPK)        // 8192
#define EPSV 1e-6f

// GEMM pipeline constants
#define AST 40
#define BST 136
#define A_STAGE (128*AST)
#define B_STAGE (32*BST)
#define STAGES 4
#define SMEMB (STAGES*(A_STAGE+B_STAGE)*2)

// ================= scratch =================
__device__ __half g_wqkvh[(size_t)3*DIMM*DIMM];
__device__ __half g_woh[(size_t)DIMM*DIMM];
__device__ __half g_e13h[(size_t)2*NEXP*DIMM*HIDD];
__device__ __half g_e2h[(size_t)NEXP*HIDD*DIMM];
__device__ __half g_s13wh[(size_t)2*DIMM*HIDD];
__device__ __half g_s2wh[(size_t)HIDD*DIMM];
__device__ __half g_xnh[(size_t)NTOK*DIMM];
__device__ __half g_qkvh[(size_t)3*NTOK*DIMM];
__device__ __half g_atth[(size_t)NTOK*DIMM];
__device__ __half g_hnh[(size_t)NTOK*DIMM];
__device__ __half g_h13h[(size_t)2*NSLOT*HIDD];
__device__ __half g_g13h[(size_t)NSLOT*HIDD];
__device__ __half g_s13hh[(size_t)2*NTOK*HIDD];
__device__ __half g_s13h[(size_t)NTOK*HIDD];
__device__ __half g_eoh[(size_t)NSLOT*DIMM];
__device__ float g_h[(size_t)NTOK*DIMM];
__device__ float g_hn32[(size_t)NTOK*DIMM];
__device__ int   g_topk_idx[NTOK*TOPK];
__device__ float g_topk_w [NTOK*TOPK];
__device__ int   g_counts[NEXP];
__device__ int   g_offsets[NEXP+1];
__device__ int   g_fill[NEXP];
__device__ int   g_tok_idx[NSLOT];
__device__ int   g_slot_map[NTOK*TOPK];

__device__ __forceinline__ uint32_t f2h2(float lo, float hi) {
    __half2 h = __floats2half2_rn(lo, hi);
    return *reinterpret_cast<uint32_t*>(&h);
}
__device__ __forceinline__ uint32_t smem_u32(const void* p) {
    uint32_t a;
    asm("{ .reg .u64 t; cvta.to.shared.u64 t, %1; cvt.u32.u64 %0, t; }" : "=r"(a) : "l"(p));
    return a;
}

#define MMA16816(acc, a0,a1,a2,a3, b0,b1) \
    asm volatile( \
        "mma.sync.aligned.m16n8k16.row.col.f32.f16.f16.f32 " \
        "{%0,%1,%2,%3}, {%4,%5,%6,%7}, {%8,%9}, {%0,%1,%2,%3};" \
        : "+f"((acc)[0]), "+f"((acc)[1]), "+f"((acc)[2]), "+f"((acc)[3]) \
        : "r"(a0), "r"(a1), "r"(a2), "r"(a3), "r"(b0), "r"(b1))

#define LDSM_X4(r, addr) \
    asm volatile("ldmatrix.sync.aligned.m8n8.x4.shared.b16 {%0,%1,%2,%3}, [%4];" \
        : "=r"((r)[0]),"=r"((r)[1]),"=r"((r)[2]),"=r"((r)[3]) : "r"(addr))
#define LDSM_X4T(r, addr) \
    asm volatile("ldmatrix.sync.aligned.m8n8.x4.trans.shared.b16 {%0,%1,%2,%3}, [%4];" \
        : "=r"((r)[0]),"=r"((r)[1]),"=r"((r)[2]),"=r"((r)[3]) : "r"(addr))

#define CP16(dst, src, sz) \
    asm volatile("cp.async.cg.shared.global [%0], [%1], 16, %2;" \
        :: "r"(dst), "l"(src), "r"(sz) : "memory")
#define CPCOMMIT asm volatile("cp.async.commit_group;" ::: "memory")
#define CPWAIT2  asm volatile("cp.async.wait_group 2;" ::: "memory")
#define CPWAIT1  asm volatile("cp.async.wait_group 1;" ::: "memory")
#define CPWAIT0  asm volatile("cp.async.wait_group 0;" ::: "memory")

// ================= GEMM: half A [M,1024], half B [1024,1024] =================
// ROPE: apply rotary to epilogue pairs when z<2 (QKV fused).
// COMBINE: add routed-expert contributions in epilogue (final GEMM fused).
template<bool GATHER, bool GROUPED, bool RESID, bool HALFOUT, bool ROPE, bool COMBINE>
__global__ void __launch_bounds__(256) gemm2(
    const __half* __restrict__ A, const __half* __restrict__ B,
    void* __restrict__ Cv, const float* __restrict__ Rr,
    int M, float scale,
    long long sAo, long long sBo, long long sCo, long long sCg,
    const int* __restrict__ gidx, const int* __restrict__ offsets,
    const float* __restrict__ Fq, const __half* __restrict__ Eo,
    const int* __restrict__ smap, const float* __restrict__ tw)
{
    extern __shared__ __half smx[];
    const int LDA = 1024;
    int tid = threadIdx.x, lane = tid & 31, wid = tid >> 5;
    int warpM = wid & 3, warpN = wid >> 2;
    int z = blockIdx.z;

    float* Cf = (float*)Cv;
    __half* Ch = (__half*)Cv;

    int Mz = M, seg0 = 0;
    if (GROUPED) {
        int e = z & 7;
        seg0 = offsets[e]; Mz = offsets[e+1] - seg0;
        B  += (size_t)z * sBo;
        if (HALFOUT) Ch += (size_t)(z >> 3) * sCg;
        else         Cf += (size_t)(z >> 3) * sCg;
    } else {
        A += (size_t)z * sAo;
        B += (size_t)z * sBo;
        if (HALFOUT) Ch += (size_t)z * sCo; else Cf += (size_t)z * sCo;
        if (RESID) Rr += (size_t)z * sCo;
    }
    int m0 = blockIdx.x * 128;
    if (GROUPED && m0 >= Mz) return;
    int n0 = blockIdx.y * 128;

    uint32_t AsB = smem_u32(smx);
    uint32_t BsB = AsB + STAGES*A_STAGE*2;

    int arow = tid >> 1, acH = (tid & 1)*16;
    bool aOK = (!GROUPED) || ((m0 + arow) < Mz);
    long long grow = 0;
    if (aOK) grow = GATHER ? (long long)gidx[seg0 + m0 + arow]
                  : (GROUPED ? (long long)(seg0 + m0 + arow) : (long long)(m0 + arow));
    const __half* aP = A + (size_t)grow*LDA + acH;
    uint32_t aD = AsB + (arow*AST + acH)*2;
    int aSz = aOK ? 16 : 0;

    int brow = tid >> 3, bH = (tid & 7)*16;
    const __half* bP = B + (size_t)brow*LDA + n0 + bH;
    uint32_t bD = BsB + (brow*BST + bH)*2;

#define LOADST(s_, c_) do { \
    int kt_ = (c_)*32; \
    CP16(aD + (s_)*(A_STAGE*2),      aP + kt_,     aSz); \
    CP16(aD + (s_)*(A_STAGE*2) + 16, aP + kt_ + 8, aSz); \
    CP16(bD + (s_)*(B_STAGE*2),      bP + (size_t)kt_*LDA,     16); \
    CP16(bD + (s_)*(B_STAGE*2) + 16, bP + (size_t)kt_*LDA + 8, 16); \
} while (0)

    float acc[2][8][4];
#pragma unroll
    for (int mt = 0; mt < 2; mt++)
#pragma unroll
        for (int nt = 0; nt < 8; nt++)
#pragma unroll
            for (int j = 0; j < 4; j++) acc[mt][nt][j] = 0.f;

    uint32_t aAddr = AsB + ((warpM*32 + (lane & 15))*AST + ((lane >> 4) & 1)*8)*2;
    uint32_t bAddr = BsB + ((lane & 15)*BST + warpN*64 + ((lane >> 4) & 1)*8)*2;

    LOADST(0, 0); CPCOMMIT;
    LOADST(1, 1); CPCOMMIT;
    LOADST(2, 2); CPCOMMIT;

    for (int c = 0; c < 32; c++) {
        CPWAIT2;
        __syncthreads();
        int st = c & 3;
        uint32_t aS = aAddr + st*(A_STAGE*2);
        uint32_t bS = bAddr + st*(B_STAGE*2);
#pragma unroll
        for (int ks = 0; ks < 2; ks++) {
            uint32_t af0[4], af1[4];
            LDSM_X4(af0, aS + ks*32);
            LDSM_X4(af1, aS + ks*32 + 16*AST*2);
            uint32_t bf[4][4];
#pragma unroll
            for (int nt2 = 0; nt2 < 4; nt2++)
                LDSM_X4T(bf[nt2], bS + ks*(16*BST*2) + nt2*32);
#pragma unroll
            for (int nt2 = 0; nt2 < 4; nt2++) {
                MMA16816(acc[0][2*nt2  ], af0[0],af0[1],af0[2],af0[3], bf[nt2][0],bf[nt2][1]);
                MMA16816(acc[0][2*nt2+1], af0[0],af0[1],af0[2],af0[3], bf[nt2][2],bf[nt2][3]);
                MMA16816(acc[1][2*nt2  ], af1[0],af1[1],af1[2],af1[3], bf[nt2][0],bf[nt2][1]);
                MMA16816(acc[1][2*nt2+1], af1[0],af1[1],af1[2],af1[3], bf[nt2][2],bf[nt2][3]);
            }
        }
        if (c + 3 < 32) { int c2 = c + 3; LOADST(c2 & 3, c2); }
        CPCOMMIT;
    }

#pragma unroll
    for (int mt = 0; mt < 2; mt++) {
        int rb = m0 + warpM*32 + mt*16 + (lane >> 2);
#pragma unroll
        for (int hh = 0; hh < 2; hh++) {
            int r = rb + hh*8;
            if (GROUPED && r >= Mz) continue;
            size_t crow = (size_t)((GROUPED ? seg0 : 0) + r) * 1024;
            int cs0 = 0, cs1 = 0; float cw0 = 0.f, cw1 = 0.f;
            if (COMBINE) {
                cs0 = smap[r*2]; cs1 = smap[r*2+1];
                cw0 = tw[r*2];   cw1 = tw[r*2+1];
            }
#pragma unroll
            for (int nt = 0; nt < 8; nt++) {
                int col = n0 + warpN*64 + nt*8 + (lane & 3)*2;
                float vx = acc[mt][nt][hh*2+0]*scale;
                float vy = acc[mt][nt][hh*2+1]*scale;
                if (ROPE) {
                    if (z < 2) {
                        int s = r & (SLEN-1);
                        int p = (col & 63) >> 1;
                        float cc = Fq[(s*(HDIM/2) + p)*2 + 0];
                        float sn = Fq[(s*(HDIM/2) + p)*2 + 1];
                        float rx = vx*cc - vy*sn;
                        float ry = vx*sn + vy*cc;
                        vx = rx; vy = ry;
                    }
                }
                if (HALFOUT) {
                    *(uint32_t*)(Ch + crow + col) = f2h2(vx, vy);
                } else {
                    if (RESID) {
                        float2 rv = *(const float2*)(Rr + crow + col);
                        vx += rv.x; vy += rv.y;
                    }
                    if (COMBINE) {
                        float2 e0 = __half22float2(*(const __half2*)(Eo + (size_t)cs0*1024 + col));
                        float2 e1 = __half22float2(*(const __half2*)(Eo + (size_t)cs1*1024 + col));
                        vx += cw0*e0.x + cw1*e1.x;
                        vy += cw0*e0.y + cw1*e1.y;
                    }
                    *(float2*)(Cf + crow + col) = make_float2(vx, vy);
                }
            }
        }
    }
#undef LOADST
}

// ================= flash attention =================
#define FTILEB (64*72*2)
__global__ void __launch_bounds__(256) flash_attn(
    const __half* __restrict__ qkv, __half* __restrict__ att)
{
    __shared__ __align__(16) __half Ksm[2][64][72];
    __shared__ __align__(16) __half Vsm[2][64][72];
    int tid = threadIdx.x, wid = tid >> 5, lane = tid & 31;
    int bh = blockIdx.y;
    int b = bh >> 4, h = bh & 15;
    size_t plane = (size_t)NTOK*DIMM;
    const __half* qh = qkv +           (size_t)b*SLEN*DIMM + h*HDIM;
    const __half* kh = qkv + plane   + (size_t)b*SLEN*DIMM + h*HDIM;
    const __half* vh = qkv + 2*plane + (size_t)b*SLEN*DIMM + h*HDIM;
    __half* oh = att + (size_t)b*SLEN*DIMM + h*HDIM;

    int qrow0 = blockIdx.x*128 + wid*16 + (lane >> 2);
    const float SC = 0.125f * 1.44269504f;

    uint32_t qf[4][4];
    {
        const __half* qr0 = qh + (size_t)qrow0*DIMM;
        const __half* qr1 = qr0 + 8*DIMM;
        int c0 = (lane & 3)*2;
#pragma unroll
        for (int ks = 0; ks < 4; ks++) {
            qf[ks][0] = *(const uint32_t*)(qr0 + ks*16 + c0);
            qf[ks][1] = *(const uint32_t*)(qr1 + ks*16 + c0);
            qf[ks][2] = *(const uint32_t*)(qr0 + ks*16 + 8 + c0);
            qf[ks][3] = *(const uint32_t*)(qr1 + ks*16 + 8 + c0);
        }
    }

    float oacc[8][4];
#pragma unroll
    for (int nt = 0; nt < 8; nt++)
#pragma unroll
        for (int j = 0; j < 4; j++) oacc[nt][j] = 0.f;
    float M0 = -1e30f, M1 = -1e30f, L0 = 0.f, L1 = 0.f;

    int lrow = tid >> 2, lc = (tid & 3)*2;
    const __half* kSrc = kh + (size_t)lrow*DIMM + lc*8;
    const __half* vSrc = vh + (size_t)lrow*DIMM + lc*8;
    uint32_t kDst = smem_u32(&Ksm[0][lrow][lc*8]);
    uint32_t vDst = smem_u32(&Vsm[0][lrow][lc*8]);

#define FLOAD(buf_, t_) do { \
    size_t off_ = (size_t)(t_)*64*DIMM; \
    CP16(kDst + (buf_)*FTILEB,      kSrc + off_,     16); \
    CP16(kDst + (buf_)*FTILEB + 16, kSrc + off_ + 8, 16); \
    CP16(vDst + (buf_)*FTILEB,      vSrc + off_,     16); \
    CP16(vDst + (buf_)*FTILEB + 16, vSrc + off_ + 8, 16); \
} while (0)

    uint32_t ksBase = smem_u32(&Ksm[0][0][0]);
    uint32_t vsBase = smem_u32(&Vsm[0][0][0]);
    uint32_t sA = ksBase + (((lane>>4)&1)*8 + (lane&7))*144 + ((lane>>3)&1)*16;
    uint32_t vA = vsBase + (lane&15)*144 + (lane>>4)*16;

    FLOAD(0, 0); CPCOMMIT;

    const int NTILES = SLEN/64;
    for (int t = 0; t < NTILES; t++) {
        int buf = t & 1;
        if (t + 1 < NTILES) { FLOAD(buf ^ 1, t + 1); CPCOMMIT; CPWAIT1; }
        else                { CPWAIT0; }
        __syncthreads();

        uint32_t sB = sA + buf*FTILEB;
        uint32_t vB = vA + buf*FTILEB;

        float sacc[8][4];
#pragma unroll
        for (int nt = 0; nt < 8; nt++)
#pragma unroll
            for (int j = 0; j < 4; j++) sacc[nt][j] = 0.f;
#pragma unroll
        for (int ks = 0; ks < 4; ks++) {
#pragma unroll
            for (int nt2 = 0; nt2 < 4; nt2++) {
                uint32_t bb[4];
                LDSM_X4(bb, sB + nt2*(16*144) + ks*32);
                MMA16816(sacc[2*nt2  ], qf[ks][0], qf[ks][1], qf[ks][2], qf[ks][3], bb[0], bb[1]);
                MMA16816(sacc[2*nt2+1], qf[ks][0], qf[ks][1], qf[ks][2], qf[ks][3], bb[2], bb[3]);
            }
        }

        float mt0 = -1e30f, mt1 = -1e30f;
#pragma unroll
        for (int nt = 0; nt < 8; nt++) {
            mt0 = fmaxf(mt0, fmaxf(sacc[nt][0], sacc[nt][1]));
            mt1 = fmaxf(mt1, fmaxf(sacc[nt][2], sacc[nt][3]));
        }
        mt0 = fmaxf(mt0, __shfl_xor_sync(0xffffffffu, mt0, 1));
        mt0 = fmaxf(mt0, __shfl_xor_sync(0xffffffffu, mt0, 2));
        mt1 = fmaxf(mt1, __shfl_xor_sync(0xffffffffu, mt1, 1));
        mt1 = fmaxf(mt1, __shfl_xor_sync(0xffffffffu, mt1, 2));
        float Mn0 = fmaxf(M0, mt0), Mn1 = fmaxf(M1, mt1);
        float al0 = exp2f((M0 - Mn0)*SC), al1 = exp2f((M1 - Mn1)*SC);
        M0 = Mn0; M1 = Mn1;
        float c0 = M0*SC, c1 = M1*SC;
        uint32_t pr[8][2];
        float rs0 = 0.f, rs1 = 0.f;
#pragma unroll
        for (int nt = 0; nt < 8; nt++) {
            uint32_t h0 = f2h2(sacc[nt][0]*SC - c0, sacc[nt][1]*SC - c0);
            uint32_t h1 = f2h2(sacc[nt][2]*SC - c1, sacc[nt][3]*SC - c1);
            asm("ex2.approx.f16x2 %0, %1;" : "=r"(pr[nt][0]) : "r"(h0));
            asm("ex2.approx.f16x2 %0, %1;" : "=r"(pr[nt][1]) : "r"(h1));
            float2 p0 = __half22float2(*(__half2*)&pr[nt][0]);
            float2 p1 = __half22float2(*(__half2*)&pr[nt][1]);
            rs0 += p0.x + p0.y;
            rs1 += p1.x + p1.y;
        }
        L0 = L0*al0 + rs0;
        L1 = L1*al1 + rs1;
#pragma unroll
        for (int nt = 0; nt < 8; nt++) {
            oacc[nt][0] *= al0; oacc[nt][1] *= al0;
            oacc[nt][2] *= al1; oacc[nt][3] *= al1;
        }

#pragma unroll
        for (int ks = 0; ks < 4; ks++) {
            uint32_t a0 = pr[2*ks  ][0], a1 = pr[2*ks  ][1];
            uint32_t a2 = pr[2*ks+1][0], a3 = pr[2*ks+1][1];
#pragma unroll
            for (int nt2 = 0; nt2 < 4; nt2++) {
                uint32_t bb[4];
                LDSM_X4T(bb, vB + ks*(16*144) + nt2*32);
                MMA16816(oacc[2*nt2  ], a0, a1, a2, a3, bb[0], bb[1]);
                MMA16816(oacc[2*nt2+1], a0, a1, a2, a3, bb[2], bb[3]);
            }
        }
        __syncthreads();
    }
#undef FLOAD

    L0 += __shfl_xor_sync(0xffffffffu, L0, 1);
    L0 += __shfl_xor_sync(0xffffffffu, L0, 2);
    L1 += __shfl_xor_sync(0xffffffffu, L1, 1);
    L1 += __shfl_xor_sync(0xffffffffu, L1, 2);
    float inv0 = 1.f / L0, inv1 = 1.f / L1;
    __half* or0 = oh + (size_t)qrow0*DIMM;
    __half* or1 = or0 + 8*DIMM;
#pragma unroll
    for (int nt = 0; nt < 8; nt++) {
        int col = nt*8 + (lane & 3)*2;
        *(uint32_t*)(or0 + col) = f2h2(oacc[nt][0]*inv0, oacc[nt][1]*inv0);
        *(uint32_t*)(or1 + col) = f2h2(oacc[nt][2]*inv1, oacc[nt][3]*inv1);
    }
}

// ================= fused weight conversion =================
struct CvtArgs {
    const float* s[10];
    __half* d[10];
    int sb[10];
};
__global__ void cvt_all(CvtArgs a) {
    int b = blockIdx.x;
    int r = 0;
#pragma unroll
    for (int i = 1; i < 10; i++) r += (b >= a.sb[i]);
    const float* src = a.s[r];
    __half* dst = a.d[r];
    int off = (b - a.sb[r])*2048 + threadIdx.x*8;
    float4 f0 = *(const float4*)(src + off);
    float4 f1 = *(const float4*)(src + off + 4);
    uint4 o;
    o.x = f2h2(f0.x, f0.y); o.y = f2h2(f0.z, f0.w);
    o.z = f2h2(f1.x, f1.y); o.w = f2h2(f1.z, f1.w);
    *(uint4*)(dst + off) = o;
}

// ================= elementwise kernels =================
__global__ void rmsnorm_kernel(const float* __restrict__ x, const float* __restrict__ w,
                               __half* __restrict__ outh, float* __restrict__ outf) {
    int row = blockIdx.x;
    const float* xr = x + (size_t)row*DIMM;
    float v[4]; float s = 0.f;
#pragma unroll
    for (int i = 0; i < 4; i++) { v[i] = xr[threadIdx.x + i*256]; s += v[i]*v[i]; }
    __shared__ float red[8];
#pragma unroll
    for (int o = 16; o > 0; o >>= 1) s += __shfl_xor_sync(0xffffffffu, s, o);
    if ((threadIdx.x & 31) == 0) red[threadIdx.x >> 5] = s;
    __syncthreads();
    if (threadIdx.x < 8) {
        float t = red[threadIdx.x];
#pragma unroll
        for (int o = 4; o > 0; o >>= 1) t += __shfl_xor_sync(0xffu, t, o);
        if (threadIdx.x == 0) red[0] = t;
    }
    __syncthreads();
    float r = rsqrtf(red[0] / (float)DIMM + EPSV);
#pragma unroll
    for (int i = 0; i < 4; i++) {
        int c = threadIdx.x + i*256;
        float val = v[i]*r*w[c];
        outh[(size_t)row*DIMM + c] = __float2half(val);
        if (outf) outf[(size_t)row*DIMM + c] = val;
    }
}

__global__ void zero_counts_kernel(int* c) { if (threadIdx.x < NEXP) c[threadIdx.x] = 0; }

__global__ void gate_topk(const float* __restrict__ hn, const float* __restrict__ gw,
                          int* __restrict__ tidx, float* __restrict__ tw,
                          int* __restrict__ counts) {
    int n = blockIdx.x;
    int w = threadIdx.x >> 5, lane = threadIdx.x & 31;
    const float* x = hn + (size_t)n*DIMM;
    const float* g = gw + (size_t)w*DIMM;
    float s = 0.f;
    for (int i = lane; i < DIMM; i += 32) s += x[i]*g[i];
#pragma unroll
    for (int o = 16; o > 0; o >>= 1) s += __shfl_xor_sync(0xffffffffu, s, o);
    __shared__ float sc[NEXP];
    if (lane == 0) sc[w] = s;
    __syncthreads();
    if (threadIdx.x == 0) {
        float mx = sc[0];
        for (int e = 1; e < NEXP; e++) mx = fmaxf(mx, sc[e]);
        float p[NEXP]; float sum = 0.f;
        for (int e = 0; e < NEXP; e++) { p[e] = expf(sc[e]-mx); sum += p[e]; }
        for (int e = 0; e < NEXP; e++) p[e] /= sum;
        int i0 = 0;
        for (int e = 1; e < NEXP; e++) if (p[e] > p[i0]) i0 = e;
        int i1 = -1;
        for (int e = 0; e < NEXP; e++)
            if (e != i0 && (i1 < 0 || p[e] > p[i1])) i1 = e;
        tidx[n*2]   = i0; tidx[n*2+1] = i1;
        tw[n*2]     = p[i0]; tw[n*2+1] = p[i1];
        atomicAdd(&counts[i0], 1);
        atomicAdd(&counts[i1], 1);
    }
}

__global__ void prefix_kernel(const int* __restrict__ counts, int* __restrict__ offs,
                              int* __restrict__ fill) {
    if (threadIdx.x == 0) {
        int a = 0;
        for (int e = 0; e < NEXP; e++) { offs[e] = a; a += counts[e]; }
        offs[NEXP] = a;
    }
    if (threadIdx.x < NEXP) fill[threadIdx.x] = 0;
}

__global__ void scatter_kernel(const int* __restrict__ tidx,
                               const int* __restrict__ offs, int* __restrict__ fill,
                               int* __restrict__ tok, int* __restrict__ smap) {
    int n = blockIdx.x*blockDim.x + threadIdx.x;
    if (n >= NTOK) return;
#pragma unroll
    for (int j = 0; j < TOPK; j++) {
        int e = tidx[n*2+j];
        int slot = offs[e] + atomicAdd(&fill[e], 1);
        tok[slot] = n;
        smap[n*2+j] = slot;
    }
}

__global__ void silu_mul_hh(const __half* __restrict__ a, const __half* __restrict__ b,
                            __half* __restrict__ o, size_t n) {
    size_t i = ((size_t)blockIdx.x*blockDim.x + threadIdx.x)*8;
    if (i >= n) return;
    uint4 av = *(const uint4*)(a + i);
    uint4 bv = *(const uint4*)(b + i);
    uint4 ov;
    uint32_t* ap = (uint32_t*)&av;
    uint32_t* bp = (uint32_t*)&bv;
    uint32_t* op = (uint32_t*)&ov;
#pragma unroll
    for (int j = 0; j < 4; j++) {
        float2 af = __half22float2(*(__half2*)&ap[j]);
        float2 bf = __half22float2(*(__half2*)&bp[j]);
        float r0 = af.x / (1.f + __expf(-af.x)) * bf.x;
        float r1 = af.y / (1.f + __expf(-af.y)) * bf.y;
        op[j] = f2h2(r0, r1);
    }
    *(uint4*)(o + i) = ov;
}

// ================= launcher =================
extern "C" void kernel_launch(void* const* d_in, const int* in_sizes, int n_in,
                              void* d_out, int out_size) {
    (void)in_sizes; (void)n_in; (void)out_size;
    const float* x     = (const float*)d_in[0];
    const float* freqs = (const float*)d_in[1];
    const float* att_w = (const float*)d_in[2];
    const float* wq    = (const float*)d_in[3];
    const float* wk    = (const float*)d_in[4];
    const float* wv    = (const float*)d_in[5];
    const float* wo    = (const float*)d_in[6];
    const float* ffn_w = (const float*)d_in[7];
    const float* gw    = (const float*)d_in[8];
    const float* ew1   = (const float*)d_in[9];
    const float* ew2   = (const float*)d_in[10];
    const float* ew3   = (const float*)d_in[11];
    const float* sw1   = (const float*)d_in[12];
    const float* sw2   = (const float*)d_in[13];
    const float* sw3   = (const float*)d_in[14];
    float* out = (float*)d_out;

    __half *wqkvh,*woh,*e13h,*e2h,*s13wh,*s2wh,*xnh,*qkvh,*atth,*hnh;
    __half *h13h,*g13h,*s13hh,*s13h,*eoh;
    float *h,*hn32,*tw;
    int *tidx,*counts,*offs,*fill,*tok,*smap;
    cudaGetSymbolAddress((void**)&wqkvh, g_wqkvh);
    cudaGetSymbolAddress((void**)&woh,   g_woh);
    cudaGetSymbolAddress((void**)&e13h,  g_e13h);
    cudaGetSymbolAddress((void**)&e2h,   g_e2h);
    cudaGetSymbolAddress((void**)&s13wh, g_s13wh);
    cudaGetSymbolAddress((void**)&s2wh,  g_s2wh);
    cudaGetSymbolAddress((void**)&xnh,   g_xnh);
    cudaGetSymbolAddress((void**)&qkvh,  g_qkvh);
    cudaGetSymbolAddress((void**)&atth,  g_atth);
    cudaGetSymbolAddress((void**)&hnh,   g_hnh);
    cudaGetSymbolAddress((void**)&h13h,  g_h13h);
    cudaGetSymbolAddress((void**)&g13h,  g_g13h);
    cudaGetSymbolAddress((void**)&s13hh, g_s13hh);
    cudaGetSymbolAddress((void**)&s13h,  g_s13h);
    cudaGetSymbolAddress((void**)&eoh,   g_eoh);
    cudaGetSymbolAddress((void**)&h,     g_h);
    cudaGetSymbolAddress((void**)&hn32,  g_hn32);
    cudaGetSymbolAddress((void**)&tidx,  g_topk_idx);
    cudaGetSymbolAddress((void**)&tw,    g_topk_w);
    cudaGetSymbolAddress((void**)&counts, g_counts);
    cudaGetSymbolAddress((void**)&offs,   g_offsets);
    cudaGetSymbolAddress((void**)&fill,   g_fill);
    cudaGetSymbolAddress((void**)&tok,    g_tok_idx);
    cudaGetSymbolAddress((void**)&smap,   g_slot_map);

    cudaFuncSetAttribute(gemm2<false,false,false,true ,true ,false>, cudaFuncAttributeMaxDynamicSharedMemorySize, SMEMB);
    cudaFuncSetAttribute(gemm2<false,false,true, false,false,false>, cudaFuncAttributeMaxDynamicSharedMemorySize, SMEMB);
    cudaFuncSetAttribute(gemm2<true, true, false,true ,false,false>, cudaFuncAttributeMaxDynamicSharedMemorySize, SMEMB);
    cudaFuncSetAttribute(gemm2<false,true, false,true ,false,false>, cudaFuncAttributeMaxDynamicSharedMemorySize, SMEMB);
    cudaFuncSetAttribute(gemm2<false,false,false,true ,false,false>, cudaFuncAttributeMaxDynamicSharedMemorySize, SMEMB);
    cudaFuncSetAttribute(gemm2<false,false,true, false,false,true >, cudaFuncAttributeMaxDynamicSharedMemorySize, SMEMB);

    const int T = 256;
    const int WQN = DIMM*DIMM;
    const int EWN = DIMM*HIDD;

    // ---- fused weight conversion ----
    {
        CvtArgs a;
        a.s[0]=wq;  a.d[0]=wqkvh;         a.sb[0]=0;
        a.s[1]=wk;  a.d[1]=wqkvh+WQN;     a.sb[1]=512;
        a.s[2]=wv;  a.d[2]=wqkvh+2*WQN;   a.sb[2]=1024;
        a.s[3]=wo;  a.d[3]=woh;           a.sb[3]=1536;
        a.s[4]=ew1; a.d[4]=e13h;                        a.sb[4]=2048;
        a.s[5]=ew3; a.d[5]=e13h+(size_t)NEXP*EWN;       a.sb[5]=6144;
        a.s[6]=ew2; a.d[6]=e2h;                         a.sb[6]=10240;
        a.s[7]=sw1; a.d[7]=s13wh;         a.sb[7]=14336;
        a.s[8]=sw3; a.d[8]=s13wh+EWN;     a.sb[8]=14848;
        a.s[9]=sw2; a.d[9]=s2wh;          a.sb[9]=15360;
        cvt_all<<<15872, T>>>(a);
    }

    // 1) attention pre-norm
    rmsnorm_kernel<<<NTOK, T>>>(x, att_w, xnh, nullptr);

    // 2) QKV with fused RoPE on q,k planes
    gemm2<false,false,false,true,true,false><<<dim3(32,8,3), T, SMEMB>>>(
        xnh, wqkvh, qkvh, nullptr, NTOK, 1.f,
        0, (long long)DIMM*DIMM, (long long)NTOK*DIMM, 0, nullptr, nullptr,
        freqs, nullptr, nullptr, nullptr);

    // 3) flash attention
    flash_attn<<<dim3(SLEN/128, BSZ*NHEAD), T>>>(qkvh, atth);

    // 4) h = x + att @ wo
    gemm2<false,false,true,false,false,false><<<dim3(32,8,1), T, SMEMB>>>(
        atth, woh, h, x, NTOK, 1.f, 0, 0, 0, 0, nullptr, nullptr,
        nullptr, nullptr, nullptr, nullptr);

    // 5) ffn pre-norm
    rmsnorm_kernel<<<NTOK, T>>>(h, ffn_w, hnh, hn32);

    // 6) gate + routing
    zero_counts_kernel<<<1, 32>>>(counts);
    gate_topk<<<NTOK, T>>>(hn32, gw, tidx, tw, counts);
    prefix_kernel<<<1, 32>>>(counts, offs, fill);
    scatter_kernel<<<(NTOK + T - 1)/T, T>>>(tidx, offs, fill, tok, smap);

    // 7) experts
    gemm2<true,true,false,true,false,false><<<dim3(32,8,16), T, SMEMB>>>(
        hnh, e13h, h13h, nullptr, 0, 1.f,
        0, (long long)EWN, 0, (long long)NSLOT*HIDD, tok, offs,
        nullptr, nullptr, nullptr, nullptr);
    silu_mul_hh<<<(unsigned)(((size_t)NSLOT*HIDD)/2048), T>>>(
        h13h, h13h + (size_t)NSLOT*HIDD, g13h, (size_t)NSLOT*HIDD);
    gemm2<false,true,false,true,false,false><<<dim3(32,8,NEXP), T, SMEMB>>>(
        g13h, e2h, eoh, nullptr, 0, 1.f,
        0, (long long)EWN, 0, 0, nullptr, offs,
        nullptr, nullptr, nullptr, nullptr);

    // 8) shared expert
    gemm2<false,false,false,true,false,false><<<dim3(32,8,2), T, SMEMB>>>(
        hnh, s13wh, s13hh, nullptr, NTOK, 1.f,
        0, (long long)EWN, (long long)NTOK*HIDD, 0, nullptr, nullptr,
        nullptr, nullptr, nullptr, nullptr);
    silu_mul_hh<<<(unsigned)(((size_t)NTOK*HIDD)/2048), T>>>(
        s13hh, s13hh + (size_t)NTOK*HIDD, s13h, (size_t)NTOK*HIDD);

    // 9) final: out = h + s13 @ sw2 + routed combine (fused)
    gemm2<false,false,true,false,false,true><<<dim3(32,8,1), T, SMEMB>>>(
        s13h, s2wh, out, h, NTOK, 1.f, 0, 0, 0, 0, nullptr, nullptr,
        nullptr, eoh, smap, tw);
}